// round 5
// baseline (speedup 1.0000x reference)
#include <cuda_runtime.h>
#include <math.h>

#define MAXN 10000

// ---------------- device scratch --------------------------------------------
__device__ float  g_cst;                       // CST_SILU
__device__ float4 g_xs4[MAXN * 96];            // up-projected node features, [node][u][12f] (pad 9..11)
__device__ float4 g_mid4[MAXN * 288];          // aggregated messages, 1152 f/node

// g_mid per-node layout (1152 floats):
//   [0:128)    l0: u*4 + s   (s=0..2 paths (0,0,0),(1,1,0),(2,2,0); s=3 pad)
//   [128:512)  l1: 128 + u*12 + s*3 + i   (s=0..3 paths (0,1,1),(1,0,1),(1,2,1),(2,1,1))
//   [512:1152) l2: 512 + u*20 + s*5 + k   (s=0..3 paths (0,2,2),(1,1,2),(2,0,2),(2,2,2))
// g_xs per-node layout (384 floats): u*12 + {x0, x1[0..2], x2[0..4], pad*3}

__device__ __forceinline__ float silu_f(float v) {
    return __fdividef(v, 1.0f + __expf(-v));
}

// ---------------- CST_SILU via composite Simpson (double) -------------------
__global__ void cst_kernel() {
    __shared__ double red[256];
    const int t = threadIdx.x;
    const int NI = 4096;
    const double h = 24.0 / NI;
    double s = 0.0;
    for (int i = t; i <= NI; i += 256) {
        double xx = -12.0 + h * i;
        double sig = 1.0 / (1.0 + exp(-xx));
        double f = xx * sig;
        f = f * f * exp(-0.5 * xx * xx);
        double c = (i == 0 || i == NI) ? 1.0 : ((i & 1) ? 4.0 : 2.0);
        s += c * f;
    }
    red[t] = s;
    __syncthreads();
    for (int o = 128; o > 0; o >>= 1) {
        if (t < o) red[t] += red[t + o];
        __syncthreads();
    }
    if (t == 0) {
        double I = red[0] * h / 3.0 / 2.5066282746310005024;
        g_cst = (float)(1.0 / sqrt(I));
    }
}

// ---------------- zero mid ---------------------------------------------------
__global__ void zero_kernel(int n4) {
    int i = blockIdx.x * blockDim.x + threadIdx.x;
    if (i < n4) g_mid4[i] = make_float4(0.f, 0.f, 0.f, 0.f);
}

// ---------------- node up-projection ----------------------------------------
__global__ void up_kernel(const float* __restrict__ f_in,
                          const float* __restrict__ Wu0,
                          const float* __restrict__ Wu1,
                          const float* __restrict__ Wu2) {
    const int n = blockIdx.x;
    const int t = threadIdx.x;  // 288
    __shared__ float fs[288];
    fs[t] = f_in[n * 288 + t];
    __syncthreads();
    int i, off, w, d, slot;
    const float* W;
    if (t < 32)       { w = t;         i = 0;         d = 1; off = 0;   W = Wu0; slot = 0; }
    else if (t < 128) { int c = t-32;  w = c/3; i = c%3; d = 3; off = 32;  W = Wu1; slot = 1 + i; }
    else              { int c = t-128; w = c/5; i = c%5; d = 5; off = 128; W = Wu2; slot = 4 + i; }
    float acc = 0.f;
#pragma unroll 8
    for (int u = 0; u < 32; u++)
        acc = fmaf(fs[off + u * d + i], __ldg(W + u * 32 + w), acc);
    reinterpret_cast<float*>(g_xs4)[n * 384 + w * 12 + slot] = acc * 0.17677669529663687f;
}

// ---------------- radial MLP 64->64 layer (4 edges per warp) ----------------
__device__ __forceinline__ void mlp64(const float* __restrict__ in,
                                      float* __restrict__ out,
                                      const float* __restrict__ W,
                                      int o0, float cst) {
    float a0[4] = {0,0,0,0}, a1[4] = {0,0,0,0};
#pragma unroll 2
    for (int j4 = 0; j4 < 16; j4++) {
        float h0[4], h1[4], h2[4], h3[4];
#pragma unroll
        for (int e = 0; e < 4; e++) {
            float4 v = *reinterpret_cast<const float4*>(in + e * 64 + j4 * 4);
            h0[e] = v.x; h1[e] = v.y; h2[e] = v.z; h3[e] = v.w;
        }
#pragma unroll
        for (int jj = 0; jj < 4; jj++) {
            float2 wv = *reinterpret_cast<const float2*>(W + (j4 * 4 + jj) * 64 + o0);
#pragma unroll
            for (int e = 0; e < 4; e++) {
                float hv = (jj == 0) ? h0[e] : (jj == 1) ? h1[e] : (jj == 2) ? h2[e] : h3[e];
                a0[e] = fmaf(hv, wv.x, a0[e]);
                a1[e] = fmaf(hv, wv.y, a1[e]);
            }
        }
    }
#pragma unroll
    for (int e = 0; e < 4; e++) {
        *reinterpret_cast<float2*>(out + e * 64 + o0) =
            make_float2(silu_f(a0[e] * 0.125f) * cst, silu_f(a1[e] * 0.125f) * cst);
    }
}

// ---------------- fused per-edge kernel (warp handles 4 edges) --------------
__global__ void __launch_bounds__(256) edge_kernel(
    const float* __restrict__ pos, const int* __restrict__ batch,
    const int* __restrict__ esrc, const int* __restrict__ edst,
    const float* __restrict__ shifts, const float* __restrict__ cell,
    const float* __restrict__ Wr0, const float* __restrict__ Wr1,
    const float* __restrict__ Wr2, const float* __restrict__ Wr3, int E)
{
    extern __shared__ float sm[];
    const int wid  = threadIdx.x >> 5;
    const int lane = threadIdx.x & 31;
    float* hA  = sm + (wid * 4) * 64;                 // [4][64]
    float* hB  = sm + 2048 + (wid * 4) * 64;          // [4][64]
    float* wsm = sm + 4096 + (wid * 4) * 352;         // [4][352]

    const int base = (blockIdx.x * 8 + wid) * 4;
    const float cst = g_cst;

    float uxr[4], uyr[4], uzr[4], Lr[4];
#pragma unroll
    for (int e = 0; e < 4; e++) {
        int ei = (base + e < E) ? base + e : E - 1;
        const int src = __ldg(esrc + ei);
        const int dst = __ldg(edst + ei);
        const float sx = __ldg(shifts + 3*ei), sy = __ldg(shifts + 3*ei+1), sz = __ldg(shifts + 3*ei+2);
        const float* Cc = cell + 9 * __ldg(batch + src);
        float vx = __ldg(pos+3*dst+0) - __ldg(pos+3*src+0) + sx*__ldg(Cc+0) + sy*__ldg(Cc+3) + sz*__ldg(Cc+6);
        float vy = __ldg(pos+3*dst+1) - __ldg(pos+3*src+1) + sx*__ldg(Cc+1) + sy*__ldg(Cc+4) + sz*__ldg(Cc+7);
        float vz = __ldg(pos+3*dst+2) - __ldg(pos+3*src+2) + sx*__ldg(Cc+2) + sy*__ldg(Cc+5) + sz*__ldg(Cc+8);
        float L = sqrtf(vx*vx + vy*vy + vz*vz);
        float inv = 1.0f / fmaxf(L, 1e-12f);
        uxr[e] = vx*inv; uyr[e] = vy*inv; uzr[e] = vz*inv; Lr[e] = L;
    }

    // ---- radial embedding, cooperative: one expf per lane ----
    {
        const int k = lane & 7;
        float Ls = (lane < 8) ? Lr[0] : (lane < 16) ? Lr[1] : (lane < 24) ? Lr[2] : Lr[3];
        float tt = (Ls - (float)(k + 1) * (5.0f / 9.0f)) * 1.8f;
        hB[(lane >> 3) * 64 + k] = __expf(-tt * tt) * 2.525381361380527f;  // sqrt(8)/1.12
    }
    __syncwarp();

    const int o0 = lane * 2;
    // ---- layer 1: 8 -> 64 (hB -> hA) ----
    {
        float a0[4] = {0,0,0,0}, a1[4] = {0,0,0,0};
#pragma unroll
        for (int j = 0; j < 8; j++) {
            float2 wv = *reinterpret_cast<const float2*>(Wr0 + j * 64 + o0);
#pragma unroll
            for (int e = 0; e < 4; e++) {
                float hv = hB[e * 64 + j];
                a0[e] = fmaf(hv, wv.x, a0[e]);
                a1[e] = fmaf(hv, wv.y, a1[e]);
            }
        }
#pragma unroll
        for (int e = 0; e < 4; e++) {
            *reinterpret_cast<float2*>(hA + e * 64 + o0) =
                make_float2(silu_f(a0[e] * 0.35355339059327373f) * cst,
                            silu_f(a1[e] * 0.35355339059327373f) * cst);
        }
    }
    __syncwarp();
    mlp64(hA, hB, Wr1, o0, cst);   // layer 2
    __syncwarp();
    mlp64(hB, hA, Wr2, o0, cst);   // layer 3
    __syncwarp();

    // ---- layer 4: 64 -> 352 (hA -> wsm), weights amortized over 4 edges ----
    {
        float4 acc0[4], acc1[4], acc2[4];
#pragma unroll
        for (int e = 0; e < 4; e++) {
            acc0[e] = make_float4(0,0,0,0); acc1[e] = acc0[e]; acc2[e] = acc0[e];
        }
        const float4* W3 = reinterpret_cast<const float4*>(Wr3);  // row stride 88 float4
#pragma unroll 1
        for (int j4 = 0; j4 < 16; j4++) {
            float h0[4], h1[4], h2[4], h3[4];
#pragma unroll
            for (int e = 0; e < 4; e++) {
                float4 v = *reinterpret_cast<const float4*>(hA + e * 64 + j4 * 4);
                h0[e] = v.x; h1[e] = v.y; h2[e] = v.z; h3[e] = v.w;
            }
#pragma unroll
            for (int jj = 0; jj < 4; jj++) {
                const float4* r = W3 + (j4 * 4 + jj) * 88;
                float4 w0 = __ldg(r + lane);
                float4 w1 = __ldg(r + lane + 32);
                float4 w2;
                if (lane < 24) w2 = __ldg(r + lane + 64);
#pragma unroll
                for (int e = 0; e < 4; e++) {
                    float hv = (jj == 0) ? h0[e] : (jj == 1) ? h1[e] : (jj == 2) ? h2[e] : h3[e];
                    acc0[e].x = fmaf(hv, w0.x, acc0[e].x); acc0[e].y = fmaf(hv, w0.y, acc0[e].y);
                    acc0[e].z = fmaf(hv, w0.z, acc0[e].z); acc0[e].w = fmaf(hv, w0.w, acc0[e].w);
                    acc1[e].x = fmaf(hv, w1.x, acc1[e].x); acc1[e].y = fmaf(hv, w1.y, acc1[e].y);
                    acc1[e].z = fmaf(hv, w1.z, acc1[e].z); acc1[e].w = fmaf(hv, w1.w, acc1[e].w);
                    if (lane < 24) {
                        acc2[e].x = fmaf(hv, w2.x, acc2[e].x); acc2[e].y = fmaf(hv, w2.y, acc2[e].y);
                        acc2[e].z = fmaf(hv, w2.z, acc2[e].z); acc2[e].w = fmaf(hv, w2.w, acc2[e].w);
                    }
                }
            }
        }
#pragma unroll
        for (int e = 0; e < 4; e++) {
            float4* wsf4 = reinterpret_cast<float4*>(wsm + e * 352);
            float4 a = acc0[e]; a.x *= 0.125f; a.y *= 0.125f; a.z *= 0.125f; a.w *= 0.125f;
            wsf4[lane] = a;
            a = acc1[e]; a.x *= 0.125f; a.y *= 0.125f; a.z *= 0.125f; a.w *= 0.125f;
            wsf4[lane + 32] = a;
            if (lane < 24) {
                a = acc2[e]; a.x *= 0.125f; a.y *= 0.125f; a.z *= 0.125f; a.w *= 0.125f;
                wsf4[lane + 64] = a;
            }
        }
    }
    __syncwarp();

    // ---- tensor product + vector atomics, per edge ----
    const float A_  = 0.31622776601683794f;  // 1/sqrt(10)
    const float B_  = 0.18257418583505536f;  // 1/sqrt(30)
    const float AL  = 0.11952286093343936f;  // 1/sqrt(70)
    const float BE  = 0.20701966780270626f;  // sqrt(3/70)
    const float SQ3 = 1.7320508075688772f;
    const float SQ5 = 2.23606797749979f;

#pragma unroll
    for (int e = 0; e < 4; e++) {
        if (base + e >= E) break;
        const int src = __ldg(esrc + base + e);
        const int dst = __ldg(edst + base + e);

        const float ux = uxr[e], uy = uyr[e], uz = uzr[e];
        const float s1x = SQ3 * ux, s1y = SQ3 * uy, s1z = SQ3 * uz;
        const float s20 = 3.872983346207417f * ux * uz;
        const float s21 = 3.872983346207417f * ux * uy;
        const float s22 = SQ5 * (uy*uy - 0.5f*(ux*ux + uz*uz));
        const float s23 = 3.872983346207417f * uy * uz;
        const float s24 = 1.9364916731037085f * (uz*uz - ux*ux);

        // radial weights for this lane's u channel
        float w[11];
#pragma unroll
        for (int k = 0; k < 11; k++) w[k] = wsm[e * 352 + k * 32 + lane];

        // source features (vectorized)
        const float4* xp = g_xs4 + src * 96 + lane * 3;
        const float4 xa = __ldg(xp);        // x0, x10, x11, x12
        const float4 xb = __ldg(xp + 1);    // x20, x21, x22, x23
        const float4 xc = __ldg(xp + 2);    // x24, pad...
        const float x0 = xa.x;
        const float x10 = xa.y, x11 = xa.z, x12 = xa.w;
        const float x20 = xb.x, x21 = xb.y, x22 = xb.z, x23 = xb.w, x24 = xc.x;

        // l0 outputs
        const float p0 = x0 * w[0];
        const float p1 = 0.5773502691896258f * (x10*s1x + x11*s1y + x12*s1z) * w[1];
        const float p2 = 0.4472135954999579f * (x20*s20 + x21*s21 + x22*s22 + x23*s23 + x24*s24) * w[2];

        // l1 outputs
        const float c3 = x0 * w[3];
        const float p3x = c3 * s1x, p3y = c3 * s1y, p3z = c3 * s1z;
        const float p4x = x10 * w[4], p4y = x11 * w[4], p4z = x12 * w[4];
        float p5x, p5y, p5z;
        {
            float wv = SQ3 * w[5];
            float B00 = -B_*s22 - A_*s24;
            float B01 =  A_*s21;
            float B02 =  A_*s20;
            float B11 =  2.f*B_*s22;
            float B12 =  A_*s23;
            float B22 = -B_*s22 + A_*s24;
            p5x = wv * (x10*B00 + x11*B01 + x12*B02);
            p5y = wv * (x10*B01 + x11*B11 + x12*B12);
            p5z = wv * (x10*B02 + x11*B12 + x12*B22);
        }
        float p6x, p6y, p6z;
        {
            float wv = SQ3 * w[6];
            p6x = wv * (A_*(x20*s1z + x21*s1y) - B_*x22*s1x - A_*x24*s1x);
            p6y = wv * (A_*(x21*s1x + x23*s1z) + 2.f*B_*x22*s1y);
            p6z = wv * (A_*(x20*s1x + x23*s1y + x24*s1z) - B_*x22*s1z);
        }

        // l2 outputs
        const float c7 = x0 * w[7];
        const float p70 = c7*s20, p71 = c7*s21, p72 = c7*s22, p73 = c7*s23, p74 = c7*s24;
        float p80, p81, p82, p83, p84;
        {
            float wv = SQ5 * w[8];
            p80 = wv * (A_*(x10*s1z + x12*s1x));
            p81 = wv * (A_*(x10*s1y + x11*s1x));
            p82 = wv * (B_*(-x10*s1x + 2.f*x11*s1y - x12*s1z));
            p83 = wv * (A_*(x11*s1z + x12*s1y));
            p84 = wv * (A_*(-x10*s1x + x12*s1z));
        }
        const float p90 = x20*w[9], p91 = x21*w[9], p92 = x22*w[9], p93 = x23*w[9], p94 = x24*w[9];
        float pa0, pa1, pa2, pa3, pa4;
        {
            float wv = SQ5 * w[10];
            pa0 = wv * (x20*(2.f*AL*s22) + x21*(-BE*s23) + x22*(2.f*AL*s20) + x23*(-BE*s21));
            pa1 = wv * (x20*(-BE*s23) + x21*(-AL*s22 + BE*s24) + x22*(-AL*s21) + x23*(-BE*s20) + x24*(BE*s21));
            pa2 = wv * (x20*(2.f*AL*s20) + x21*(-AL*s21) + x22*(-2.f*AL*s22) + x23*(-AL*s23) + x24*(2.f*AL*s24));
            pa3 = wv * (x20*(-BE*s21) + x21*(-BE*s20) + x22*(-AL*s23) + x23*(-AL*s22 - BE*s24) + x24*(-BE*s23));
            pa4 = wv * (x21*(BE*s21) + x22*(2.f*AL*s24) + x23*(-BE*s23) + x24*(2.f*AL*s22));
        }

        float* mb = reinterpret_cast<float*>(g_mid4) + dst * 1152;
        atomicAdd(reinterpret_cast<float4*>(mb + lane * 4), make_float4(p0, p1, p2, 0.f));
        float4* mb1 = reinterpret_cast<float4*>(mb + 128 + lane * 12);
        atomicAdd(mb1 + 0, make_float4(p3x, p3y, p3z, p4x));
        atomicAdd(mb1 + 1, make_float4(p4y, p4z, p5x, p5y));
        atomicAdd(mb1 + 2, make_float4(p5z, p6x, p6y, p6z));
        float4* mb2 = reinterpret_cast<float4*>(mb + 512 + lane * 20);
        atomicAdd(mb2 + 0, make_float4(p70, p71, p72, p73));
        atomicAdd(mb2 + 1, make_float4(p74, p80, p81, p82));
        atomicAdd(mb2 + 2, make_float4(p83, p84, p90, p91));
        atomicAdd(mb2 + 3, make_float4(p92, p93, p94, pa0));
        atomicAdd(mb2 + 4, make_float4(pa1, pa2, pa3, pa4));
    }
}

// ---------------- per-node output projection --------------------------------
__global__ void out_kernel(const float* __restrict__ Wo0,
                           const float* __restrict__ Wo1,
                           const float* __restrict__ Wo2,
                           float* __restrict__ out) {
    const int n = blockIdx.x;
    const int t = threadIdx.x;  // 288
    __shared__ float ms[1152];
    reinterpret_cast<float4*>(ms)[t] = g_mid4[n * 288 + t];
    __syncthreads();

    float acc = 0.f;
    if (t < 32) {
#pragma unroll
        for (int s = 0; s < 3; s++)
#pragma unroll 8
            for (int u = 0; u < 32; u++)
                acc = fmaf(ms[u * 4 + s], __ldg(Wo0 + (s * 32 + u) * 32 + t), acc);
        acc *= 0.006378879538497859f;   // 1/(sqrt(96)*16)
    } else if (t < 128) {
        int c = t - 32, w = c / 3, i = c % 3;
#pragma unroll
        for (int s = 0; s < 4; s++)
#pragma unroll 8
            for (int u = 0; u < 32; u++)
                acc = fmaf(ms[128 + u * 12 + s * 3 + i], __ldg(Wo1 + (s * 32 + u) * 32 + w), acc);
        acc *= 0.005524271728019903f;   // 1/(sqrt(128)*16)
    } else {
        int c = t - 128, w = c / 5, i = c % 5;
#pragma unroll
        for (int s = 0; s < 4; s++)
#pragma unroll 8
            for (int u = 0; u < 32; u++)
                acc = fmaf(ms[512 + u * 20 + s * 5 + i], __ldg(Wo2 + (s * 32 + u) * 32 + w), acc);
        acc *= 0.005524271728019903f;
    }
    out[n * 288 + t] = acc;
}

// ---------------- launch -----------------------------------------------------
extern "C" void kernel_launch(void* const* d_in, const int* in_sizes, int n_in,
                              void* d_out, int out_size) {
    const float* f_in   = (const float*)d_in[0];
    const float* pos    = (const float*)d_in[1];
    const int*   batch  = (const int*)d_in[2];
    const int*   esrc   = (const int*)d_in[3];
    const int*   edst   = (const int*)d_in[4];
    const float* shifts = (const float*)d_in[5];
    const float* cell   = (const float*)d_in[6];
    const int wb = n_in - 10;
    const float* Wu0 = (const float*)d_in[wb + 0];
    const float* Wu1 = (const float*)d_in[wb + 1];
    const float* Wu2 = (const float*)d_in[wb + 2];
    const float* Wr0 = (const float*)d_in[wb + 3];
    const float* Wr1 = (const float*)d_in[wb + 4];
    const float* Wr2 = (const float*)d_in[wb + 5];
    const float* Wr3 = (const float*)d_in[wb + 6];
    const float* Wo0 = (const float*)d_in[wb + 7];
    const float* Wo1 = (const float*)d_in[wb + 8];
    const float* Wo2 = (const float*)d_in[wb + 9];

    const int N = in_sizes[0] / 288;
    const int E = in_sizes[3];

    static int smem_set = 0;
    const int smem_bytes = (2048 + 2048 + 8 * 4 * 352) * 4;  // 61440
    if (!smem_set) {
        cudaFuncSetAttribute(edge_kernel, cudaFuncAttributeMaxDynamicSharedMemorySize, smem_bytes);
        smem_set = 1;
    }

    cst_kernel<<<1, 256>>>();
    const int n4 = N * 288;
    zero_kernel<<<(n4 + 255) / 256, 256>>>(n4);
    up_kernel<<<N, 288>>>(f_in, Wu0, Wu1, Wu2);
    edge_kernel<<<(E + 31) / 32, 256, smem_bytes>>>(pos, batch, esrc, edst, shifts, cell,
                                                    Wr0, Wr1, Wr2, Wr3, E);
    out_kernel<<<N, 288>>>(Wo0, Wo1, Wo2, (float*)d_out);
}

// round 6
// speedup vs baseline: 1.0549x; 1.0549x over previous
#include <cuda_runtime.h>
#include <math.h>

#define MAXN 10000

// ---------------- device scratch --------------------------------------------
__device__ float  g_cst;                       // CST_SILU
__device__ float  g_xs[MAXN * 288];            // up-projected node features, [node][slot 0..8][u 0..31]
__device__ float4 g_mid4[MAXN * 320];          // aggregated messages, 1280 f/node

// g_xs per-node layout (288 floats): slot*32 + u, slot = {x0, x1_0..2, x2_0..4}
//
// g_mid per-node layout (1280 floats), all blocks u-major float4 groups:
//   A [0,128):      u*4 + s        s = path0,path1,path2,(pad)          (l0)
//   B [128,640):    128 + q*128 + u*4 + i   q=l1 path 0..3, i=x,y,z,(pad)
//   C [640,1152):   640 + r*128 + u*4 + c   r=l2 path 0..3, c=0..3
//   D [1152,1280):  1152 + u*4 + r          comp4 of l2 path r

__device__ __forceinline__ float silu_f(float v) {
    return __fdividef(v, 1.0f + __expf(-v));
}

// ---------------- CST_SILU via composite Simpson (double) -------------------
__global__ void cst_kernel() {
    __shared__ double red[256];
    const int t = threadIdx.x;
    const int NI = 4096;
    const double h = 24.0 / NI;
    double s = 0.0;
    for (int i = t; i <= NI; i += 256) {
        double xx = -12.0 + h * i;
        double sig = 1.0 / (1.0 + exp(-xx));
        double f = xx * sig;
        f = f * f * exp(-0.5 * xx * xx);
        double c = (i == 0 || i == NI) ? 1.0 : ((i & 1) ? 4.0 : 2.0);
        s += c * f;
    }
    red[t] = s;
    __syncthreads();
    for (int o = 128; o > 0; o >>= 1) {
        if (t < o) red[t] += red[t + o];
        __syncthreads();
    }
    if (t == 0) {
        double I = red[0] * h / 3.0 / 2.5066282746310005024;
        g_cst = (float)(1.0 / sqrt(I));
    }
}

// ---------------- zero mid ---------------------------------------------------
__global__ void zero_kernel(int n4) {
    int i = blockIdx.x * blockDim.x + threadIdx.x;
    if (i < n4) g_mid4[i] = make_float4(0.f, 0.f, 0.f, 0.f);
}

// ---------------- node up-projection ----------------------------------------
__global__ void up_kernel(const float* __restrict__ f_in,
                          const float* __restrict__ Wu0,
                          const float* __restrict__ Wu1,
                          const float* __restrict__ Wu2) {
    const int n = blockIdx.x;
    const int t = threadIdx.x;  // 288
    __shared__ float fs[288];
    fs[t] = f_in[n * 288 + t];
    __syncthreads();
    int i, off, w, d, slot;
    const float* W;
    if (t < 32)       { w = t;         i = 0;         d = 1; off = 0;   W = Wu0; slot = 0; }
    else if (t < 128) { int c = t-32;  w = c/3; i = c%3; d = 3; off = 32;  W = Wu1; slot = 1 + i; }
    else              { int c = t-128; w = c/5; i = c%5; d = 5; off = 128; W = Wu2; slot = 4 + i; }
    float acc = 0.f;
#pragma unroll 8
    for (int u = 0; u < 32; u++)
        acc = fmaf(fs[off + u * d + i], __ldg(W + u * 32 + w), acc);
    g_xs[n * 288 + slot * 32 + w] = acc * 0.17677669529663687f;
}

// ---------------- radial MLP 64->64 layer (4 edges per warp) ----------------
__device__ __forceinline__ void mlp64(const float* __restrict__ in,
                                      float* __restrict__ out,
                                      const float* __restrict__ W,
                                      int o0, float cst) {
    float a0[4] = {0,0,0,0}, a1[4] = {0,0,0,0};
#pragma unroll 2
    for (int j4 = 0; j4 < 16; j4++) {
        float h0[4], h1[4], h2[4], h3[4];
#pragma unroll
        for (int e = 0; e < 4; e++) {
            float4 v = *reinterpret_cast<const float4*>(in + e * 64 + j4 * 4);
            h0[e] = v.x; h1[e] = v.y; h2[e] = v.z; h3[e] = v.w;
        }
#pragma unroll
        for (int jj = 0; jj < 4; jj++) {
            float2 wv = *reinterpret_cast<const float2*>(W + (j4 * 4 + jj) * 64 + o0);
#pragma unroll
            for (int e = 0; e < 4; e++) {
                float hv = (jj == 0) ? h0[e] : (jj == 1) ? h1[e] : (jj == 2) ? h2[e] : h3[e];
                a0[e] = fmaf(hv, wv.x, a0[e]);
                a1[e] = fmaf(hv, wv.y, a1[e]);
            }
        }
    }
#pragma unroll
    for (int e = 0; e < 4; e++) {
        *reinterpret_cast<float2*>(out + e * 64 + o0) =
            make_float2(silu_f(a0[e] * 0.125f) * cst, silu_f(a1[e] * 0.125f) * cst);
    }
}

// ---------------- fused per-edge kernel (warp handles 4 edges) --------------
__global__ void __launch_bounds__(256) edge_kernel(
    const float* __restrict__ pos, const int* __restrict__ batch,
    const int* __restrict__ esrc, const int* __restrict__ edst,
    const float* __restrict__ shifts, const float* __restrict__ cell,
    const float* __restrict__ Wr0, const float* __restrict__ Wr1,
    const float* __restrict__ Wr2, const float* __restrict__ Wr3, int E)
{
    extern __shared__ float sm[];
    const int wid  = threadIdx.x >> 5;
    const int lane = threadIdx.x & 31;
    float* hA  = sm + (wid * 4) * 64;                 // [4][64]
    float* hB  = sm + 2048 + (wid * 4) * 64;          // [4][64]
    float* wsm = sm + 4096 + (wid * 4) * 352;         // [4][352]

    const int base = (blockIdx.x * 8 + wid) * 4;
    const float cst = g_cst;

    float uxr[4], uyr[4], uzr[4], Lr[4];
#pragma unroll
    for (int e = 0; e < 4; e++) {
        int ei = (base + e < E) ? base + e : E - 1;
        const int src = __ldg(esrc + ei);
        const int dst = __ldg(edst + ei);
        const float sx = __ldg(shifts + 3*ei), sy = __ldg(shifts + 3*ei+1), sz = __ldg(shifts + 3*ei+2);
        const float* Cc = cell + 9 * __ldg(batch + src);
        float vx = __ldg(pos+3*dst+0) - __ldg(pos+3*src+0) + sx*__ldg(Cc+0) + sy*__ldg(Cc+3) + sz*__ldg(Cc+6);
        float vy = __ldg(pos+3*dst+1) - __ldg(pos+3*src+1) + sx*__ldg(Cc+1) + sy*__ldg(Cc+4) + sz*__ldg(Cc+7);
        float vz = __ldg(pos+3*dst+2) - __ldg(pos+3*src+2) + sx*__ldg(Cc+2) + sy*__ldg(Cc+5) + sz*__ldg(Cc+8);
        float L = sqrtf(vx*vx + vy*vy + vz*vz);
        float inv = 1.0f / fmaxf(L, 1e-12f);
        uxr[e] = vx*inv; uyr[e] = vy*inv; uzr[e] = vz*inv; Lr[e] = L;
    }

    // ---- radial embedding, cooperative: one expf per lane ----
    {
        const int k = lane & 7;
        float Ls = (lane < 8) ? Lr[0] : (lane < 16) ? Lr[1] : (lane < 24) ? Lr[2] : Lr[3];
        float tt = (Ls - (float)(k + 1) * (5.0f / 9.0f)) * 1.8f;
        hB[(lane >> 3) * 64 + k] = __expf(-tt * tt) * 2.525381361380527f;  // sqrt(8)/1.12
    }
    __syncwarp();

    const int o0 = lane * 2;
    // ---- layer 1: 8 -> 64 (hB -> hA) ----
    {
        float a0[4] = {0,0,0,0}, a1[4] = {0,0,0,0};
#pragma unroll
        for (int j = 0; j < 8; j++) {
            float2 wv = *reinterpret_cast<const float2*>(Wr0 + j * 64 + o0);
#pragma unroll
            for (int e = 0; e < 4; e++) {
                float hv = hB[e * 64 + j];
                a0[e] = fmaf(hv, wv.x, a0[e]);
                a1[e] = fmaf(hv, wv.y, a1[e]);
            }
        }
#pragma unroll
        for (int e = 0; e < 4; e++) {
            *reinterpret_cast<float2*>(hA + e * 64 + o0) =
                make_float2(silu_f(a0[e] * 0.35355339059327373f) * cst,
                            silu_f(a1[e] * 0.35355339059327373f) * cst);
        }
    }
    __syncwarp();
    mlp64(hA, hB, Wr1, o0, cst);   // layer 2
    __syncwarp();
    mlp64(hB, hA, Wr2, o0, cst);   // layer 3
    __syncwarp();

    // ---- layer 4: 64 -> 352 (hA -> wsm), weights amortized over 4 edges ----
    {
        float4 acc0[4], acc1[4], acc2[4];
#pragma unroll
        for (int e = 0; e < 4; e++) {
            acc0[e] = make_float4(0,0,0,0); acc1[e] = acc0[e]; acc2[e] = acc0[e];
        }
        const float4* W3 = reinterpret_cast<const float4*>(Wr3);  // row stride 88 float4
#pragma unroll 1
        for (int j4 = 0; j4 < 16; j4++) {
            float h0[4], h1[4], h2[4], h3[4];
#pragma unroll
            for (int e = 0; e < 4; e++) {
                float4 v = *reinterpret_cast<const float4*>(hA + e * 64 + j4 * 4);
                h0[e] = v.x; h1[e] = v.y; h2[e] = v.z; h3[e] = v.w;
            }
#pragma unroll
            for (int jj = 0; jj < 4; jj++) {
                const float4* r = W3 + (j4 * 4 + jj) * 88;
                float4 w0 = __ldg(r + lane);
                float4 w1 = __ldg(r + lane + 32);
                float4 w2;
                if (lane < 24) w2 = __ldg(r + lane + 64);
#pragma unroll
                for (int e = 0; e < 4; e++) {
                    float hv = (jj == 0) ? h0[e] : (jj == 1) ? h1[e] : (jj == 2) ? h2[e] : h3[e];
                    acc0[e].x = fmaf(hv, w0.x, acc0[e].x); acc0[e].y = fmaf(hv, w0.y, acc0[e].y);
                    acc0[e].z = fmaf(hv, w0.z, acc0[e].z); acc0[e].w = fmaf(hv, w0.w, acc0[e].w);
                    acc1[e].x = fmaf(hv, w1.x, acc1[e].x); acc1[e].y = fmaf(hv, w1.y, acc1[e].y);
                    acc1[e].z = fmaf(hv, w1.z, acc1[e].z); acc1[e].w = fmaf(hv, w1.w, acc1[e].w);
                    if (lane < 24) {
                        acc2[e].x = fmaf(hv, w2.x, acc2[e].x); acc2[e].y = fmaf(hv, w2.y, acc2[e].y);
                        acc2[e].z = fmaf(hv, w2.z, acc2[e].z); acc2[e].w = fmaf(hv, w2.w, acc2[e].w);
                    }
                }
            }
        }
#pragma unroll
        for (int e = 0; e < 4; e++) {
            float4* wsf4 = reinterpret_cast<float4*>(wsm + e * 352);
            float4 a = acc0[e]; a.x *= 0.125f; a.y *= 0.125f; a.z *= 0.125f; a.w *= 0.125f;
            wsf4[lane] = a;
            a = acc1[e]; a.x *= 0.125f; a.y *= 0.125f; a.z *= 0.125f; a.w *= 0.125f;
            wsf4[lane + 32] = a;
            if (lane < 24) {
                a = acc2[e]; a.x *= 0.125f; a.y *= 0.125f; a.z *= 0.125f; a.w *= 0.125f;
                wsf4[lane + 64] = a;
            }
        }
    }
    __syncwarp();

    // ---- tensor product + coalesced vector atomics, per edge ----
    const float A_  = 0.31622776601683794f;  // 1/sqrt(10)
    const float B_  = 0.18257418583505536f;  // 1/sqrt(30)
    const float AL  = 0.11952286093343936f;  // 1/sqrt(70)
    const float BE  = 0.20701966780270626f;  // sqrt(3/70)
    const float SQ3 = 1.7320508075688772f;
    const float SQ5 = 2.23606797749979f;

#pragma unroll
    for (int e = 0; e < 4; e++) {
        if (base + e >= E) break;
        const int src = __ldg(esrc + base + e);
        const int dst = __ldg(edst + base + e);

        const float ux = uxr[e], uy = uyr[e], uz = uzr[e];
        const float s1x = SQ3 * ux, s1y = SQ3 * uy, s1z = SQ3 * uz;
        const float s20 = 3.872983346207417f * ux * uz;
        const float s21 = 3.872983346207417f * ux * uy;
        const float s22 = SQ5 * (uy*uy - 0.5f*(ux*ux + uz*uz));
        const float s23 = 3.872983346207417f * uy * uz;
        const float s24 = 1.9364916731037085f * (uz*uz - ux*ux);

        // radial weights for this lane's u channel (coalesced LDS)
        float w[11];
#pragma unroll
        for (int k = 0; k < 11; k++) w[k] = wsm[e * 352 + k * 32 + lane];

        // source features: coalesced scalar loads from [src][slot][u]
        const float* xp = g_xs + src * 288 + lane;
        const float x0  = __ldg(xp);
        const float x10 = __ldg(xp + 32),  x11 = __ldg(xp + 64),  x12 = __ldg(xp + 96);
        const float x20 = __ldg(xp + 128), x21 = __ldg(xp + 160), x22 = __ldg(xp + 192);
        const float x23 = __ldg(xp + 224), x24 = __ldg(xp + 256);

        // l0 outputs
        const float p0 = x0 * w[0];
        const float p1 = 0.5773502691896258f * (x10*s1x + x11*s1y + x12*s1z) * w[1];
        const float p2 = 0.4472135954999579f * (x20*s20 + x21*s21 + x22*s22 + x23*s23 + x24*s24) * w[2];

        // l1 outputs
        const float c3 = x0 * w[3];
        const float p3x = c3 * s1x, p3y = c3 * s1y, p3z = c3 * s1z;
        const float p4x = x10 * w[4], p4y = x11 * w[4], p4z = x12 * w[4];
        float p5x, p5y, p5z;
        {
            float wv = SQ3 * w[5];
            float B00 = -B_*s22 - A_*s24;
            float B01 =  A_*s21;
            float B02 =  A_*s20;
            float B11 =  2.f*B_*s22;
            float B12 =  A_*s23;
            float B22 = -B_*s22 + A_*s24;
            p5x = wv * (x10*B00 + x11*B01 + x12*B02);
            p5y = wv * (x10*B01 + x11*B11 + x12*B12);
            p5z = wv * (x10*B02 + x11*B12 + x12*B22);
        }
        float p6x, p6y, p6z;
        {
            float wv = SQ3 * w[6];
            p6x = wv * (A_*(x20*s1z + x21*s1y) - B_*x22*s1x - A_*x24*s1x);
            p6y = wv * (A_*(x21*s1x + x23*s1z) + 2.f*B_*x22*s1y);
            p6z = wv * (A_*(x20*s1x + x23*s1y + x24*s1z) - B_*x22*s1z);
        }

        // l2 outputs
        const float c7 = x0 * w[7];
        const float p70 = c7*s20, p71 = c7*s21, p72 = c7*s22, p73 = c7*s23, p74 = c7*s24;
        float p80, p81, p82, p83, p84;
        {
            float wv = SQ5 * w[8];
            p80 = wv * (A_*(x10*s1z + x12*s1x));
            p81 = wv * (A_*(x10*s1y + x11*s1x));
            p82 = wv * (B_*(-x10*s1x + 2.f*x11*s1y - x12*s1z));
            p83 = wv * (A_*(x11*s1z + x12*s1y));
            p84 = wv * (A_*(-x10*s1x + x12*s1z));
        }
        const float p90 = x20*w[9], p91 = x21*w[9], p92 = x22*w[9], p93 = x23*w[9], p94 = x24*w[9];
        float pa0, pa1, pa2, pa3, pa4;
        {
            float wv = SQ5 * w[10];
            pa0 = wv * (x20*(2.f*AL*s22) + x21*(-BE*s23) + x22*(2.f*AL*s20) + x23*(-BE*s21));
            pa1 = wv * (x20*(-BE*s23) + x21*(-AL*s22 + BE*s24) + x22*(-AL*s21) + x23*(-BE*s20) + x24*(BE*s21));
            pa2 = wv * (x20*(2.f*AL*s20) + x21*(-AL*s21) + x22*(-2.f*AL*s22) + x23*(-AL*s23) + x24*(2.f*AL*s24));
            pa3 = wv * (x20*(-BE*s21) + x21*(-BE*s20) + x22*(-AL*s23) + x23*(-AL*s22 - BE*s24) + x24*(-BE*s23));
            pa4 = wv * (x21*(BE*s21) + x22*(2.f*AL*s24) + x23*(-BE*s23) + x24*(2.f*AL*s22));
        }

        // 10 warp-coalesced float4 atomics (each spans exactly 512B)
        float4* mb = reinterpret_cast<float4*>(reinterpret_cast<float*>(g_mid4) + dst * 1280) + lane;
        atomicAdd(mb,       make_float4(p0, p1, p2, 0.f));          // A
        atomicAdd(mb + 32,  make_float4(p3x, p3y, p3z, 0.f));       // B q=0
        atomicAdd(mb + 64,  make_float4(p4x, p4y, p4z, 0.f));       // B q=1
        atomicAdd(mb + 96,  make_float4(p5x, p5y, p5z, 0.f));       // B q=2
        atomicAdd(mb + 128, make_float4(p6x, p6y, p6z, 0.f));       // B q=3
        atomicAdd(mb + 160, make_float4(p70, p71, p72, p73));       // C r=0
        atomicAdd(mb + 192, make_float4(p80, p81, p82, p83));       // C r=1
        atomicAdd(mb + 224, make_float4(p90, p91, p92, p93));       // C r=2
        atomicAdd(mb + 256, make_float4(pa0, pa1, pa2, pa3));       // C r=3
        atomicAdd(mb + 288, make_float4(p74, p84, p94, pa4));       // D
    }
}

// ---------------- per-node output projection --------------------------------
__global__ void out_kernel(const float* __restrict__ Wo0,
                           const float* __restrict__ Wo1,
                           const float* __restrict__ Wo2,
                           float* __restrict__ out) {
    const int n = blockIdx.x;
    const int t = threadIdx.x;  // 288
    __shared__ float ms[1280];
    for (int j = t; j < 320; j += 288)
        reinterpret_cast<float4*>(ms)[j] = g_mid4[n * 320 + j];
    __syncthreads();

    float acc = 0.f;
    if (t < 32) {
#pragma unroll
        for (int s = 0; s < 3; s++)
#pragma unroll 8
            for (int u = 0; u < 32; u++)
                acc = fmaf(ms[u * 4 + s], __ldg(Wo0 + (s * 32 + u) * 32 + t), acc);
        acc *= 0.006378879538497859f;   // 1/(sqrt(96)*16)
    } else if (t < 128) {
        int c = t - 32, w = c / 3, i = c % 3;
#pragma unroll
        for (int q = 0; q < 4; q++)
#pragma unroll 8
            for (int u = 0; u < 32; u++)
                acc = fmaf(ms[128 + q * 128 + u * 4 + i], __ldg(Wo1 + (q * 32 + u) * 32 + w), acc);
        acc *= 0.005524271728019903f;   // 1/(sqrt(128)*16)
    } else {
        int c = t - 128, w = c / 5, i = c % 5;
        if (i < 4) {
#pragma unroll
            for (int r = 0; r < 4; r++)
#pragma unroll 8
                for (int u = 0; u < 32; u++)
                    acc = fmaf(ms[640 + r * 128 + u * 4 + i], __ldg(Wo2 + (r * 32 + u) * 32 + w), acc);
        } else {
#pragma unroll
            for (int r = 0; r < 4; r++)
#pragma unroll 8
                for (int u = 0; u < 32; u++)
                    acc = fmaf(ms[1152 + u * 4 + r], __ldg(Wo2 + (r * 32 + u) * 32 + w), acc);
        }
        acc *= 0.005524271728019903f;
    }
    out[n * 288 + t] = acc;
}

// ---------------- launch -----------------------------------------------------
extern "C" void kernel_launch(void* const* d_in, const int* in_sizes, int n_in,
                              void* d_out, int out_size) {
    const float* f_in   = (const float*)d_in[0];
    const float* pos    = (const float*)d_in[1];
    const int*   batch  = (const int*)d_in[2];
    const int*   esrc   = (const int*)d_in[3];
    const int*   edst   = (const int*)d_in[4];
    const float* shifts = (const float*)d_in[5];
    const float* cell   = (const float*)d_in[6];
    const int wb = n_in - 10;
    const float* Wu0 = (const float*)d_in[wb + 0];
    const float* Wu1 = (const float*)d_in[wb + 1];
    const float* Wu2 = (const float*)d_in[wb + 2];
    const float* Wr0 = (const float*)d_in[wb + 3];
    const float* Wr1 = (const float*)d_in[wb + 4];
    const float* Wr2 = (const float*)d_in[wb + 5];
    const float* Wr3 = (const float*)d_in[wb + 6];
    const float* Wo0 = (const float*)d_in[wb + 7];
    const float* Wo1 = (const float*)d_in[wb + 8];
    const float* Wo2 = (const float*)d_in[wb + 9];

    const int N = in_sizes[0] / 288;
    const int E = in_sizes[3];

    static int smem_set = 0;
    const int smem_bytes = (2048 + 2048 + 8 * 4 * 352) * 4;  // 61440
    if (!smem_set) {
        cudaFuncSetAttribute(edge_kernel, cudaFuncAttributeMaxDynamicSharedMemorySize, smem_bytes);
        smem_set = 1;
    }

    cst_kernel<<<1, 256>>>();
    const int n4 = N * 320;
    zero_kernel<<<(n4 + 255) / 256, 256>>>(n4);
    up_kernel<<<N, 288>>>(f_in, Wu0, Wu1, Wu2);
    edge_kernel<<<(E + 31) / 32, 256, smem_bytes>>>(pos, batch, esrc, edst, shifts, cell,
                                                    Wr0, Wr1, Wr2, Wr3, E);
    out_kernel<<<N, 288>>>(Wo0, Wo1, Wo2, (float*)d_out);
}

// round 7
// speedup vs baseline: 1.1314x; 1.0725x over previous
#include <cuda_runtime.h>
#include <math.h>

#define MAXN 10000

// ---------------- device scratch --------------------------------------------
__device__ float  g_cst;                       // CST_SILU
__device__ float  g_xs[MAXN * 288];            // up-projected node features, [node][slot 0..8][u 0..31]
__device__ float4 g_mid4[MAXN * 320];          // aggregated messages, 1280 f/node

// g_xs per-node layout (288 floats): slot*32 + u, slot = {x0, x1_0..2, x2_0..4}
//
// g_mid per-node layout (1280 floats), all blocks u-major float4 groups:
//   A [0,128):      u*4 + s        s = path0,path1,path2,(pad)          (l0)
//   B [128,640):    128 + q*128 + u*4 + i   q=l1 path 0..3, i=x,y,z,(pad)
//   C [640,1152):   640 + r*128 + u*4 + c   r=l2 path 0..3, c=0..3
//   D [1152,1280):  1152 + u*4 + r          comp4 of l2 path r

typedef unsigned long long ull;

__device__ __forceinline__ float silu_f(float v) {
    return __fdividef(v, 1.0f + __expf(-v));
}

// packed fp32x2 fma: d = a*b + d (per 32-bit half, IEEE rn)
#define FFMA2(d, a, b) asm("fma.rn.f32x2 %0, %1, %2, %3;" : "=l"(d) : "l"(a), "l"(b), "l"(d))
#define FMUL2(d, a, b) asm("mul.rn.f32x2 %0, %1, %2;" : "=l"(d) : "l"(a), "l"(b))

__device__ __forceinline__ float2 upk(ull v) {
    float2 r;
    asm("mov.b64 {%0, %1}, %2;" : "=f"(r.x), "=f"(r.y) : "l"(v));
    return r;
}
__device__ __forceinline__ ull pk(float lo, float hi) {
    ull d;
    asm("mov.b64 %0, {%1, %2};" : "=l"(d) : "f"(lo), "f"(hi));
    return d;
}
__device__ __forceinline__ ull dal(double d) { return __double_as_longlong(d); }

// ---------------- CST_SILU via composite Simpson (double) -------------------
__global__ void cst_kernel() {
    __shared__ double red[256];
    const int t = threadIdx.x;
    const int NI = 4096;
    const double h = 24.0 / NI;
    double s = 0.0;
    for (int i = t; i <= NI; i += 256) {
        double xx = -12.0 + h * i;
        double sig = 1.0 / (1.0 + exp(-xx));
        double f = xx * sig;
        f = f * f * exp(-0.5 * xx * xx);
        double c = (i == 0 || i == NI) ? 1.0 : ((i & 1) ? 4.0 : 2.0);
        s += c * f;
    }
    red[t] = s;
    __syncthreads();
    for (int o = 128; o > 0; o >>= 1) {
        if (t < o) red[t] += red[t + o];
        __syncthreads();
    }
    if (t == 0) {
        double I = red[0] * h / 3.0 / 2.5066282746310005024;
        g_cst = (float)(1.0 / sqrt(I));
    }
}

// ---------------- zero mid ---------------------------------------------------
__global__ void zero_kernel(int n4) {
    int i = blockIdx.x * blockDim.x + threadIdx.x;
    if (i < n4) g_mid4[i] = make_float4(0.f, 0.f, 0.f, 0.f);
}

// ---------------- node up-projection ----------------------------------------
__global__ void up_kernel(const float* __restrict__ f_in,
                          const float* __restrict__ Wu0,
                          const float* __restrict__ Wu1,
                          const float* __restrict__ Wu2) {
    const int n = blockIdx.x;
    const int t = threadIdx.x;  // 288
    __shared__ float fs[288];
    fs[t] = f_in[n * 288 + t];
    __syncthreads();
    int i, off, w, d, slot;
    const float* W;
    if (t < 32)       { w = t;         i = 0;         d = 1; off = 0;   W = Wu0; slot = 0; }
    else if (t < 128) { int c = t-32;  w = c/3; i = c%3; d = 3; off = 32;  W = Wu1; slot = 1 + i; }
    else              { int c = t-128; w = c/5; i = c%5; d = 5; off = 128; W = Wu2; slot = 4 + i; }
    float acc = 0.f;
#pragma unroll 8
    for (int u = 0; u < 32; u++)
        acc = fmaf(fs[off + u * d + i], __ldg(W + u * 32 + w), acc);
    g_xs[n * 288 + slot * 32 + w] = acc * 0.17677669529663687f;
}

// ---------------- radial MLP 64->64 layer (4 edges, duplicated layout) ------
// in2/out2: per-warp [4 edges][128] with h2[2j]=h2[2j+1]=h[j]
__device__ __forceinline__ void mlp64d(const float* __restrict__ in2,
                                       float* __restrict__ out2,
                                       const float* __restrict__ W,
                                       int lane, float cst) {
    const int o0 = 2 * lane;
    ull accA[4] = {0ull,0ull,0ull,0ull};
    ull accB[4] = {0ull,0ull,0ull,0ull};
#pragma unroll 4
    for (int j2 = 0; j2 < 32; j2++) {
        ull w0 = dal(__ldg(reinterpret_cast<const double*>(W + (2*j2)   * 64 + o0)));
        ull w1 = dal(__ldg(reinterpret_cast<const double*>(W + (2*j2+1) * 64 + o0)));
#pragma unroll
        for (int e = 0; e < 4; e++) {
            ulonglong2 hp = *reinterpret_cast<const ulonglong2*>(in2 + e * 128 + 4 * j2);
            FFMA2(accA[e], w0, hp.x);
            FFMA2(accB[e], w1, hp.y);
        }
    }
#pragma unroll
    for (int e = 0; e < 4; e++) {
        float2 va = upk(accA[e]);
        float2 vb = upk(accB[e]);
        float v0 = silu_f((va.x + vb.x) * 0.125f) * cst;
        float v1 = silu_f((va.y + vb.y) * 0.125f) * cst;
        *reinterpret_cast<float4*>(out2 + e * 128 + 4 * lane) = make_float4(v0, v0, v1, v1);
    }
}

// ---------------- fused per-edge kernel (warp handles 4 edges) --------------
__global__ void __launch_bounds__(256, 2) edge_kernel(
    const float* __restrict__ pos, const int* __restrict__ batch,
    const int* __restrict__ esrc, const int* __restrict__ edst,
    const float* __restrict__ shifts, const float* __restrict__ cell,
    const float* __restrict__ Wr0, const float* __restrict__ Wr1,
    const float* __restrict__ Wr2, const float* __restrict__ Wr3, int E)
{
    extern __shared__ float sm[];
    const int wid  = threadIdx.x >> 5;
    const int lane = threadIdx.x & 31;
    float* hA2 = sm + wid * 512;                    // [4][128] duplicated activations
    float* hB2 = sm + 4096 + wid * 512;             // [4][128]
    float* wsm = sm + 8192 + wid * 1408;            // [4][352]

    const int base = (blockIdx.x * 8 + wid) * 4;
    const float cst = g_cst;

    float uxr[4], uyr[4], uzr[4], Lr[4];
#pragma unroll
    for (int e = 0; e < 4; e++) {
        int ei = (base + e < E) ? base + e : E - 1;
        const int src = __ldg(esrc + ei);
        const int dst = __ldg(edst + ei);
        const float sx = __ldg(shifts + 3*ei), sy = __ldg(shifts + 3*ei+1), sz = __ldg(shifts + 3*ei+2);
        const float* Cc = cell + 9 * __ldg(batch + src);
        float vx = __ldg(pos+3*dst+0) - __ldg(pos+3*src+0) + sx*__ldg(Cc+0) + sy*__ldg(Cc+3) + sz*__ldg(Cc+6);
        float vy = __ldg(pos+3*dst+1) - __ldg(pos+3*src+1) + sx*__ldg(Cc+1) + sy*__ldg(Cc+4) + sz*__ldg(Cc+7);
        float vz = __ldg(pos+3*dst+2) - __ldg(pos+3*src+2) + sx*__ldg(Cc+2) + sy*__ldg(Cc+5) + sz*__ldg(Cc+8);
        float L = sqrtf(vx*vx + vy*vy + vz*vz);
        float inv = 1.0f / fmaxf(L, 1e-12f);
        uxr[e] = vx*inv; uyr[e] = vy*inv; uzr[e] = vz*inv; Lr[e] = L;
    }

    // ---- radial embedding, cooperative, duplicated into hB2[e][0..15] ----
    {
        const int k = lane & 7;
        const int e = lane >> 3;
        float Ls = Lr[0];
        if (e == 1) Ls = Lr[1]; else if (e == 2) Ls = Lr[2]; else if (e == 3) Ls = Lr[3];
        float tt = (Ls - (float)(k + 1) * (5.0f / 9.0f)) * 1.8f;
        float v = __expf(-tt * tt) * 2.525381361380527f;  // sqrt(8)/1.12
        *reinterpret_cast<float2*>(hB2 + e * 128 + 2 * k) = make_float2(v, v);
    }
    __syncwarp();

    const int o0 = 2 * lane;
    // ---- layer 1: 8 -> 64 (hB2 -> hA2) ----
    {
        ull acc[4] = {0ull,0ull,0ull,0ull};
#pragma unroll
        for (int j2 = 0; j2 < 4; j2++) {
            ull w0 = dal(__ldg(reinterpret_cast<const double*>(Wr0 + (2*j2)   * 64 + o0)));
            ull w1 = dal(__ldg(reinterpret_cast<const double*>(Wr0 + (2*j2+1) * 64 + o0)));
#pragma unroll
            for (int e = 0; e < 4; e++) {
                ulonglong2 hp = *reinterpret_cast<const ulonglong2*>(hB2 + e * 128 + 4 * j2);
                FFMA2(acc[e], w0, hp.x);
                FFMA2(acc[e], w1, hp.y);
            }
        }
#pragma unroll
        for (int e = 0; e < 4; e++) {
            float2 v = upk(acc[e]);
            float v0 = silu_f(v.x * 0.35355339059327373f) * cst;
            float v1 = silu_f(v.y * 0.35355339059327373f) * cst;
            *reinterpret_cast<float4*>(hA2 + e * 128 + 4 * lane) = make_float4(v0, v0, v1, v1);
        }
    }
    __syncwarp();
    mlp64d(hA2, hB2, Wr1, lane, cst);   // layer 2
    __syncwarp();
    mlp64d(hB2, hA2, Wr2, lane, cst);   // layer 3
    __syncwarp();

    // ---- layer 4: 64 -> 352 (hA2 -> wsm), FFMA2 throughout ----
    {
        ull a0[4], a1[4], a2[4], a3[4], a4[4], a5[4];
#pragma unroll
        for (int e = 0; e < 4; e++) { a0[e]=0; a1[e]=0; a2[e]=0; a3[e]=0; a4[e]=0; a5[e]=0; }
        const double2* W3d = reinterpret_cast<const double2*>(Wr3);  // row stride 88 double2
        const int c0 = lane, c1 = lane + 32, c2 = lane + 64;
#pragma unroll 2
        for (int j2 = 0; j2 < 32; j2++) {
            ulonglong2 hp[4];
#pragma unroll
            for (int e = 0; e < 4; e++)
                hp[e] = *reinterpret_cast<const ulonglong2*>(hA2 + e * 128 + 4 * j2);
#pragma unroll
            for (int jj = 0; jj < 2; jj++) {
                const int j = 2 * j2 + jj;
                double2 w0 = __ldg(W3d + j * 88 + c0);
                double2 w1 = __ldg(W3d + j * 88 + c1);
                double2 w2 = make_double2(0.0, 0.0);
                if (lane < 24) w2 = __ldg(W3d + j * 88 + c2);
                ull b0 = dal(w0.x), b1 = dal(w0.y);
                ull b2 = dal(w1.x), b3 = dal(w1.y);
                ull b4 = dal(w2.x), b5 = dal(w2.y);
#pragma unroll
                for (int e = 0; e < 4; e++) {
                    ull hd = jj ? hp[e].y : hp[e].x;
                    FFMA2(a0[e], b0, hd); FFMA2(a1[e], b1, hd);
                    FFMA2(a2[e], b2, hd); FFMA2(a3[e], b3, hd);
                    FFMA2(a4[e], b4, hd); FFMA2(a5[e], b5, hd);
                }
            }
        }
        const ull kd = pk(0.125f, 0.125f);
        union CV { ull u[2]; float4 f; };
#pragma unroll
        for (int e = 0; e < 4; e++) {
            float4* wsf4 = reinterpret_cast<float4*>(wsm + e * 352);
            CV c;
            FMUL2(a0[e], a0[e], kd); FMUL2(a1[e], a1[e], kd);
            c.u[0] = a0[e]; c.u[1] = a1[e]; wsf4[lane] = c.f;
            FMUL2(a2[e], a2[e], kd); FMUL2(a3[e], a3[e], kd);
            c.u[0] = a2[e]; c.u[1] = a3[e]; wsf4[lane + 32] = c.f;
            if (lane < 24) {
                FMUL2(a4[e], a4[e], kd); FMUL2(a5[e], a5[e], kd);
                c.u[0] = a4[e]; c.u[1] = a5[e]; wsf4[lane + 64] = c.f;
            }
        }
    }
    __syncwarp();

    // ---- tensor product + coalesced vector atomics, per edge ----
    const float A_  = 0.31622776601683794f;  // 1/sqrt(10)
    const float B_  = 0.18257418583505536f;  // 1/sqrt(30)
    const float AL  = 0.11952286093343936f;  // 1/sqrt(70)
    const float BE  = 0.20701966780270626f;  // sqrt(3/70)
    const float SQ3 = 1.7320508075688772f;
    const float SQ5 = 2.23606797749979f;

#pragma unroll
    for (int e = 0; e < 4; e++) {
        if (base + e >= E) break;
        const int src = __ldg(esrc + base + e);
        const int dst = __ldg(edst + base + e);

        const float ux = uxr[e], uy = uyr[e], uz = uzr[e];
        const float s1x = SQ3 * ux, s1y = SQ3 * uy, s1z = SQ3 * uz;
        const float s20 = 3.872983346207417f * ux * uz;
        const float s21 = 3.872983346207417f * ux * uy;
        const float s22 = SQ5 * (uy*uy - 0.5f*(ux*ux + uz*uz));
        const float s23 = 3.872983346207417f * uy * uz;
        const float s24 = 1.9364916731037085f * (uz*uz - ux*ux);

        // radial weights for this lane's u channel (coalesced LDS)
        float w[11];
#pragma unroll
        for (int k = 0; k < 11; k++) w[k] = wsm[e * 352 + k * 32 + lane];

        // source features: coalesced scalar loads from [src][slot][u]
        const float* xp = g_xs + src * 288 + lane;
        const float x0  = __ldg(xp);
        const float x10 = __ldg(xp + 32),  x11 = __ldg(xp + 64),  x12 = __ldg(xp + 96);
        const float x20 = __ldg(xp + 128), x21 = __ldg(xp + 160), x22 = __ldg(xp + 192);
        const float x23 = __ldg(xp + 224), x24 = __ldg(xp + 256);

        // l0 outputs
        const float p0 = x0 * w[0];
        const float p1 = 0.5773502691896258f * (x10*s1x + x11*s1y + x12*s1z) * w[1];
        const float p2 = 0.4472135954999579f * (x20*s20 + x21*s21 + x22*s22 + x23*s23 + x24*s24) * w[2];

        // l1 outputs
        const float c3 = x0 * w[3];
        const float p3x = c3 * s1x, p3y = c3 * s1y, p3z = c3 * s1z;
        const float p4x = x10 * w[4], p4y = x11 * w[4], p4z = x12 * w[4];
        float p5x, p5y, p5z;
        {
            float wv = SQ3 * w[5];
            float B00 = -B_*s22 - A_*s24;
            float B01 =  A_*s21;
            float B02 =  A_*s20;
            float B11 =  2.f*B_*s22;
            float B12 =  A_*s23;
            float B22 = -B_*s22 + A_*s24;
            p5x = wv * (x10*B00 + x11*B01 + x12*B02);
            p5y = wv * (x10*B01 + x11*B11 + x12*B12);
            p5z = wv * (x10*B02 + x11*B12 + x12*B22);
        }
        float p6x, p6y, p6z;
        {
            float wv = SQ3 * w[6];
            p6x = wv * (A_*(x20*s1z + x21*s1y) - B_*x22*s1x - A_*x24*s1x);
            p6y = wv * (A_*(x21*s1x + x23*s1z) + 2.f*B_*x22*s1y);
            p6z = wv * (A_*(x20*s1x + x23*s1y + x24*s1z) - B_*x22*s1z);
        }

        // l2 outputs
        const float c7 = x0 * w[7];
        const float p70 = c7*s20, p71 = c7*s21, p72 = c7*s22, p73 = c7*s23, p74 = c7*s24;
        float p80, p81, p82, p83, p84;
        {
            float wv = SQ5 * w[8];
            p80 = wv * (A_*(x10*s1z + x12*s1x));
            p81 = wv * (A_*(x10*s1y + x11*s1x));
            p82 = wv * (B_*(-x10*s1x + 2.f*x11*s1y - x12*s1z));
            p83 = wv * (A_*(x11*s1z + x12*s1y));
            p84 = wv * (A_*(-x10*s1x + x12*s1z));
        }
        const float p90 = x20*w[9], p91 = x21*w[9], p92 = x22*w[9], p93 = x23*w[9], p94 = x24*w[9];
        float pa0, pa1, pa2, pa3, pa4;
        {
            float wv = SQ5 * w[10];
            pa0 = wv * (x20*(2.f*AL*s22) + x21*(-BE*s23) + x22*(2.f*AL*s20) + x23*(-BE*s21));
            pa1 = wv * (x20*(-BE*s23) + x21*(-AL*s22 + BE*s24) + x22*(-AL*s21) + x23*(-BE*s20) + x24*(BE*s21));
            pa2 = wv * (x20*(2.f*AL*s20) + x21*(-AL*s21) + x22*(-2.f*AL*s22) + x23*(-AL*s23) + x24*(2.f*AL*s24));
            pa3 = wv * (x20*(-BE*s21) + x21*(-BE*s20) + x22*(-AL*s23) + x23*(-AL*s22 - BE*s24) + x24*(-BE*s23));
            pa4 = wv * (x21*(BE*s21) + x22*(2.f*AL*s24) + x23*(-BE*s23) + x24*(2.f*AL*s22));
        }

        // 10 warp-coalesced float4 atomics (each spans exactly 512B)
        float4* mb = reinterpret_cast<float4*>(reinterpret_cast<float*>(g_mid4) + dst * 1280) + lane;
        atomicAdd(mb,       make_float4(p0, p1, p2, 0.f));          // A
        atomicAdd(mb + 32,  make_float4(p3x, p3y, p3z, 0.f));       // B q=0
        atomicAdd(mb + 64,  make_float4(p4x, p4y, p4z, 0.f));       // B q=1
        atomicAdd(mb + 96,  make_float4(p5x, p5y, p5z, 0.f));       // B q=2
        atomicAdd(mb + 128, make_float4(p6x, p6y, p6z, 0.f));       // B q=3
        atomicAdd(mb + 160, make_float4(p70, p71, p72, p73));       // C r=0
        atomicAdd(mb + 192, make_float4(p80, p81, p82, p83));       // C r=1
        atomicAdd(mb + 224, make_float4(p90, p91, p92, p93));       // C r=2
        atomicAdd(mb + 256, make_float4(pa0, pa1, pa2, pa3));       // C r=3
        atomicAdd(mb + 288, make_float4(p74, p84, p94, pa4));       // D
    }
}

// ---------------- per-node output projection --------------------------------
__global__ void out_kernel(const float* __restrict__ Wo0,
                           const float* __restrict__ Wo1,
                           const float* __restrict__ Wo2,
                           float* __restrict__ out) {
    const int n = blockIdx.x;
    const int t = threadIdx.x;  // 288
    __shared__ float ms[1280];
    for (int j = t; j < 320; j += 288)
        reinterpret_cast<float4*>(ms)[j] = g_mid4[n * 320 + j];
    __syncthreads();

    float acc = 0.f;
    if (t < 32) {
#pragma unroll
        for (int s = 0; s < 3; s++)
#pragma unroll 8
            for (int u = 0; u < 32; u++)
                acc = fmaf(ms[u * 4 + s], __ldg(Wo0 + (s * 32 + u) * 32 + t), acc);
        acc *= 0.006378879538497859f;   // 1/(sqrt(96)*16)
    } else if (t < 128) {
        int c = t - 32, w = c / 3, i = c % 3;
#pragma unroll
        for (int q = 0; q < 4; q++)
#pragma unroll 8
            for (int u = 0; u < 32; u++)
                acc = fmaf(ms[128 + q * 128 + u * 4 + i], __ldg(Wo1 + (q * 32 + u) * 32 + w), acc);
        acc *= 0.005524271728019903f;   // 1/(sqrt(128)*16)
    } else {
        int c = t - 128, w = c / 5, i = c % 5;
        if (i < 4) {
#pragma unroll
            for (int r = 0; r < 4; r++)
#pragma unroll 8
                for (int u = 0; u < 32; u++)
                    acc = fmaf(ms[640 + r * 128 + u * 4 + i], __ldg(Wo2 + (r * 32 + u) * 32 + w), acc);
        } else {
#pragma unroll
            for (int r = 0; r < 4; r++)
#pragma unroll 8
                for (int u = 0; u < 32; u++)
                    acc = fmaf(ms[1152 + u * 4 + r], __ldg(Wo2 + (r * 32 + u) * 32 + w), acc);
        }
        acc *= 0.005524271728019903f;
    }
    out[n * 288 + t] = acc;
}

// ---------------- launch -----------------------------------------------------
extern "C" void kernel_launch(void* const* d_in, const int* in_sizes, int n_in,
                              void* d_out, int out_size) {
    const float* f_in   = (const float*)d_in[0];
    const float* pos    = (const float*)d_in[1];
    const int*   batch  = (const int*)d_in[2];
    const int*   esrc   = (const int*)d_in[3];
    const int*   edst   = (const int*)d_in[4];
    const float* shifts = (const float*)d_in[5];
    const float* cell   = (const float*)d_in[6];
    const int wb = n_in - 10;
    const float* Wu0 = (const float*)d_in[wb + 0];
    const float* Wu1 = (const float*)d_in[wb + 1];
    const float* Wu2 = (const float*)d_in[wb + 2];
    const float* Wr0 = (const float*)d_in[wb + 3];
    const float* Wr1 = (const float*)d_in[wb + 4];
    const float* Wr2 = (const float*)d_in[wb + 5];
    const float* Wr3 = (const float*)d_in[wb + 6];
    const float* Wo0 = (const float*)d_in[wb + 7];
    const float* Wo1 = (const float*)d_in[wb + 8];
    const float* Wo2 = (const float*)d_in[wb + 9];

    const int N = in_sizes[0] / 288;
    const int E = in_sizes[3];

    static int smem_set = 0;
    const int smem_bytes = (4096 + 4096 + 8 * 4 * 352) * 4;  // 77824
    if (!smem_set) {
        cudaFuncSetAttribute(edge_kernel, cudaFuncAttributeMaxDynamicSharedMemorySize, smem_bytes);
        smem_set = 1;
    }

    cst_kernel<<<1, 256>>>();
    const int n4 = N * 320;
    zero_kernel<<<(n4 + 255) / 256, 256>>>(n4);
    up_kernel<<<N, 288>>>(f_in, Wu0, Wu1, Wu2);
    edge_kernel<<<(E + 31) / 32, 256, smem_bytes>>>(pos, batch, esrc, edst, shifts, cell,
                                                    Wr0, Wr1, Wr2, Wr3, E);
    out_kernel<<<N, 288>>>(Wo0, Wo1, Wo2, (float*)d_out);
}

// round 8
// speedup vs baseline: 1.2785x; 1.1300x over previous
#include <cuda_runtime.h>
#include <math.h>

#define MAXN 10000

// ---------------- device scratch --------------------------------------------
__device__ float    g_cst;                     // CST_SILU
__device__ float    g_xs[MAXN * 288];          // up-projected node features, [node][slot 0..8][u 0..31]
__device__ float4   g_mid4[MAXN * 320];        // aggregated messages, 1280 f/node
__device__ unsigned g_w3f[8 * 44 * 32 * 2];    // Wr3/8 in tf32 mma-B fragment layout

// g_xs per-node layout (288 floats): slot*32 + u, slot = {x0, x1_0..2, x2_0..4}
// g_mid per-node layout (1280 floats):
//   A [0,128):      u*4 + s        s = path0,path1,path2,(pad)          (l0)
//   B [128,640):    128 + q*128 + u*4 + i   q=l1 path 0..3, i=x,y,z,(pad)
//   C [640,1152):   640 + r*128 + u*4 + c   r=l2 path 0..3, c=0..3
//   D [1152,1280):  1152 + u*4 + r          comp4 of l2 path r

typedef unsigned long long ull;

__device__ __forceinline__ float silu_f(float v) {
    return __fdividef(v, 1.0f + __expf(-v));
}

// packed fp32x2 fma helpers
#define FFMA2(d, a, b) asm("fma.rn.f32x2 %0, %1, %2, %3;" : "=l"(d) : "l"(a), "l"(b), "l"(d))

__device__ __forceinline__ float2 upk(ull v) {
    float2 r;
    asm("mov.b64 {%0, %1}, %2;" : "=f"(r.x), "=f"(r.y) : "l"(v));
    return r;
}
__device__ __forceinline__ ull dal(double d) { return __double_as_longlong(d); }

__device__ __forceinline__ unsigned tf32_rna(float x) {
    unsigned u;
    asm("cvt.rna.tf32.f32 %0, %1;" : "=r"(u) : "f"(x));
    return u;
}

__device__ __forceinline__ void mma_tf32(float& c0, float& c1, float& c2, float& c3,
                                         unsigned a0, unsigned a1, unsigned a2, unsigned a3,
                                         unsigned b0, unsigned b1) {
    asm volatile(
        "mma.sync.aligned.m16n8k8.row.col.f32.tf32.tf32.f32 "
        "{%0,%1,%2,%3},{%4,%5,%6,%7},{%8,%9},{%0,%1,%2,%3};"
        : "+f"(c0), "+f"(c1), "+f"(c2), "+f"(c3)
        : "r"(a0), "r"(a1), "r"(a2), "r"(a3), "r"(b0), "r"(b1));
}

// ---------------- CST_SILU via composite Simpson (double) -------------------
__global__ void cst_kernel() {
    __shared__ double red[256];
    const int t = threadIdx.x;
    const int NI = 4096;
    const double h = 24.0 / NI;
    double s = 0.0;
    for (int i = t; i <= NI; i += 256) {
        double xx = -12.0 + h * i;
        double sig = 1.0 / (1.0 + exp(-xx));
        double f = xx * sig;
        f = f * f * exp(-0.5 * xx * xx);
        double c = (i == 0 || i == NI) ? 1.0 : ((i & 1) ? 4.0 : 2.0);
        s += c * f;
    }
    red[t] = s;
    __syncthreads();
    for (int o = 128; o > 0; o >>= 1) {
        if (t < o) red[t] += red[t + o];
        __syncthreads();
    }
    if (t == 0) {
        double I = red[0] * h / 3.0 / 2.5066282746310005024;
        g_cst = (float)(1.0 / sqrt(I));
    }
}

// ---------------- zero mid ---------------------------------------------------
__global__ void zero_kernel(int n4) {
    int i = blockIdx.x * blockDim.x + threadIdx.x;
    if (i < n4) g_mid4[i] = make_float4(0.f, 0.f, 0.f, 0.f);
}

// ---------------- Wr3 -> tf32 B-fragment repack -----------------------------
// b0 = W[kt*8+tig][nt*8+gid] * 0.125, b1 = W[kt*8+tig+4][nt*8+gid] * 0.125
__global__ void w3prep_kernel(const float* __restrict__ Wr3) {
    const int f = blockIdx.x * blockDim.x + threadIdx.x;  // 0 .. 8*44*32-1
    if (f >= 8 * 44 * 32) return;
    const int lane = f & 31;
    const int pair = f >> 5;
    const int nt = pair % 44;
    const int kt = pair / 44;
    const int tig = lane & 3;
    const int gid = lane >> 2;
    const int n = nt * 8 + gid;
    float w0 = Wr3[(kt * 8 + tig) * 352 + n] * 0.125f;
    float w1 = Wr3[(kt * 8 + tig + 4) * 352 + n] * 0.125f;
    g_w3f[f * 2 + 0] = tf32_rna(w0);
    g_w3f[f * 2 + 1] = tf32_rna(w1);
}

// ---------------- node up-projection ----------------------------------------
__global__ void up_kernel(const float* __restrict__ f_in,
                          const float* __restrict__ Wu0,
                          const float* __restrict__ Wu1,
                          const float* __restrict__ Wu2) {
    const int n = blockIdx.x;
    const int t = threadIdx.x;  // 288
    __shared__ float fs[288];
    fs[t] = f_in[n * 288 + t];
    __syncthreads();
    int i, off, w, d, slot;
    const float* W;
    if (t < 32)       { w = t;         i = 0;         d = 1; off = 0;   W = Wu0; slot = 0; }
    else if (t < 128) { int c = t-32;  w = c/3; i = c%3; d = 3; off = 32;  W = Wu1; slot = 1 + i; }
    else              { int c = t-128; w = c/5; i = c%5; d = 5; off = 128; W = Wu2; slot = 4 + i; }
    float acc = 0.f;
#pragma unroll 8
    for (int u = 0; u < 32; u++)
        acc = fmaf(fs[off + u * d + i], __ldg(W + u * 32 + w), acc);
    g_xs[n * 288 + slot * 32 + w] = acc * 0.17677669529663687f;
}

// ---------------- radial MLP 64->64 layer (4 edges, duplicated layout) ------
__device__ __forceinline__ void mlp64d(const float* __restrict__ in2,
                                       float* __restrict__ out2,
                                       const float* __restrict__ W,
                                       int lane, float cst) {
    const int o0 = 2 * lane;
    ull accA[4] = {0ull,0ull,0ull,0ull};
    ull accB[4] = {0ull,0ull,0ull,0ull};
#pragma unroll 4
    for (int j2 = 0; j2 < 32; j2++) {
        ull w0 = dal(__ldg(reinterpret_cast<const double*>(W + (2*j2)   * 64 + o0)));
        ull w1 = dal(__ldg(reinterpret_cast<const double*>(W + (2*j2+1) * 64 + o0)));
#pragma unroll
        for (int e = 0; e < 4; e++) {
            ulonglong2 hp = *reinterpret_cast<const ulonglong2*>(in2 + e * 128 + 4 * j2);
            FFMA2(accA[e], w0, hp.x);
            FFMA2(accB[e], w1, hp.y);
        }
    }
#pragma unroll
    for (int e = 0; e < 4; e++) {
        float2 va = upk(accA[e]);
        float2 vb = upk(accB[e]);
        float v0 = silu_f((va.x + vb.x) * 0.125f) * cst;
        float v1 = silu_f((va.y + vb.y) * 0.125f) * cst;
        *reinterpret_cast<float4*>(out2 + e * 128 + 4 * lane) = make_float4(v0, v0, v1, v1);
    }
}

// smem layout (floats):
//   hA2  [0, 4096)        8 warps x [4 edges][128] duplicated activations
//   hB2  [4096, 8192)
//   hfr  [8192, 10304)    A-fragments (tf32 bits): [etile 2][kt 8][reg 4][33]
//   wsm  [10304, 16704)   radial weights half: [32 edges][200]  (cols 0..191 used)
#define SM_HA 0
#define SM_HB 4096
#define SM_HF 8192
#define SM_WS 10304
#define WS_STRIDE 200

// ---------------- fused per-edge kernel (block = 32 edges) ------------------
__global__ void __launch_bounds__(256, 2) edge_kernel(
    const float* __restrict__ pos, const int* __restrict__ batch,
    const int* __restrict__ esrc, const int* __restrict__ edst,
    const float* __restrict__ shifts, const float* __restrict__ cell,
    const float* __restrict__ Wr0, const float* __restrict__ Wr1,
    const float* __restrict__ Wr2, int E)
{
    extern __shared__ float sm[];
    const int wid  = threadIdx.x >> 5;
    const int lane = threadIdx.x & 31;
    float* hA2 = sm + SM_HA + wid * 512;
    float* hB2 = sm + SM_HB + wid * 512;
    unsigned* hfr = reinterpret_cast<unsigned*>(sm + SM_HF);
    float* wsm = sm + SM_WS;

    const int base = blockIdx.x * 32 + wid * 4;   // this warp's 4 TP edges
    const int etile = wid >> 2;                   // which 16-edge tile this warp belongs to
    const float cst = g_cst;

    // ================= phase 1: geometry + radial MLP layers 1-3 ============
    float uxr[4], uyr[4], uzr[4], Lr[4];
#pragma unroll
    for (int e = 0; e < 4; e++) {
        int ei = (base + e < E) ? base + e : E - 1;
        const int src = __ldg(esrc + ei);
        const int dst = __ldg(edst + ei);
        const float sx = __ldg(shifts + 3*ei), sy = __ldg(shifts + 3*ei+1), sz = __ldg(shifts + 3*ei+2);
        const float* Cc = cell + 9 * __ldg(batch + src);
        float vx = __ldg(pos+3*dst+0) - __ldg(pos+3*src+0) + sx*__ldg(Cc+0) + sy*__ldg(Cc+3) + sz*__ldg(Cc+6);
        float vy = __ldg(pos+3*dst+1) - __ldg(pos+3*src+1) + sx*__ldg(Cc+1) + sy*__ldg(Cc+4) + sz*__ldg(Cc+7);
        float vz = __ldg(pos+3*dst+2) - __ldg(pos+3*src+2) + sx*__ldg(Cc+2) + sy*__ldg(Cc+5) + sz*__ldg(Cc+8);
        float L = sqrtf(vx*vx + vy*vy + vz*vz);
        float inv = 1.0f / fmaxf(L, 1e-12f);
        uxr[e] = vx*inv; uyr[e] = vy*inv; uzr[e] = vz*inv; Lr[e] = L;
    }

    // radial embedding, duplicated into hB2[e][0..15]
    {
        const int k = lane & 7;
        const int e = lane >> 3;
        float Ls = Lr[0];
        if (e == 1) Ls = Lr[1]; else if (e == 2) Ls = Lr[2]; else if (e == 3) Ls = Lr[3];
        float tt = (Ls - (float)(k + 1) * (5.0f / 9.0f)) * 1.8f;
        float v = __expf(-tt * tt) * 2.525381361380527f;  // sqrt(8)/1.12
        *reinterpret_cast<float2*>(hB2 + e * 128 + 2 * k) = make_float2(v, v);
    }
    __syncwarp();

    const int o0 = 2 * lane;
    // layer 1: 8 -> 64 (hB2 -> hA2)
    {
        ull acc[4] = {0ull,0ull,0ull,0ull};
#pragma unroll
        for (int j2 = 0; j2 < 4; j2++) {
            ull w0 = dal(__ldg(reinterpret_cast<const double*>(Wr0 + (2*j2)   * 64 + o0)));
            ull w1 = dal(__ldg(reinterpret_cast<const double*>(Wr0 + (2*j2+1) * 64 + o0)));
#pragma unroll
            for (int e = 0; e < 4; e++) {
                ulonglong2 hp = *reinterpret_cast<const ulonglong2*>(hB2 + e * 128 + 4 * j2);
                FFMA2(acc[e], w0, hp.x);
                FFMA2(acc[e], w1, hp.y);
            }
        }
#pragma unroll
        for (int e = 0; e < 4; e++) {
            float2 v = upk(acc[e]);
            float v0 = silu_f(v.x * 0.35355339059327373f) * cst;
            float v1 = silu_f(v.y * 0.35355339059327373f) * cst;
            *reinterpret_cast<float4*>(hA2 + e * 128 + 4 * lane) = make_float4(v0, v0, v1, v1);
        }
    }
    __syncwarp();
    mlp64d(hA2, hB2, Wr1, lane, cst);   // layer 2
    __syncwarp();

    // layer 3: read hB2, write h into A-fragment layout (tf32 bits)
    {
        ull accA[4] = {0ull,0ull,0ull,0ull};
        ull accB[4] = {0ull,0ull,0ull,0ull};
#pragma unroll 4
        for (int j2 = 0; j2 < 32; j2++) {
            ull w0 = dal(__ldg(reinterpret_cast<const double*>(Wr2 + (2*j2)   * 64 + o0)));
            ull w1 = dal(__ldg(reinterpret_cast<const double*>(Wr2 + (2*j2+1) * 64 + o0)));
#pragma unroll
            for (int e = 0; e < 4; e++) {
                ulonglong2 hp = *reinterpret_cast<const ulonglong2*>(hB2 + e * 128 + 4 * j2);
                FFMA2(accA[e], w0, hp.x);
                FFMA2(accB[e], w1, hp.y);
            }
        }
#pragma unroll
        for (int e = 0; e < 4; e++) {
            float2 va = upk(accA[e]);
            float2 vb = upk(accB[e]);
            float v0 = silu_f((va.x + vb.x) * 0.125f) * cst;
            float v1 = silu_f((va.y + vb.y) * 0.125f) * cst;
            const int m = (wid & 3) * 4 + e;           // row within 16-edge tile
            // store v0 at col k=2*lane, v1 at col k=2*lane+1
#pragma unroll
            for (int cc = 0; cc < 2; cc++) {
                int k  = 2 * lane + cc;
                float v = cc ? v1 : v0;
                int kt  = k >> 3;
                int kin = k & 7;
                int reg = ((m >= 8) ? 1 : 0) + ((kin >= 4) ? 2 : 0);
                int lp  = (m & 7) * 4 + (kin & 3);
                hfr[((etile * 8 + kt) * 4 + reg) * 33 + lp] = tf32_rna(v);
            }
        }
    }
    __syncthreads();

    // ================= MMA setup ===========================================
    const int nch = wid & 3;  // n-chunk of this warp within its etile
    // A fragments for this warp's etile (kept in regs across both halves)
    unsigned afr[8][4];
#pragma unroll
    for (int kt = 0; kt < 8; kt++)
#pragma unroll
        for (int r = 0; r < 4; r++)
            afr[kt][r] = hfr[((etile * 8 + kt) * 4 + r) * 33 + lane];

    const int gid = lane >> 2;
    const int tig = lane & 3;
    const uint2* Bf = reinterpret_cast<const uint2*>(g_w3f);

    // ---- MMA half 1: n-tiles 0..23 (w cols 0..191), warp does 6 tiles ----
#pragma unroll 1
    for (int t6 = 0; t6 < 6; t6++) {
        const int nt = nch * 6 + t6;
        float c0 = 0.f, c1 = 0.f, c2 = 0.f, c3 = 0.f;
#pragma unroll
        for (int kt = 0; kt < 8; kt++) {
            uint2 b = __ldg(Bf + (kt * 44 + nt) * 32 + lane);
            mma_tf32(c0, c1, c2, c3, afr[kt][0], afr[kt][1], afr[kt][2], afr[kt][3], b.x, b.y);
        }
        const int col = nt * 8 + tig * 2;
        float* r0 = wsm + (etile * 16 + gid) * WS_STRIDE + col;
        r0[0] = c0; r0[1] = c1;
        float* r1 = r0 + 8 * WS_STRIDE;
        r1[0] = c2; r1[1] = c3;
    }
    __syncthreads();

    // ================= TP constants ========================================
    const float A_  = 0.31622776601683794f;  // 1/sqrt(10)
    const float B_  = 0.18257418583505536f;  // 1/sqrt(30)
    const float AL  = 0.11952286093343936f;  // 1/sqrt(70)
    const float BE  = 0.20701966780270626f;  // sqrt(3/70)
    const float SQ3 = 1.7320508075688772f;
    const float SQ5 = 2.23606797749979f;

    // ---- TP half 1: paths 0..5 (w cols 0..191) ----
#pragma unroll 1
    for (int e = 0; e < 4; e++) {
        if (base + e >= E) break;
        const int src = __ldg(esrc + base + e);
        const int dst = __ldg(edst + base + e);
        const float ux = uxr[e], uy = uyr[e], uz = uzr[e];
        const float s1x = SQ3 * ux, s1y = SQ3 * uy, s1z = SQ3 * uz;
        const float s20 = 3.872983346207417f * ux * uz;
        const float s21 = 3.872983346207417f * ux * uy;
        const float s22 = SQ5 * (uy*uy - 0.5f*(ux*ux + uz*uz));
        const float s23 = 3.872983346207417f * uy * uz;
        const float s24 = 1.9364916731037085f * (uz*uz - ux*ux);

        const float* wrow = wsm + (wid * 4 + e) * WS_STRIDE + lane;
        float w0 = wrow[0], w1 = wrow[32], w2 = wrow[64], w3 = wrow[96], w4 = wrow[128], w5 = wrow[160];

        const float* xp = g_xs + src * 288 + lane;
        const float x0  = __ldg(xp);
        const float x10 = __ldg(xp + 32),  x11 = __ldg(xp + 64),  x12 = __ldg(xp + 96);
        const float x20 = __ldg(xp + 128), x21 = __ldg(xp + 160), x22 = __ldg(xp + 192);
        const float x23 = __ldg(xp + 224), x24 = __ldg(xp + 256);

        const float p0 = x0 * w0;
        const float p1 = 0.5773502691896258f * (x10*s1x + x11*s1y + x12*s1z) * w1;
        const float p2 = 0.4472135954999579f * (x20*s20 + x21*s21 + x22*s22 + x23*s23 + x24*s24) * w2;
        const float c3 = x0 * w3;
        float p5x, p5y, p5z;
        {
            float wv = SQ3 * w5;
            float B00 = -B_*s22 - A_*s24;
            float B01 =  A_*s21;
            float B02 =  A_*s20;
            float B11 =  2.f*B_*s22;
            float B12 =  A_*s23;
            float B22 = -B_*s22 + A_*s24;
            p5x = wv * (x10*B00 + x11*B01 + x12*B02);
            p5y = wv * (x10*B01 + x11*B11 + x12*B12);
            p5z = wv * (x10*B02 + x11*B12 + x12*B22);
        }
        float4* mb = reinterpret_cast<float4*>(reinterpret_cast<float*>(g_mid4) + dst * 1280) + lane;
        atomicAdd(mb,       make_float4(p0, p1, p2, 0.f));
        atomicAdd(mb + 32,  make_float4(c3*s1x, c3*s1y, c3*s1z, 0.f));
        atomicAdd(mb + 64,  make_float4(x10*w4, x11*w4, x12*w4, 0.f));
        atomicAdd(mb + 96,  make_float4(p5x, p5y, p5z, 0.f));
    }
    __syncthreads();

    // ---- MMA half 2: n-tiles 24..43 (w cols 192..351), warp does 5 tiles ----
#pragma unroll 1
    for (int t5 = 0; t5 < 5; t5++) {
        const int nt = 24 + nch * 5 + t5;
        float c0 = 0.f, c1 = 0.f, c2 = 0.f, c3 = 0.f;
#pragma unroll
        for (int kt = 0; kt < 8; kt++) {
            uint2 b = __ldg(Bf + (kt * 44 + nt) * 32 + lane);
            mma_tf32(c0, c1, c2, c3, afr[kt][0], afr[kt][1], afr[kt][2], afr[kt][3], b.x, b.y);
        }
        const int col = (nt - 24) * 8 + tig * 2;
        float* r0 = wsm + (etile * 16 + gid) * WS_STRIDE + col;
        r0[0] = c0; r0[1] = c1;
        float* r1 = r0 + 8 * WS_STRIDE;
        r1[0] = c2; r1[1] = c3;
    }
    __syncthreads();

    // ---- TP half 2: paths 6..10 (w cols 192..351, local 0..159) ----
#pragma unroll 1
    for (int e = 0; e < 4; e++) {
        if (base + e >= E) break;
        const int src = __ldg(esrc + base + e);
        const int dst = __ldg(edst + base + e);
        const float ux = uxr[e], uy = uyr[e], uz = uzr[e];
        const float s1x = SQ3 * ux, s1y = SQ3 * uy, s1z = SQ3 * uz;
        const float s20 = 3.872983346207417f * ux * uz;
        const float s21 = 3.872983346207417f * ux * uy;
        const float s22 = SQ5 * (uy*uy - 0.5f*(ux*ux + uz*uz));
        const float s23 = 3.872983346207417f * uy * uz;
        const float s24 = 1.9364916731037085f * (uz*uz - ux*ux);

        const float* wrow = wsm + (wid * 4 + e) * WS_STRIDE + lane;
        float w6 = wrow[0], w7 = wrow[32], w8 = wrow[64], w9 = wrow[96], w10 = wrow[128];

        const float* xp = g_xs + src * 288 + lane;
        const float x0  = __ldg(xp);
        const float x10 = __ldg(xp + 32),  x11 = __ldg(xp + 64),  x12 = __ldg(xp + 96);
        const float x20 = __ldg(xp + 128), x21 = __ldg(xp + 160), x22 = __ldg(xp + 192);
        const float x23 = __ldg(xp + 224), x24 = __ldg(xp + 256);

        float p6x, p6y, p6z;
        {
            float wv = SQ3 * w6;
            p6x = wv * (A_*(x20*s1z + x21*s1y) - B_*x22*s1x - A_*x24*s1x);
            p6y = wv * (A_*(x21*s1x + x23*s1z) + 2.f*B_*x22*s1y);
            p6z = wv * (A_*(x20*s1x + x23*s1y + x24*s1z) - B_*x22*s1z);
        }
        const float c7 = x0 * w7;
        const float p70 = c7*s20, p71 = c7*s21, p72 = c7*s22, p73 = c7*s23, p74 = c7*s24;
        float p80, p81, p82, p83, p84;
        {
            float wv = SQ5 * w8;
            p80 = wv * (A_*(x10*s1z + x12*s1x));
            p81 = wv * (A_*(x10*s1y + x11*s1x));
            p82 = wv * (B_*(-x10*s1x + 2.f*x11*s1y - x12*s1z));
            p83 = wv * (A_*(x11*s1z + x12*s1y));
            p84 = wv * (A_*(-x10*s1x + x12*s1z));
        }
        const float p90 = x20*w9, p91 = x21*w9, p92 = x22*w9, p93 = x23*w9, p94 = x24*w9;
        float pa0, pa1, pa2, pa3, pa4;
        {
            float wv = SQ5 * w10;
            pa0 = wv * (x20*(2.f*AL*s22) + x21*(-BE*s23) + x22*(2.f*AL*s20) + x23*(-BE*s21));
            pa1 = wv * (x20*(-BE*s23) + x21*(-AL*s22 + BE*s24) + x22*(-AL*s21) + x23*(-BE*s20) + x24*(BE*s21));
            pa2 = wv * (x20*(2.f*AL*s20) + x21*(-AL*s21) + x22*(-2.f*AL*s22) + x23*(-AL*s23) + x24*(2.f*AL*s24));
            pa3 = wv * (x20*(-BE*s21) + x21*(-BE*s20) + x22*(-AL*s23) + x23*(-AL*s22 - BE*s24) + x24*(-BE*s23));
            pa4 = wv * (x21*(BE*s21) + x22*(2.f*AL*s24) + x23*(-BE*s23) + x24*(2.f*AL*s22));
        }
        float4* mb = reinterpret_cast<float4*>(reinterpret_cast<float*>(g_mid4) + dst * 1280) + lane;
        atomicAdd(mb + 128, make_float4(p6x, p6y, p6z, 0.f));
        atomicAdd(mb + 160, make_float4(p70, p71, p72, p73));
        atomicAdd(mb + 192, make_float4(p80, p81, p82, p83));
        atomicAdd(mb + 224, make_float4(p90, p91, p92, p93));
        atomicAdd(mb + 256, make_float4(pa0, pa1, pa2, pa3));
        atomicAdd(mb + 288, make_float4(p74, p84, p94, pa4));
    }
}

// ---------------- per-node output projection --------------------------------
__global__ void out_kernel(const float* __restrict__ Wo0,
                           const float* __restrict__ Wo1,
                           const float* __restrict__ Wo2,
                           float* __restrict__ out) {
    const int n = blockIdx.x;
    const int t = threadIdx.x;  // 288
    __shared__ float ms[1280];
    for (int j = t; j < 320; j += 288)
        reinterpret_cast<float4*>(ms)[j] = g_mid4[n * 320 + j];
    __syncthreads();

    float acc = 0.f;
    if (t < 32) {
#pragma unroll
        for (int s = 0; s < 3; s++)
#pragma unroll 8
            for (int u = 0; u < 32; u++)
                acc = fmaf(ms[u * 4 + s], __ldg(Wo0 + (s * 32 + u) * 32 + t), acc);
        acc *= 0.006378879538497859f;   // 1/(sqrt(96)*16)
    } else if (t < 128) {
        int c = t - 32, w = c / 3, i = c % 3;
#pragma unroll
        for (int q = 0; q < 4; q++)
#pragma unroll 8
            for (int u = 0; u < 32; u++)
                acc = fmaf(ms[128 + q * 128 + u * 4 + i], __ldg(Wo1 + (q * 32 + u) * 32 + w), acc);
        acc *= 0.005524271728019903f;   // 1/(sqrt(128)*16)
    } else {
        int c = t - 128, w = c / 5, i = c % 5;
        if (i < 4) {
#pragma unroll
            for (int r = 0; r < 4; r++)
#pragma unroll 8
                for (int u = 0; u < 32; u++)
                    acc = fmaf(ms[640 + r * 128 + u * 4 + i], __ldg(Wo2 + (r * 32 + u) * 32 + w), acc);
        } else {
#pragma unroll
            for (int r = 0; r < 4; r++)
#pragma unroll 8
                for (int u = 0; u < 32; u++)
                    acc = fmaf(ms[1152 + u * 4 + r], __ldg(Wo2 + (r * 32 + u) * 32 + w), acc);
        }
        acc *= 0.005524271728019903f;
    }
    out[n * 288 + t] = acc;
}

// ---------------- launch -----------------------------------------------------
extern "C" void kernel_launch(void* const* d_in, const int* in_sizes, int n_in,
                              void* d_out, int out_size) {
    const float* f_in   = (const float*)d_in[0];
    const float* pos    = (const float*)d_in[1];
    const int*   batch  = (const int*)d_in[2];
    const int*   esrc   = (const int*)d_in[3];
    const int*   edst   = (const int*)d_in[4];
    const float* shifts = (const float*)d_in[5];
    const float* cell   = (const float*)d_in[6];
    const int wb = n_in - 10;
    const float* Wu0 = (const float*)d_in[wb + 0];
    const float* Wu1 = (const float*)d_in[wb + 1];
    const float* Wu2 = (const float*)d_in[wb + 2];
    const float* Wr0 = (const float*)d_in[wb + 3];
    const float* Wr1 = (const float*)d_in[wb + 4];
    const float* Wr2 = (const float*)d_in[wb + 5];
    const float* Wr3 = (const float*)d_in[wb + 6];
    const float* Wo0 = (const float*)d_in[wb + 7];
    const float* Wo1 = (const float*)d_in[wb + 8];
    const float* Wo2 = (const float*)d_in[wb + 9];

    const int N = in_sizes[0] / 288;
    const int E = in_sizes[3];

    static int smem_set = 0;
    const int smem_bytes = 16704 * 4;  // 66816
    if (!smem_set) {
        cudaFuncSetAttribute(edge_kernel, cudaFuncAttributeMaxDynamicSharedMemorySize, smem_bytes);
        smem_set = 1;
    }

    cst_kernel<<<1, 256>>>();
    const int n4 = N * 320;
    zero_kernel<<<(n4 + 255) / 256, 256>>>(n4);
    w3prep_kernel<<<(8 * 44 * 32 + 255) / 256, 256>>>(Wr3);
    up_kernel<<<N, 288>>>(f_in, Wu0, Wu1, Wu2);
    edge_kernel<<<(E + 31) / 32, 256, smem_bytes>>>(pos, batch, esrc, edst, shifts, cell,
                                                    Wr0, Wr1, Wr2, E);
    out_kernel<<<N, 288>>>(Wo0, Wo1, Wo2, (float*)d_out);
}

// round 9
// speedup vs baseline: 1.3162x; 1.0295x over previous
#include <cuda_runtime.h>
#include <math.h>

#define MAXN 10000

// ---------------- device scratch --------------------------------------------
__device__ float    g_cst;                     // CST_SILU
__device__ float    g_xs[MAXN * 288];          // up-projected node features, [node][slot 0..8][u 0..31]
__device__ float4   g_mid4[MAXN * 320];        // aggregated messages, 1280 f/node
__device__ unsigned g_w3f[8 * 44 * 32 * 2];    // Wr3/8 in tf32 mma-B fragment layout

// g_xs per-node layout (288 floats): slot*32 + u, slot = {x0, x1_0..2, x2_0..4}
// g_mid per-node layout (1280 floats):
//   A [0,128):      u*4 + s        s = path0,path1,path2,(pad)          (l0)
//   B [128,640):    128 + q*128 + u*4 + i   q=l1 path 0..3, i=x,y,z,(pad)
//   C [640,1152):   640 + r*128 + u*4 + c   r=l2 path 0..3, c=0..3
//   D [1152,1280):  1152 + u*4 + r          comp4 of l2 path r

typedef unsigned long long ull;

__device__ __forceinline__ float silu_f(float v) {
    return __fdividef(v, 1.0f + __expf(-v));
}

// packed fp32x2 fma helpers
#define FFMA2(d, a, b) asm("fma.rn.f32x2 %0, %1, %2, %3;" : "=l"(d) : "l"(a), "l"(b), "l"(d))

__device__ __forceinline__ float2 upk(ull v) {
    float2 r;
    asm("mov.b64 {%0, %1}, %2;" : "=f"(r.x), "=f"(r.y) : "l"(v));
    return r;
}
__device__ __forceinline__ ull dal(double d) { return __double_as_longlong(d); }

__device__ __forceinline__ unsigned tf32_rna(float x) {
    unsigned u;
    asm("cvt.rna.tf32.f32 %0, %1;" : "=r"(u) : "f"(x));
    return u;
}

__device__ __forceinline__ void mma_tf32(float& c0, float& c1, float& c2, float& c3,
                                         unsigned a0, unsigned a1, unsigned a2, unsigned a3,
                                         unsigned b0, unsigned b1) {
    asm volatile(
        "mma.sync.aligned.m16n8k8.row.col.f32.tf32.tf32.f32 "
        "{%0,%1,%2,%3},{%4,%5,%6,%7},{%8,%9},{%0,%1,%2,%3};"
        : "+f"(c0), "+f"(c1), "+f"(c2), "+f"(c3)
        : "r"(a0), "r"(a1), "r"(a2), "r"(a3), "r"(b0), "r"(b1));
}

// ---------------- CST_SILU via composite Simpson (double) -------------------
__global__ void cst_kernel() {
    __shared__ double red[256];
    const int t = threadIdx.x;
    const int NI = 4096;
    const double h = 24.0 / NI;
    double s = 0.0;
    for (int i = t; i <= NI; i += 256) {
        double xx = -12.0 + h * i;
        double sig = 1.0 / (1.0 + exp(-xx));
        double f = xx * sig;
        f = f * f * exp(-0.5 * xx * xx);
        double c = (i == 0 || i == NI) ? 1.0 : ((i & 1) ? 4.0 : 2.0);
        s += c * f;
    }
    red[t] = s;
    __syncthreads();
    for (int o = 128; o > 0; o >>= 1) {
        if (t < o) red[t] += red[t + o];
        __syncthreads();
    }
    if (t == 0) {
        double I = red[0] * h / 3.0 / 2.5066282746310005024;
        g_cst = (float)(1.0 / sqrt(I));
    }
}

// ---------------- zero mid ---------------------------------------------------
__global__ void zero_kernel(int n4) {
    int i = blockIdx.x * blockDim.x + threadIdx.x;
    if (i < n4) g_mid4[i] = make_float4(0.f, 0.f, 0.f, 0.f);
}

// ---------------- Wr3 -> tf32 B-fragment repack -----------------------------
__global__ void w3prep_kernel(const float* __restrict__ Wr3) {
    const int f = blockIdx.x * blockDim.x + threadIdx.x;  // 0 .. 8*44*32-1
    if (f >= 8 * 44 * 32) return;
    const int lane = f & 31;
    const int pair = f >> 5;
    const int nt = pair % 44;
    const int kt = pair / 44;
    const int tig = lane & 3;
    const int gid = lane >> 2;
    const int n = nt * 8 + gid;
    float w0 = Wr3[(kt * 8 + tig) * 352 + n] * 0.125f;
    float w1 = Wr3[(kt * 8 + tig + 4) * 352 + n] * 0.125f;
    g_w3f[f * 2 + 0] = tf32_rna(w0);
    g_w3f[f * 2 + 1] = tf32_rna(w1);
}

// ---------------- node up-projection ----------------------------------------
__global__ void up_kernel(const float* __restrict__ f_in,
                          const float* __restrict__ Wu0,
                          const float* __restrict__ Wu1,
                          const float* __restrict__ Wu2) {
    const int n = blockIdx.x;
    const int t = threadIdx.x;  // 288
    __shared__ float fs[288];
    fs[t] = f_in[n * 288 + t];
    __syncthreads();
    int i, off, w, d, slot;
    const float* W;
    if (t < 32)       { w = t;         i = 0;         d = 1; off = 0;   W = Wu0; slot = 0; }
    else if (t < 128) { int c = t-32;  w = c/3; i = c%3; d = 3; off = 32;  W = Wu1; slot = 1 + i; }
    else              { int c = t-128; w = c/5; i = c%5; d = 5; off = 128; W = Wu2; slot = 4 + i; }
    float acc = 0.f;
#pragma unroll 8
    for (int u = 0; u < 32; u++)
        acc = fmaf(fs[off + u * d + i], __ldg(W + u * 32 + w), acc);
    g_xs[n * 288 + slot * 32 + w] = acc * 0.17677669529663687f;
}

// ---------------- radial MLP 64->64 layer (4 edges, duplicated layout) ------
__device__ __forceinline__ void mlp64d(const float* __restrict__ in2,
                                       float* __restrict__ out2,
                                       const float* __restrict__ W,
                                       int lane, float cst) {
    const int o0 = 2 * lane;
    ull accA[4] = {0ull,0ull,0ull,0ull};
    ull accB[4] = {0ull,0ull,0ull,0ull};
#pragma unroll 4
    for (int j2 = 0; j2 < 32; j2++) {
        ull w0 = dal(__ldg(reinterpret_cast<const double*>(W + (2*j2)   * 64 + o0)));
        ull w1 = dal(__ldg(reinterpret_cast<const double*>(W + (2*j2+1) * 64 + o0)));
#pragma unroll
        for (int e = 0; e < 4; e++) {
            ulonglong2 hp = *reinterpret_cast<const ulonglong2*>(in2 + e * 128 + 4 * j2);
            FFMA2(accA[e], w0, hp.x);
            FFMA2(accB[e], w1, hp.y);
        }
    }
#pragma unroll
    for (int e = 0; e < 4; e++) {
        float2 va = upk(accA[e]);
        float2 vb = upk(accB[e]);
        float v0 = silu_f((va.x + vb.x) * 0.125f) * cst;
        float v1 = silu_f((va.y + vb.y) * 0.125f) * cst;
        *reinterpret_cast<float4*>(out2 + e * 128 + 4 * lane) = make_float4(v0, v0, v1, v1);
    }
}

// smem layout (floats), phases alias:
//   phase 1: hA2 [0,4096)  hB2 [4096,8192)   8 warps x [4 edges][128]
//            hfr [8192,10304)  A-fragments: [etile 2][kt 8][reg 4][33]
//   phase 2+ (after afr regs loaded): wsm [0, 11584) = [32 edges][stride 362]
#define SM_HA 0
#define SM_HB 4096
#define SM_HF 8192
#define WS_STRIDE 362
#define SM_TOTAL_F 11584

// ---------------- fused per-edge kernel (block = 32 edges) ------------------
__global__ void __launch_bounds__(256, 2) edge_kernel(
    const float* __restrict__ pos, const int* __restrict__ batch,
    const int* __restrict__ esrc, const int* __restrict__ edst,
    const float* __restrict__ shifts, const float* __restrict__ cell,
    const float* __restrict__ Wr0, const float* __restrict__ Wr1,
    const float* __restrict__ Wr2, int E)
{
    extern __shared__ float sm[];
    const int wid  = threadIdx.x >> 5;
    const int lane = threadIdx.x & 31;
    float* hA2 = sm + SM_HA + wid * 512;
    float* hB2 = sm + SM_HB + wid * 512;
    unsigned* hfr = reinterpret_cast<unsigned*>(sm + SM_HF);
    float* wsm = sm;   // aliases hA2/hB2/hfr after fragment handoff

    const int base = blockIdx.x * 32 + wid * 4;   // this warp's 4 TP edges
    const int etile = wid >> 2;                   // 16-edge tile of this warp
    const float cst = g_cst;

    // ================= phase 1: geometry + radial MLP layers 1-3 ============
    float uxr[4], uyr[4], uzr[4], Lr[4];
    int srcr[4], dstr[4];
#pragma unroll
    for (int e = 0; e < 4; e++) {
        int ei = (base + e < E) ? base + e : E - 1;
        const int src = __ldg(esrc + ei);
        const int dst = __ldg(edst + ei);
        srcr[e] = src; dstr[e] = dst;
        const float sx = __ldg(shifts + 3*ei), sy = __ldg(shifts + 3*ei+1), sz = __ldg(shifts + 3*ei+2);
        const float* Cc = cell + 9 * __ldg(batch + src);
        float vx = __ldg(pos+3*dst+0) - __ldg(pos+3*src+0) + sx*__ldg(Cc+0) + sy*__ldg(Cc+3) + sz*__ldg(Cc+6);
        float vy = __ldg(pos+3*dst+1) - __ldg(pos+3*src+1) + sx*__ldg(Cc+1) + sy*__ldg(Cc+4) + sz*__ldg(Cc+7);
        float vz = __ldg(pos+3*dst+2) - __ldg(pos+3*src+2) + sx*__ldg(Cc+2) + sy*__ldg(Cc+5) + sz*__ldg(Cc+8);
        float L = sqrtf(vx*vx + vy*vy + vz*vz);
        float inv = 1.0f / fmaxf(L, 1e-12f);
        uxr[e] = vx*inv; uyr[e] = vy*inv; uzr[e] = vz*inv; Lr[e] = L;
    }

    // radial embedding, duplicated into hB2[e][0..15]
    {
        const int k = lane & 7;
        const int e = lane >> 3;
        float Ls = Lr[0];
        if (e == 1) Ls = Lr[1]; else if (e == 2) Ls = Lr[2]; else if (e == 3) Ls = Lr[3];
        float tt = (Ls - (float)(k + 1) * (5.0f / 9.0f)) * 1.8f;
        float v = __expf(-tt * tt) * 2.525381361380527f;  // sqrt(8)/1.12
        *reinterpret_cast<float2*>(hB2 + e * 128 + 2 * k) = make_float2(v, v);
    }
    __syncwarp();

    const int o0 = 2 * lane;
    // layer 1: 8 -> 64 (hB2 -> hA2)
    {
        ull acc[4] = {0ull,0ull,0ull,0ull};
#pragma unroll
        for (int j2 = 0; j2 < 4; j2++) {
            ull w0 = dal(__ldg(reinterpret_cast<const double*>(Wr0 + (2*j2)   * 64 + o0)));
            ull w1 = dal(__ldg(reinterpret_cast<const double*>(Wr0 + (2*j2+1) * 64 + o0)));
#pragma unroll
            for (int e = 0; e < 4; e++) {
                ulonglong2 hp = *reinterpret_cast<const ulonglong2*>(hB2 + e * 128 + 4 * j2);
                FFMA2(acc[e], w0, hp.x);
                FFMA2(acc[e], w1, hp.y);
            }
        }
#pragma unroll
        for (int e = 0; e < 4; e++) {
            float2 v = upk(acc[e]);
            float v0 = silu_f(v.x * 0.35355339059327373f) * cst;
            float v1 = silu_f(v.y * 0.35355339059327373f) * cst;
            *reinterpret_cast<float4*>(hA2 + e * 128 + 4 * lane) = make_float4(v0, v0, v1, v1);
        }
    }
    __syncwarp();
    mlp64d(hA2, hB2, Wr1, lane, cst);   // layer 2
    __syncwarp();

    // layer 3: read hB2, write h into A-fragment layout (tf32 bits)
    {
        ull accA[4] = {0ull,0ull,0ull,0ull};
        ull accB[4] = {0ull,0ull,0ull,0ull};
#pragma unroll 4
        for (int j2 = 0; j2 < 32; j2++) {
            ull w0 = dal(__ldg(reinterpret_cast<const double*>(Wr2 + (2*j2)   * 64 + o0)));
            ull w1 = dal(__ldg(reinterpret_cast<const double*>(Wr2 + (2*j2+1) * 64 + o0)));
#pragma unroll
            for (int e = 0; e < 4; e++) {
                ulonglong2 hp = *reinterpret_cast<const ulonglong2*>(hB2 + e * 128 + 4 * j2);
                FFMA2(accA[e], w0, hp.x);
                FFMA2(accB[e], w1, hp.y);
            }
        }
#pragma unroll
        for (int e = 0; e < 4; e++) {
            float2 va = upk(accA[e]);
            float2 vb = upk(accB[e]);
            float v0 = silu_f((va.x + vb.x) * 0.125f) * cst;
            float v1 = silu_f((va.y + vb.y) * 0.125f) * cst;
            const int m = (wid & 3) * 4 + e;           // row within 16-edge tile
#pragma unroll
            for (int cc = 0; cc < 2; cc++) {
                int k  = 2 * lane + cc;
                float v = cc ? v1 : v0;
                int kt  = k >> 3;
                int kin = k & 7;
                int reg = ((m >= 8) ? 1 : 0) + ((kin >= 4) ? 2 : 0);
                int lp  = (m & 7) * 4 + (kin & 3);
                hfr[((etile * 8 + kt) * 4 + reg) * 33 + lp] = tf32_rna(v);
            }
        }
    }
    __syncthreads();

    // ================= fragment handoff =====================================
    unsigned afr[8][4];
#pragma unroll
    for (int kt = 0; kt < 8; kt++)
#pragma unroll
        for (int r = 0; r < 4; r++)
            afr[kt][r] = hfr[((etile * 8 + kt) * 4 + r) * 33 + lane];
    __syncthreads();   // fragments now in regs; smem freed for wsm

    // ================= single MMA pass: all 44 n-tiles ======================
    const int nch = wid & 3;
    const int gid = lane >> 2;
    const int tig = lane & 3;
    const uint2* Bf = reinterpret_cast<const uint2*>(g_w3f);
#pragma unroll 1
    for (int tt = 0; tt < 11; tt++) {
        const int nt = nch * 11 + tt;
        float c0 = 0.f, c1 = 0.f, c2 = 0.f, c3 = 0.f;
#pragma unroll
        for (int kt = 0; kt < 8; kt++) {
            uint2 b = __ldg(Bf + (kt * 44 + nt) * 32 + lane);
            mma_tf32(c0, c1, c2, c3, afr[kt][0], afr[kt][1], afr[kt][2], afr[kt][3], b.x, b.y);
        }
        const int col = nt * 8 + tig * 2;
        float* r0 = wsm + (etile * 16 + gid) * WS_STRIDE + col;
        *reinterpret_cast<float2*>(r0) = make_float2(c0, c1);
        *reinterpret_cast<float2*>(r0 + 8 * WS_STRIDE) = make_float2(c2, c3);
    }
    __syncthreads();

    // ================= TP + coalesced vector atomics (single pass) ==========
    const float A_  = 0.31622776601683794f;  // 1/sqrt(10)
    const float B_  = 0.18257418583505536f;  // 1/sqrt(30)
    const float AL  = 0.11952286093343936f;  // 1/sqrt(70)
    const float BE  = 0.20701966780270626f;  // sqrt(3/70)
    const float SQ3 = 1.7320508075688772f;
    const float SQ5 = 2.23606797749979f;

#pragma unroll 1
    for (int e = 0; e < 4; e++) {
        if (base + e >= E) break;
        const int src = srcr[e];
        const int dst = dstr[e];
        const float ux = uxr[e], uy = uyr[e], uz = uzr[e];
        const float s1x = SQ3 * ux, s1y = SQ3 * uy, s1z = SQ3 * uz;
        const float s20 = 3.872983346207417f * ux * uz;
        const float s21 = 3.872983346207417f * ux * uy;
        const float s22 = SQ5 * (uy*uy - 0.5f*(ux*ux + uz*uz));
        const float s23 = 3.872983346207417f * uy * uz;
        const float s24 = 1.9364916731037085f * (uz*uz - ux*ux);

        const float* wrow = wsm + (wid * 4 + e) * WS_STRIDE + lane;
        float w[11];
#pragma unroll
        for (int k = 0; k < 11; k++) w[k] = wrow[k * 32];

        const float* xp = g_xs + src * 288 + lane;
        const float x0  = __ldg(xp);
        const float x10 = __ldg(xp + 32),  x11 = __ldg(xp + 64),  x12 = __ldg(xp + 96);
        const float x20 = __ldg(xp + 128), x21 = __ldg(xp + 160), x22 = __ldg(xp + 192);
        const float x23 = __ldg(xp + 224), x24 = __ldg(xp + 256);

        // l0
        const float p0 = x0 * w[0];
        const float p1 = 0.5773502691896258f * (x10*s1x + x11*s1y + x12*s1z) * w[1];
        const float p2 = 0.4472135954999579f * (x20*s20 + x21*s21 + x22*s22 + x23*s23 + x24*s24) * w[2];

        // l1
        const float c3 = x0 * w[3];
        float p5x, p5y, p5z;
        {
            float wv = SQ3 * w[5];
            float B00 = -B_*s22 - A_*s24;
            float B01 =  A_*s21;
            float B02 =  A_*s20;
            float B11 =  2.f*B_*s22;
            float B12 =  A_*s23;
            float B22 = -B_*s22 + A_*s24;
            p5x = wv * (x10*B00 + x11*B01 + x12*B02);
            p5y = wv * (x10*B01 + x11*B11 + x12*B12);
            p5z = wv * (x10*B02 + x11*B12 + x12*B22);
        }
        float p6x, p6y, p6z;
        {
            float wv = SQ3 * w[6];
            p6x = wv * (A_*(x20*s1z + x21*s1y) - B_*x22*s1x - A_*x24*s1x);
            p6y = wv * (A_*(x21*s1x + x23*s1z) + 2.f*B_*x22*s1y);
            p6z = wv * (A_*(x20*s1x + x23*s1y + x24*s1z) - B_*x22*s1z);
        }

        // l2
        const float c7 = x0 * w[7];
        const float p70 = c7*s20, p71 = c7*s21, p72 = c7*s22, p73 = c7*s23, p74 = c7*s24;
        float p80, p81, p82, p83, p84;
        {
            float wv = SQ5 * w[8];
            p80 = wv * (A_*(x10*s1z + x12*s1x));
            p81 = wv * (A_*(x10*s1y + x11*s1x));
            p82 = wv * (B_*(-x10*s1x + 2.f*x11*s1y - x12*s1z));
            p83 = wv * (A_*(x11*s1z + x12*s1y));
            p84 = wv * (A_*(-x10*s1x + x12*s1z));
        }
        const float p90 = x20*w[9], p91 = x21*w[9], p92 = x22*w[9], p93 = x23*w[9], p94 = x24*w[9];
        float pa0, pa1, pa2, pa3, pa4;
        {
            float wv = SQ5 * w[10];
            pa0 = wv * (x20*(2.f*AL*s22) + x21*(-BE*s23) + x22*(2.f*AL*s20) + x23*(-BE*s21));
            pa1 = wv * (x20*(-BE*s23) + x21*(-AL*s22 + BE*s24) + x22*(-AL*s21) + x23*(-BE*s20) + x24*(BE*s21));
            pa2 = wv * (x20*(2.f*AL*s20) + x21*(-AL*s21) + x22*(-2.f*AL*s22) + x23*(-AL*s23) + x24*(2.f*AL*s24));
            pa3 = wv * (x20*(-BE*s21) + x21*(-BE*s20) + x22*(-AL*s23) + x23*(-AL*s22 - BE*s24) + x24*(-BE*s23));
            pa4 = wv * (x21*(BE*s21) + x22*(2.f*AL*s24) + x23*(-BE*s23) + x24*(2.f*AL*s22));
        }

        float4* mb = reinterpret_cast<float4*>(reinterpret_cast<float*>(g_mid4) + dst * 1280) + lane;
        atomicAdd(mb,       make_float4(p0, p1, p2, 0.f));          // A
        atomicAdd(mb + 32,  make_float4(c3*s1x, c3*s1y, c3*s1z, 0.f));
        atomicAdd(mb + 64,  make_float4(x10*w[4], x11*w[4], x12*w[4], 0.f));
        atomicAdd(mb + 96,  make_float4(p5x, p5y, p5z, 0.f));
        atomicAdd(mb + 128, make_float4(p6x, p6y, p6z, 0.f));
        atomicAdd(mb + 160, make_float4(p70, p71, p72, p73));
        atomicAdd(mb + 192, make_float4(p80, p81, p82, p83));
        atomicAdd(mb + 224, make_float4(p90, p91, p92, p93));
        atomicAdd(mb + 256, make_float4(pa0, pa1, pa2, pa3));
        atomicAdd(mb + 288, make_float4(p74, p84, p94, pa4));
    }
}

// ---------------- per-node output projection --------------------------------
__global__ void out_kernel(const float* __restrict__ Wo0,
                           const float* __restrict__ Wo1,
                           const float* __restrict__ Wo2,
                           float* __restrict__ out) {
    const int n = blockIdx.x;
    const int t = threadIdx.x;  // 288
    __shared__ float ms[1280];
    for (int j = t; j < 320; j += 288)
        reinterpret_cast<float4*>(ms)[j] = g_mid4[n * 320 + j];
    __syncthreads();

    float acc = 0.f;
    if (t < 32) {
#pragma unroll
        for (int s = 0; s < 3; s++)
#pragma unroll 8
            for (int u = 0; u < 32; u++)
                acc = fmaf(ms[u * 4 + s], __ldg(Wo0 + (s * 32 + u) * 32 + t), acc);
        acc *= 0.006378879538497859f;   // 1/(sqrt(96)*16)
    } else if (t < 128) {
        int c = t - 32, w = c / 3, i = c % 3;
#pragma unroll
        for (int q = 0; q < 4; q++)
#pragma unroll 8
            for (int u = 0; u < 32; u++)
                acc = fmaf(ms[128 + q * 128 + u * 4 + i], __ldg(Wo1 + (q * 32 + u) * 32 + w), acc);
        acc *= 0.005524271728019903f;   // 1/(sqrt(128)*16)
    } else {
        int c = t - 128, w = c / 5, i = c % 5;
        if (i < 4) {
#pragma unroll
            for (int r = 0; r < 4; r++)
#pragma unroll 8
                for (int u = 0; u < 32; u++)
                    acc = fmaf(ms[640 + r * 128 + u * 4 + i], __ldg(Wo2 + (r * 32 + u) * 32 + w), acc);
        } else {
#pragma unroll
            for (int r = 0; r < 4; r++)
#pragma unroll 8
                for (int u = 0; u < 32; u++)
                    acc = fmaf(ms[1152 + u * 4 + r], __ldg(Wo2 + (r * 32 + u) * 32 + w), acc);
        }
        acc *= 0.005524271728019903f;
    }
    out[n * 288 + t] = acc;
}

// ---------------- launch -----------------------------------------------------
extern "C" void kernel_launch(void* const* d_in, const int* in_sizes, int n_in,
                              void* d_out, int out_size) {
    const float* f_in   = (const float*)d_in[0];
    const float* pos    = (const float*)d_in[1];
    const int*   batch  = (const int*)d_in[2];
    const int*   esrc   = (const int*)d_in[3];
    const int*   edst   = (const int*)d_in[4];
    const float* shifts = (const float*)d_in[5];
    const float* cell   = (const float*)d_in[6];
    const int wb = n_in - 10;
    const float* Wu0 = (const float*)d_in[wb + 0];
    const float* Wu1 = (const float*)d_in[wb + 1];
    const float* Wu2 = (const float*)d_in[wb + 2];
    const float* Wr0 = (const float*)d_in[wb + 3];
    const float* Wr1 = (const float*)d_in[wb + 4];
    const float* Wr2 = (const float*)d_in[wb + 5];
    const float* Wr3 = (const float*)d_in[wb + 6];
    const float* Wo0 = (const float*)d_in[wb + 7];
    const float* Wo1 = (const float*)d_in[wb + 8];
    const float* Wo2 = (const float*)d_in[wb + 9];

    const int N = in_sizes[0] / 288;
    const int E = in_sizes[3];

    static int smem_set = 0;
    const int smem_bytes = SM_TOTAL_F * 4;  // 46336
    if (!smem_set) {
        cudaFuncSetAttribute(edge_kernel, cudaFuncAttributeMaxDynamicSharedMemorySize, smem_bytes);
        smem_set = 1;
    }

    cst_kernel<<<1, 256>>>();
    const int n4 = N * 320;
    zero_kernel<<<(n4 + 255) / 256, 256>>>(n4);
    w3prep_kernel<<<(8 * 44 * 32 + 255) / 256, 256>>>(Wr3);
    up_kernel<<<N, 288>>>(f_in, Wu0, Wu1, Wu2);
    edge_kernel<<<(E + 31) / 32, 256, smem_bytes>>>(pos, batch, esrc, edst, shifts, cell,
                                                    Wr0, Wr1, Wr2, E);
    out_kernel<<<N, 288>>>(Wo0, Wo1, Wo2, (float*)d_out);
}

// round 10
// speedup vs baseline: 1.5374x; 1.1681x over previous
#include <cuda_runtime.h>
#include <math.h>

#define MAXN 10000

// ---------------- device scratch --------------------------------------------
__device__ float    g_cst;                     // CST_SILU
__device__ float    g_xs[MAXN * 288];          // up-projected node features, [node][slot 0..8][u 0..31]
__device__ float4   g_mid4[MAXN * 320];        // aggregated messages, 1280 f/node
__device__ unsigned g_w3f[8 * 44 * 32 * 2];    // Wr3/8 in tf32 mma-B fragment layout

// g_xs per-node layout (288 floats): slot*32 + u, slot = {x0, x1_0..2, x2_0..4}
// g_mid per-node layout (1280 floats):
//   A [0,128):      u*4 + s        s = path0,path1,path2,(pad)          (l0)
//   B [128,640):    128 + q*128 + u*4 + i   q=l1 path 0..3, i=x,y,z,(pad)
//   C [640,1152):   640 + r*128 + u*4 + c   r=l2 path 0..3, c=0..3
//   D [1152,1280):  1152 + u*4 + r          comp4 of l2 path r

typedef unsigned long long ull;

__device__ __forceinline__ float silu_f(float v) {
    return __fdividef(v, 1.0f + __expf(-v));
}

// packed fp32x2 fma helpers
#define FFMA2(d, a, b) asm("fma.rn.f32x2 %0, %1, %2, %3;" : "=l"(d) : "l"(a), "l"(b), "l"(d))

__device__ __forceinline__ float2 upk(ull v) {
    float2 r;
    asm("mov.b64 {%0, %1}, %2;" : "=f"(r.x), "=f"(r.y) : "l"(v));
    return r;
}
__device__ __forceinline__ ull dal(double d) { return __double_as_longlong(d); }

__device__ __forceinline__ unsigned tf32_rna(float x) {
    unsigned u;
    asm("cvt.rna.tf32.f32 %0, %1;" : "=r"(u) : "f"(x));
    return u;
}

__device__ __forceinline__ void mma_tf32(float& c0, float& c1, float& c2, float& c3,
                                         unsigned a0, unsigned a1, unsigned a2, unsigned a3,
                                         unsigned b0, unsigned b1) {
    asm volatile(
        "mma.sync.aligned.m16n8k8.row.col.f32.tf32.tf32.f32 "
        "{%0,%1,%2,%3},{%4,%5,%6,%7},{%8,%9},{%0,%1,%2,%3};"
        : "+f"(c0), "+f"(c1), "+f"(c2), "+f"(c3)
        : "r"(a0), "r"(a1), "r"(a2), "r"(a3), "r"(b0), "r"(b1));
}

// ---------------- CST_SILU via composite Simpson (double) -------------------
__global__ void cst_kernel() {
    __shared__ double red[256];
    const int t = threadIdx.x;
    const int NI = 4096;
    const double h = 24.0 / NI;
    double s = 0.0;
    for (int i = t; i <= NI; i += 256) {
        double xx = -12.0 + h * i;
        double sig = 1.0 / (1.0 + exp(-xx));
        double f = xx * sig;
        f = f * f * exp(-0.5 * xx * xx);
        double c = (i == 0 || i == NI) ? 1.0 : ((i & 1) ? 4.0 : 2.0);
        s += c * f;
    }
    red[t] = s;
    __syncthreads();
    for (int o = 128; o > 0; o >>= 1) {
        if (t < o) red[t] += red[t + o];
        __syncthreads();
    }
    if (t == 0) {
        double I = red[0] * h / 3.0 / 2.5066282746310005024;
        g_cst = (float)(1.0 / sqrt(I));
    }
}

// ---------------- zero mid ---------------------------------------------------
__global__ void zero_kernel(int n4) {
    int i = blockIdx.x * blockDim.x + threadIdx.x;
    if (i < n4) g_mid4[i] = make_float4(0.f, 0.f, 0.f, 0.f);
}

// ---------------- Wr3 -> tf32 B-fragment repack -----------------------------
__global__ void w3prep_kernel(const float* __restrict__ Wr3) {
    const int f = blockIdx.x * blockDim.x + threadIdx.x;  // 0 .. 8*44*32-1
    if (f >= 8 * 44 * 32) return;
    const int lane = f & 31;
    const int pair = f >> 5;
    const int nt = pair % 44;
    const int kt = pair / 44;
    const int tig = lane & 3;
    const int gid = lane >> 2;
    const int n = nt * 8 + gid;
    float w0 = Wr3[(kt * 8 + tig) * 352 + n] * 0.125f;
    float w1 = Wr3[(kt * 8 + tig + 4) * 352 + n] * 0.125f;
    g_w3f[f * 2 + 0] = tf32_rna(w0);
    g_w3f[f * 2 + 1] = tf32_rna(w1);
}

// ---------------- node up-projection (4 nodes/block, slot-major) ------------
__global__ void up_kernel(const float* __restrict__ f_in,
                          const float* __restrict__ Wu0,
                          const float* __restrict__ Wu1,
                          const float* __restrict__ Wu2, int N) {
    const int n0 = blockIdx.x * 4;
    const int t = threadIdx.x;  // 288
    __shared__ float fs[4][288];
    const int nmax = (N - n0 < 4) ? (N - n0) : 4;
#pragma unroll 1
    for (int j = t; j < nmax * 288; j += 288)
        fs[j / 288][j % 288] = f_in[n0 * 288 + j];
    __syncthreads();

    const int slot = t >> 5;
    const int w = t & 31;
    int i, off, d;
    const float* W;
    if (slot == 0)      { i = 0;        d = 1; off = 0;   W = Wu0; }
    else if (slot < 4)  { i = slot - 1; d = 3; off = 32;  W = Wu1; }
    else                { i = slot - 4; d = 5; off = 128; W = Wu2; }

    float acc[4] = {0.f, 0.f, 0.f, 0.f};
#pragma unroll 8
    for (int u = 0; u < 32; u++) {
        float wt = __ldg(W + u * 32 + w);
        const int fi = off + u * d + i;
#pragma unroll
        for (int e = 0; e < 4; e++)
            acc[e] = fmaf(fs[e][fi], wt, acc[e]);
    }
#pragma unroll
    for (int e = 0; e < nmax; e++)
        g_xs[(n0 + e) * 288 + slot * 32 + w] = acc[e] * 0.17677669529663687f;
}

// ---------------- radial MLP 64->64 layer (4 edges, duplicated layout) ------
__device__ __forceinline__ void mlp64d(const float* __restrict__ in2,
                                       float* __restrict__ out2,
                                       const float* __restrict__ W,
                                       int lane, float cst) {
    const int o0 = 2 * lane;
    ull accA[4] = {0ull,0ull,0ull,0ull};
    ull accB[4] = {0ull,0ull,0ull,0ull};
#pragma unroll 4
    for (int j2 = 0; j2 < 32; j2++) {
        ull w0 = dal(__ldg(reinterpret_cast<const double*>(W + (2*j2)   * 64 + o0)));
        ull w1 = dal(__ldg(reinterpret_cast<const double*>(W + (2*j2+1) * 64 + o0)));
#pragma unroll
        for (int e = 0; e < 4; e++) {
            ulonglong2 hp = *reinterpret_cast<const ulonglong2*>(in2 + e * 128 + 4 * j2);
            FFMA2(accA[e], w0, hp.x);
            FFMA2(accB[e], w1, hp.y);
        }
    }
#pragma unroll
    for (int e = 0; e < 4; e++) {
        float2 va = upk(accA[e]);
        float2 vb = upk(accB[e]);
        float v0 = silu_f((va.x + vb.x) * 0.125f) * cst;
        float v1 = silu_f((va.y + vb.y) * 0.125f) * cst;
        *reinterpret_cast<float4*>(out2 + e * 128 + 4 * lane) = make_float4(v0, v0, v1, v1);
    }
}

// smem layout (floats), phases alias:
//   phase 1: hA2 [0,4096)  hB2 [4096,8192)   8 warps x [4 edges][128]
//            hfr [8192,10304)  A-fragments: [etile 2][kt 8][reg 4][33]
//   phase 2+ (after afr regs loaded): wsm [0, 11584) = [32 edges][stride 362]
#define SM_HA 0
#define SM_HB 4096
#define SM_HF 8192
#define WS_STRIDE 362
#define SM_TOTAL_F 11584

// ---------------- fused per-edge kernel (block = 32 edges) ------------------
__global__ void __launch_bounds__(256, 2) edge_kernel(
    const float* __restrict__ pos, const int* __restrict__ batch,
    const int* __restrict__ esrc, const int* __restrict__ edst,
    const float* __restrict__ shifts, const float* __restrict__ cell,
    const float* __restrict__ Wr0, const float* __restrict__ Wr1,
    const float* __restrict__ Wr2, int E)
{
    extern __shared__ float sm[];
    const int wid  = threadIdx.x >> 5;
    const int lane = threadIdx.x & 31;
    float* hA2 = sm + SM_HA + wid * 512;
    float* hB2 = sm + SM_HB + wid * 512;
    unsigned* hfr = reinterpret_cast<unsigned*>(sm + SM_HF);
    float* wsm = sm;   // aliases hA2/hB2/hfr after fragment handoff

    const int base = blockIdx.x * 32 + wid * 4;   // this warp's 4 TP edges
    const int etile = wid >> 2;                   // 16-edge tile of this warp
    const float cst = g_cst;

    // ================= phase 1: geometry + radial MLP layers 1-3 ============
    float uxr[4], uyr[4], uzr[4], Lr[4];
    int srcr[4], dstr[4];
#pragma unroll
    for (int e = 0; e < 4; e++) {
        int ei = (base + e < E) ? base + e : E - 1;
        const int src = __ldg(esrc + ei);
        const int dst = __ldg(edst + ei);
        srcr[e] = src; dstr[e] = dst;
        const float sx = __ldg(shifts + 3*ei), sy = __ldg(shifts + 3*ei+1), sz = __ldg(shifts + 3*ei+2);
        const float* Cc = cell + 9 * __ldg(batch + src);
        float vx = __ldg(pos+3*dst+0) - __ldg(pos+3*src+0) + sx*__ldg(Cc+0) + sy*__ldg(Cc+3) + sz*__ldg(Cc+6);
        float vy = __ldg(pos+3*dst+1) - __ldg(pos+3*src+1) + sx*__ldg(Cc+1) + sy*__ldg(Cc+4) + sz*__ldg(Cc+7);
        float vz = __ldg(pos+3*dst+2) - __ldg(pos+3*src+2) + sx*__ldg(Cc+2) + sy*__ldg(Cc+5) + sz*__ldg(Cc+8);
        float L = sqrtf(vx*vx + vy*vy + vz*vz);
        float inv = 1.0f / fmaxf(L, 1e-12f);
        uxr[e] = vx*inv; uyr[e] = vy*inv; uzr[e] = vz*inv; Lr[e] = L;
    }

    // radial embedding, duplicated into hB2[e][0..15]
    {
        const int k = lane & 7;
        const int e = lane >> 3;
        float Ls = Lr[0];
        if (e == 1) Ls = Lr[1]; else if (e == 2) Ls = Lr[2]; else if (e == 3) Ls = Lr[3];
        float tt = (Ls - (float)(k + 1) * (5.0f / 9.0f)) * 1.8f;
        float v = __expf(-tt * tt) * 2.525381361380527f;  // sqrt(8)/1.12
        *reinterpret_cast<float2*>(hB2 + e * 128 + 2 * k) = make_float2(v, v);
    }
    __syncwarp();

    const int o0 = 2 * lane;
    // layer 1: 8 -> 64 (hB2 -> hA2)
    {
        ull acc[4] = {0ull,0ull,0ull,0ull};
#pragma unroll
        for (int j2 = 0; j2 < 4; j2++) {
            ull w0 = dal(__ldg(reinterpret_cast<const double*>(Wr0 + (2*j2)   * 64 + o0)));
            ull w1 = dal(__ldg(reinterpret_cast<const double*>(Wr0 + (2*j2+1) * 64 + o0)));
#pragma unroll
            for (int e = 0; e < 4; e++) {
                ulonglong2 hp = *reinterpret_cast<const ulonglong2*>(hB2 + e * 128 + 4 * j2);
                FFMA2(acc[e], w0, hp.x);
                FFMA2(acc[e], w1, hp.y);
            }
        }
#pragma unroll
        for (int e = 0; e < 4; e++) {
            float2 v = upk(acc[e]);
            float v0 = silu_f(v.x * 0.35355339059327373f) * cst;
            float v1 = silu_f(v.y * 0.35355339059327373f) * cst;
            *reinterpret_cast<float4*>(hA2 + e * 128 + 4 * lane) = make_float4(v0, v0, v1, v1);
        }
    }
    __syncwarp();
    mlp64d(hA2, hB2, Wr1, lane, cst);   // layer 2
    __syncwarp();

    // layer 3: read hB2, write h into A-fragment layout (tf32 bits)
    {
        ull accA[4] = {0ull,0ull,0ull,0ull};
        ull accB[4] = {0ull,0ull,0ull,0ull};
#pragma unroll 4
        for (int j2 = 0; j2 < 32; j2++) {
            ull w0 = dal(__ldg(reinterpret_cast<const double*>(Wr2 + (2*j2)   * 64 + o0)));
            ull w1 = dal(__ldg(reinterpret_cast<const double*>(Wr2 + (2*j2+1) * 64 + o0)));
#pragma unroll
            for (int e = 0; e < 4; e++) {
                ulonglong2 hp = *reinterpret_cast<const ulonglong2*>(hB2 + e * 128 + 4 * j2);
                FFMA2(accA[e], w0, hp.x);
                FFMA2(accB[e], w1, hp.y);
            }
        }
#pragma unroll
        for (int e = 0; e < 4; e++) {
            float2 va = upk(accA[e]);
            float2 vb = upk(accB[e]);
            float v0 = silu_f((va.x + vb.x) * 0.125f) * cst;
            float v1 = silu_f((va.y + vb.y) * 0.125f) * cst;
            const int m = (wid & 3) * 4 + e;           // row within 16-edge tile
#pragma unroll
            for (int cc = 0; cc < 2; cc++) {
                int k  = 2 * lane + cc;
                float v = cc ? v1 : v0;
                int kt  = k >> 3;
                int kin = k & 7;
                int reg = ((m >= 8) ? 1 : 0) + ((kin >= 4) ? 2 : 0);
                int lp  = (m & 7) * 4 + (kin & 3);
                hfr[((etile * 8 + kt) * 4 + reg) * 33 + lp] = tf32_rna(v);
            }
        }
    }
    __syncthreads();

    // ================= fragment handoff =====================================
    unsigned afr[8][4];
#pragma unroll
    for (int kt = 0; kt < 8; kt++)
#pragma unroll
        for (int r = 0; r < 4; r++)
            afr[kt][r] = hfr[((etile * 8 + kt) * 4 + r) * 33 + lane];
    __syncthreads();   // fragments now in regs; smem freed for wsm

    // ================= single MMA pass: all 44 n-tiles ======================
    const int nch = wid & 3;
    const int gid = lane >> 2;
    const int tig = lane & 3;
    const uint2* Bf = reinterpret_cast<const uint2*>(g_w3f);
#pragma unroll 1
    for (int tt = 0; tt < 11; tt++) {
        const int nt = nch * 11 + tt;
        float c0 = 0.f, c1 = 0.f, c2 = 0.f, c3 = 0.f;
#pragma unroll
        for (int kt = 0; kt < 8; kt++) {
            uint2 b = __ldg(Bf + (kt * 44 + nt) * 32 + lane);
            mma_tf32(c0, c1, c2, c3, afr[kt][0], afr[kt][1], afr[kt][2], afr[kt][3], b.x, b.y);
        }
        const int col = nt * 8 + tig * 2;
        float* r0 = wsm + (etile * 16 + gid) * WS_STRIDE + col;
        *reinterpret_cast<float2*>(r0) = make_float2(c0, c1);
        *reinterpret_cast<float2*>(r0 + 8 * WS_STRIDE) = make_float2(c2, c3);
    }
    __syncthreads();

    // ================= TP + coalesced vector atomics (single pass) ==========
    const float A_  = 0.31622776601683794f;  // 1/sqrt(10)
    const float B_  = 0.18257418583505536f;  // 1/sqrt(30)
    const float AL  = 0.11952286093343936f;  // 1/sqrt(70)
    const float BE  = 0.20701966780270626f;  // sqrt(3/70)
    const float SQ3 = 1.7320508075688772f;
    const float SQ5 = 2.23606797749979f;

#pragma unroll 1
    for (int e = 0; e < 4; e++) {
        if (base + e >= E) break;
        const int src = srcr[e];
        const int dst = dstr[e];
        const float ux = uxr[e], uy = uyr[e], uz = uzr[e];
        const float s1x = SQ3 * ux, s1y = SQ3 * uy, s1z = SQ3 * uz;
        const float s20 = 3.872983346207417f * ux * uz;
        const float s21 = 3.872983346207417f * ux * uy;
        const float s22 = SQ5 * (uy*uy - 0.5f*(ux*ux + uz*uz));
        const float s23 = 3.872983346207417f * uy * uz;
        const float s24 = 1.9364916731037085f * (uz*uz - ux*ux);

        const float* wrow = wsm + (wid * 4 + e) * WS_STRIDE + lane;
        float w[11];
#pragma unroll
        for (int k = 0; k < 11; k++) w[k] = wrow[k * 32];

        const float* xp = g_xs + src * 288 + lane;
        const float x0  = __ldg(xp);
        const float x10 = __ldg(xp + 32),  x11 = __ldg(xp + 64),  x12 = __ldg(xp + 96);
        const float x20 = __ldg(xp + 128), x21 = __ldg(xp + 160), x22 = __ldg(xp + 192);
        const float x23 = __ldg(xp + 224), x24 = __ldg(xp + 256);

        // l0
        const float p0 = x0 * w[0];
        const float p1 = 0.5773502691896258f * (x10*s1x + x11*s1y + x12*s1z) * w[1];
        const float p2 = 0.4472135954999579f * (x20*s20 + x21*s21 + x22*s22 + x23*s23 + x24*s24) * w[2];

        // l1
        const float c3 = x0 * w[3];
        float p5x, p5y, p5z;
        {
            float wv = SQ3 * w[5];
            float B00 = -B_*s22 - A_*s24;
            float B01 =  A_*s21;
            float B02 =  A_*s20;
            float B11 =  2.f*B_*s22;
            float B12 =  A_*s23;
            float B22 = -B_*s22 + A_*s24;
            p5x = wv * (x10*B00 + x11*B01 + x12*B02);
            p5y = wv * (x10*B01 + x11*B11 + x12*B12);
            p5z = wv * (x10*B02 + x11*B12 + x12*B22);
        }
        float p6x, p6y, p6z;
        {
            float wv = SQ3 * w[6];
            p6x = wv * (A_*(x20*s1z + x21*s1y) - B_*x22*s1x - A_*x24*s1x);
            p6y = wv * (A_*(x21*s1x + x23*s1z) + 2.f*B_*x22*s1y);
            p6z = wv * (A_*(x20*s1x + x23*s1y + x24*s1z) - B_*x22*s1z);
        }

        // l2
        const float c7 = x0 * w[7];
        const float p70 = c7*s20, p71 = c7*s21, p72 = c7*s22, p73 = c7*s23, p74 = c7*s24;
        float p80, p81, p82, p83, p84;
        {
            float wv = SQ5 * w[8];
            p80 = wv * (A_*(x10*s1z + x12*s1x));
            p81 = wv * (A_*(x10*s1y + x11*s1x));
            p82 = wv * (B_*(-x10*s1x + 2.f*x11*s1y - x12*s1z));
            p83 = wv * (A_*(x11*s1z + x12*s1y));
            p84 = wv * (A_*(-x10*s1x + x12*s1z));
        }
        const float p90 = x20*w[9], p91 = x21*w[9], p92 = x22*w[9], p93 = x23*w[9], p94 = x24*w[9];
        float pa0, pa1, pa2, pa3, pa4;
        {
            float wv = SQ5 * w[10];
            pa0 = wv * (x20*(2.f*AL*s22) + x21*(-BE*s23) + x22*(2.f*AL*s20) + x23*(-BE*s21));
            pa1 = wv * (x20*(-BE*s23) + x21*(-AL*s22 + BE*s24) + x22*(-AL*s21) + x23*(-BE*s20) + x24*(BE*s21));
            pa2 = wv * (x20*(2.f*AL*s20) + x21*(-AL*s21) + x22*(-2.f*AL*s22) + x23*(-AL*s23) + x24*(2.f*AL*s24));
            pa3 = wv * (x20*(-BE*s21) + x21*(-BE*s20) + x22*(-AL*s23) + x23*(-AL*s22 - BE*s24) + x24*(-BE*s23));
            pa4 = wv * (x21*(BE*s21) + x22*(2.f*AL*s24) + x23*(-BE*s23) + x24*(2.f*AL*s22));
        }

        float4* mb = reinterpret_cast<float4*>(reinterpret_cast<float*>(g_mid4) + dst * 1280) + lane;
        atomicAdd(mb,       make_float4(p0, p1, p2, 0.f));          // A
        atomicAdd(mb + 32,  make_float4(c3*s1x, c3*s1y, c3*s1z, 0.f));
        atomicAdd(mb + 64,  make_float4(x10*w[4], x11*w[4], x12*w[4], 0.f));
        atomicAdd(mb + 96,  make_float4(p5x, p5y, p5z, 0.f));
        atomicAdd(mb + 128, make_float4(p6x, p6y, p6z, 0.f));
        atomicAdd(mb + 160, make_float4(p70, p71, p72, p73));
        atomicAdd(mb + 192, make_float4(p80, p81, p82, p83));
        atomicAdd(mb + 224, make_float4(p90, p91, p92, p93));
        atomicAdd(mb + 256, make_float4(pa0, pa1, pa2, pa3));
        atomicAdd(mb + 288, make_float4(p74, p84, p94, pa4));
    }
}

// ---------------- per-node output projection (4 nodes/block, slot-major) ----
__global__ void out_kernel(const float* __restrict__ Wo0,
                           const float* __restrict__ Wo1,
                           const float* __restrict__ Wo2,
                           float* __restrict__ out, int N) {
    const int n0 = blockIdx.x * 4;
    const int t = threadIdx.x;  // 288
    __shared__ float ms[4][1280];
    const int nmax = (N - n0 < 4) ? (N - n0) : 4;
#pragma unroll 1
    for (int j = t; j < nmax * 320; j += 288) {
        const int node = j / 320, jj = j % 320;
        reinterpret_cast<float4*>(ms[node])[jj] = g_mid4[(n0 + node) * 320 + jj];
    }
    __syncthreads();

    const int slot = t >> 5;
    const int w = t & 31;
    float acc[4] = {0.f, 0.f, 0.f, 0.f};
    int off, d, i;
    float scale;

    if (slot == 0) {
        off = 0; d = 1; i = 0;
        scale = 0.006378879538497859f;   // 1/(sqrt(96)*16)
#pragma unroll
        for (int s = 0; s < 3; s++)
#pragma unroll 8
            for (int u = 0; u < 32; u++) {
                float wt = __ldg(Wo0 + (s * 32 + u) * 32 + w);
                const int mi = u * 4 + s;
#pragma unroll
                for (int e = 0; e < 4; e++)
                    acc[e] = fmaf(ms[e][mi], wt, acc[e]);
            }
    } else if (slot < 4) {
        off = 32; d = 3; i = slot - 1;
        scale = 0.005524271728019903f;   // 1/(sqrt(128)*16)
#pragma unroll
        for (int q = 0; q < 4; q++)
#pragma unroll 8
            for (int u = 0; u < 32; u++) {
                float wt = __ldg(Wo1 + (q * 32 + u) * 32 + w);
                const int mi = 128 + q * 128 + u * 4 + i;
#pragma unroll
                for (int e = 0; e < 4; e++)
                    acc[e] = fmaf(ms[e][mi], wt, acc[e]);
            }
    } else {
        off = 128; d = 5; i = slot - 4;
        scale = 0.005524271728019903f;
        if (i < 4) {
#pragma unroll
            for (int r = 0; r < 4; r++)
#pragma unroll 8
                for (int u = 0; u < 32; u++) {
                    float wt = __ldg(Wo2 + (r * 32 + u) * 32 + w);
                    const int mi = 640 + r * 128 + u * 4 + i;
#pragma unroll
                    for (int e = 0; e < 4; e++)
                        acc[e] = fmaf(ms[e][mi], wt, acc[e]);
                }
        } else {
#pragma unroll
            for (int r = 0; r < 4; r++)
#pragma unroll 8
                for (int u = 0; u < 32; u++) {
                    float wt = __ldg(Wo2 + (r * 32 + u) * 32 + w);
                    const int mi = 1152 + u * 4 + r;
#pragma unroll
                    for (int e = 0; e < 4; e++)
                        acc[e] = fmaf(ms[e][mi], wt, acc[e]);
                }
        }
    }

#pragma unroll
    for (int e = 0; e < nmax; e++)
        out[(n0 + e) * 288 + off + w * d + i] = acc[e] * scale;
}

// ---------------- launch -----------------------------------------------------
extern "C" void kernel_launch(void* const* d_in, const int* in_sizes, int n_in,
                              void* d_out, int out_size) {
    const float* f_in   = (const float*)d_in[0];
    const float* pos    = (const float*)d_in[1];
    const int*   batch  = (const int*)d_in[2];
    const int*   esrc   = (const int*)d_in[3];
    const int*   edst   = (const int*)d_in[4];
    const float* shifts = (const float*)d_in[5];
    const float* cell   = (const float*)d_in[6];
    const int wb = n_in - 10;
    const float* Wu0 = (const float*)d_in[wb + 0];
    const float* Wu1 = (const float*)d_in[wb + 1];
    const float* Wu2 = (const float*)d_in[wb + 2];
    const float* Wr0 = (const float*)d_in[wb + 3];
    const float* Wr1 = (const float*)d_in[wb + 4];
    const float* Wr2 = (const float*)d_in[wb + 5];
    const float* Wr3 = (const float*)d_in[wb + 6];
    const float* Wo0 = (const float*)d_in[wb + 7];
    const float* Wo1 = (const float*)d_in[wb + 8];
    const float* Wo2 = (const float*)d_in[wb + 9];

    const int N = in_sizes[0] / 288;
    const int E = in_sizes[3];

    static int smem_set = 0;
    const int smem_bytes = SM_TOTAL_F * 4;  // 46336
    if (!smem_set) {
        cudaFuncSetAttribute(edge_kernel, cudaFuncAttributeMaxDynamicSharedMemorySize, smem_bytes);
        smem_set = 1;
    }

    cst_kernel<<<1, 256>>>();
    const int n4 = N * 320;
    zero_kernel<<<(n4 + 255) / 256, 256>>>(n4);
    w3prep_kernel<<<(8 * 44 * 32 + 255) / 256, 256>>>(Wr3);
    up_kernel<<<(N + 3) / 4, 288>>>(f_in, Wu0, Wu1, Wu2, N);
    edge_kernel<<<(E + 31) / 32, 256, smem_bytes>>>(pos, batch, esrc, edst, shifts, cell,
                                                    Wr0, Wr1, Wr2, E);
    out_kernel<<<(N + 3) / 4, 288>>>(Wo0, Wo1, Wo2, (float*)d_out, N);
}

// round 11
// speedup vs baseline: 1.7019x; 1.1070x over previous
#include <cuda_runtime.h>
#include <math.h>

#define MAXN 10000

// ---------------- device scratch --------------------------------------------
__device__ float    g_cst;                     // CST_SILU
__device__ float    g_xs[MAXN * 288];          // up-projected node features, [node][slot 0..8][u 0..31]
__device__ float4   g_mid4[MAXN * 320];        // aggregated messages, 1280 f/node
__device__ unsigned g_w3f[8 * 44 * 32 * 2];    // Wr3/8 in tf32 mma-B fragment layout

// g_xs per-node layout (288 floats): slot*32 + u, slot = {x0, x1_0..2, x2_0..4}
// g_mid per-node layout (1280 floats):
//   A [0,128):      u*4 + s        s = path0,path1,path2,(pad)          (l0)
//   B [128,640):    128 + q*128 + u*4 + i   q=l1 path 0..3, i=x,y,z,(pad)
//   C [640,1152):   640 + r*128 + u*4 + c   r=l2 path 0..3, c=0..3
//   D [1152,1280):  1152 + u*4 + r          comp4 of l2 path r

typedef unsigned long long ull;

__device__ __forceinline__ float silu_f(float v) {
    return __fdividef(v, 1.0f + __expf(-v));
}

// packed fp32x2 fma helpers
#define FFMA2(d, a, b) asm("fma.rn.f32x2 %0, %1, %2, %3;" : "=l"(d) : "l"(a), "l"(b), "l"(d))

__device__ __forceinline__ float2 upk(ull v) {
    float2 r;
    asm("mov.b64 {%0, %1}, %2;" : "=f"(r.x), "=f"(r.y) : "l"(v));
    return r;
}
__device__ __forceinline__ ull dal(double d) { return __double_as_longlong(d); }

__device__ __forceinline__ unsigned tf32_rna(float x) {
    unsigned u;
    asm("cvt.rna.tf32.f32 %0, %1;" : "=r"(u) : "f"(x));
    return u;
}

__device__ __forceinline__ void mma_tf32(float& c0, float& c1, float& c2, float& c3,
                                         unsigned a0, unsigned a1, unsigned a2, unsigned a3,
                                         unsigned b0, unsigned b1) {
    asm volatile(
        "mma.sync.aligned.m16n8k8.row.col.f32.tf32.tf32.f32 "
        "{%0,%1,%2,%3},{%4,%5,%6,%7},{%8,%9},{%0,%1,%2,%3};"
        : "+f"(c0), "+f"(c1), "+f"(c2), "+f"(c3)
        : "r"(a0), "r"(a1), "r"(a2), "r"(a3), "r"(b0), "r"(b1));
}

// ---------------- CST_SILU via composite Simpson (double) -------------------
__global__ void cst_kernel() {
    __shared__ double red[256];
    const int t = threadIdx.x;
    const int NI = 4096;
    const double h = 24.0 / NI;
    double s = 0.0;
    for (int i = t; i <= NI; i += 256) {
        double xx = -12.0 + h * i;
        double sig = 1.0 / (1.0 + exp(-xx));
        double f = xx * sig;
        f = f * f * exp(-0.5 * xx * xx);
        double c = (i == 0 || i == NI) ? 1.0 : ((i & 1) ? 4.0 : 2.0);
        s += c * f;
    }
    red[t] = s;
    __syncthreads();
    for (int o = 128; o > 0; o >>= 1) {
        if (t < o) red[t] += red[t + o];
        __syncthreads();
    }
    if (t == 0) {
        double I = red[0] * h / 3.0 / 2.5066282746310005024;
        g_cst = (float)(1.0 / sqrt(I));
    }
}

// ---------------- zero mid ---------------------------------------------------
__global__ void zero_kernel(int n4) {
    int i = blockIdx.x * blockDim.x + threadIdx.x;
    if (i < n4) g_mid4[i] = make_float4(0.f, 0.f, 0.f, 0.f);
}

// ---------------- Wr3 -> tf32 B-fragment repack -----------------------------
__global__ void w3prep_kernel(const float* __restrict__ Wr3) {
    const int f = blockIdx.x * blockDim.x + threadIdx.x;  // 0 .. 8*44*32-1
    if (f >= 8 * 44 * 32) return;
    const int lane = f & 31;
    const int pair = f >> 5;
    const int nt = pair % 44;
    const int kt = pair / 44;
    const int tig = lane & 3;
    const int gid = lane >> 2;
    const int n = nt * 8 + gid;
    float w0 = Wr3[(kt * 8 + tig) * 352 + n] * 0.125f;
    float w1 = Wr3[(kt * 8 + tig + 4) * 352 + n] * 0.125f;
    g_w3f[f * 2 + 0] = tf32_rna(w0);
    g_w3f[f * 2 + 1] = tf32_rna(w1);
}

// ---------------- node up-projection (4 nodes/block, slot-major) ------------
__global__ void up_kernel(const float* __restrict__ f_in,
                          const float* __restrict__ Wu0,
                          const float* __restrict__ Wu1,
                          const float* __restrict__ Wu2, int N) {
    const int n0 = blockIdx.x * 4;
    const int t = threadIdx.x;  // 288
    __shared__ float fs[4][288];
    const int nmax = (N - n0 < 4) ? (N - n0) : 4;
#pragma unroll 1
    for (int j = t; j < nmax * 288; j += 288)
        fs[j / 288][j % 288] = f_in[n0 * 288 + j];
    __syncthreads();

    const int slot = t >> 5;
    const int w = t & 31;
    int i, off, d;
    const float* W;
    if (slot == 0)      { i = 0;        d = 1; off = 0;   W = Wu0; }
    else if (slot < 4)  { i = slot - 1; d = 3; off = 32;  W = Wu1; }
    else                { i = slot - 4; d = 5; off = 128; W = Wu2; }

    float acc[4] = {0.f, 0.f, 0.f, 0.f};
#pragma unroll 8
    for (int u = 0; u < 32; u++) {
        float wt = __ldg(W + u * 32 + w);
        const int fi = off + u * d + i;
#pragma unroll
        for (int e = 0; e < 4; e++)
            acc[e] = fmaf(fs[e][fi], wt, acc[e]);
    }
#pragma unroll
    for (int e = 0; e < nmax; e++)
        g_xs[(n0 + e) * 288 + slot * 32 + w] = acc[e] * 0.17677669529663687f;
}

// ---------------- radial MLP 64->64 layer (4 edges, duplicated layout) ------
__device__ __forceinline__ void mlp64d(const float* __restrict__ in2,
                                       float* __restrict__ out2,
                                       const float* __restrict__ W,
                                       int lane, float cst) {
    const int o0 = 2 * lane;
    ull accA[4] = {0ull,0ull,0ull,0ull};
    ull accB[4] = {0ull,0ull,0ull,0ull};
#pragma unroll 4
    for (int j2 = 0; j2 < 32; j2++) {
        ull w0 = dal(__ldg(reinterpret_cast<const double*>(W + (2*j2)   * 64 + o0)));
        ull w1 = dal(__ldg(reinterpret_cast<const double*>(W + (2*j2+1) * 64 + o0)));
#pragma unroll
        for (int e = 0; e < 4; e++) {
            ulonglong2 hp = *reinterpret_cast<const ulonglong2*>(in2 + e * 128 + 4 * j2);
            FFMA2(accA[e], w0, hp.x);
            FFMA2(accB[e], w1, hp.y);
        }
    }
#pragma unroll
    for (int e = 0; e < 4; e++) {
        float2 va = upk(accA[e]);
        float2 vb = upk(accB[e]);
        float v0 = silu_f((va.x + vb.x) * 0.125f) * cst;
        float v1 = silu_f((va.y + vb.y) * 0.125f) * cst;
        *reinterpret_cast<float4*>(out2 + e * 128 + 4 * lane) = make_float4(v0, v0, v1, v1);
    }
}

// smem layout (floats):
//   wsm  [0, 11584)        phase-2 radial weights: [32 edges][stride 362]
//        (phase-1 hA2/hB2 [0,8192) alias under wsm; dead before wsm written)
//   hfr  [11584, 13696)    A-fragments (NOT aliased): [etile 2][kt 8][reg 4][33]
//   geo  [13696, 13856)    per-warp edge state: [8 warps][4 edges][5] = ux,uy,uz,src,dst
#define SM_HA 0
#define SM_HB 4096
#define SM_HF 11584
#define SM_GEO 13696
#define WS_STRIDE 362
#define SM_TOTAL_F 13856

// ---------------- fused per-edge kernel (block = 32 edges) ------------------
__global__ void __launch_bounds__(256, 3) edge_kernel(
    const float* __restrict__ pos, const int* __restrict__ batch,
    const int* __restrict__ esrc, const int* __restrict__ edst,
    const float* __restrict__ shifts, const float* __restrict__ cell,
    const float* __restrict__ Wr0, const float* __restrict__ Wr1,
    const float* __restrict__ Wr2, int E)
{
    extern __shared__ float sm[];
    const int wid  = threadIdx.x >> 5;
    const int lane = threadIdx.x & 31;
    float* hA2 = sm + SM_HA + wid * 512;
    float* hB2 = sm + SM_HB + wid * 512;
    unsigned* hfr = reinterpret_cast<unsigned*>(sm + SM_HF);
    float* geo = sm + SM_GEO + wid * 20;   // [4 edges][5]
    float* wsm = sm;                       // aliases hA2/hB2 after phase 1

    const int base = blockIdx.x * 32 + wid * 4;   // this warp's 4 TP edges
    const int etile = wid >> 2;                   // 16-edge tile of this warp
    const float cst = g_cst;

    // ================= phase 1: geometry + radial MLP layers 1-3 ============
    {
        float Lr[4];
#pragma unroll
        for (int e = 0; e < 4; e++) {
            int ei = (base + e < E) ? base + e : E - 1;
            const int src = __ldg(esrc + ei);
            const int dst = __ldg(edst + ei);
            const float sx = __ldg(shifts + 3*ei), sy = __ldg(shifts + 3*ei+1), sz = __ldg(shifts + 3*ei+2);
            const float* Cc = cell + 9 * __ldg(batch + src);
            float vx = __ldg(pos+3*dst+0) - __ldg(pos+3*src+0) + sx*__ldg(Cc+0) + sy*__ldg(Cc+3) + sz*__ldg(Cc+6);
            float vy = __ldg(pos+3*dst+1) - __ldg(pos+3*src+1) + sx*__ldg(Cc+1) + sy*__ldg(Cc+4) + sz*__ldg(Cc+7);
            float vz = __ldg(pos+3*dst+2) - __ldg(pos+3*src+2) + sx*__ldg(Cc+2) + sy*__ldg(Cc+5) + sz*__ldg(Cc+8);
            float L = sqrtf(vx*vx + vy*vy + vz*vz);
            float inv = 1.0f / fmaxf(L, 1e-12f);
            Lr[e] = L;
            if (lane == 0) {
                geo[e * 5 + 0] = vx * inv;
                geo[e * 5 + 1] = vy * inv;
                geo[e * 5 + 2] = vz * inv;
                geo[e * 5 + 3] = __int_as_float(src);
                geo[e * 5 + 4] = __int_as_float(dst);
            }
        }

        // radial embedding, duplicated into hB2[e][0..15]
        const int k = lane & 7;
        const int e = lane >> 3;
        float Ls = Lr[0];
        if (e == 1) Ls = Lr[1]; else if (e == 2) Ls = Lr[2]; else if (e == 3) Ls = Lr[3];
        float tt = (Ls - (float)(k + 1) * (5.0f / 9.0f)) * 1.8f;
        float v = __expf(-tt * tt) * 2.525381361380527f;  // sqrt(8)/1.12
        *reinterpret_cast<float2*>(hB2 + e * 128 + 2 * k) = make_float2(v, v);
    }
    __syncwarp();

    const int o0 = 2 * lane;
    // layer 1: 8 -> 64 (hB2 -> hA2)
    {
        ull acc[4] = {0ull,0ull,0ull,0ull};
#pragma unroll
        for (int j2 = 0; j2 < 4; j2++) {
            ull w0 = dal(__ldg(reinterpret_cast<const double*>(Wr0 + (2*j2)   * 64 + o0)));
            ull w1 = dal(__ldg(reinterpret_cast<const double*>(Wr0 + (2*j2+1) * 64 + o0)));
#pragma unroll
            for (int e = 0; e < 4; e++) {
                ulonglong2 hp = *reinterpret_cast<const ulonglong2*>(hB2 + e * 128 + 4 * j2);
                FFMA2(acc[e], w0, hp.x);
                FFMA2(acc[e], w1, hp.y);
            }
        }
#pragma unroll
        for (int e = 0; e < 4; e++) {
            float2 v = upk(acc[e]);
            float v0 = silu_f(v.x * 0.35355339059327373f) * cst;
            float v1 = silu_f(v.y * 0.35355339059327373f) * cst;
            *reinterpret_cast<float4*>(hA2 + e * 128 + 4 * lane) = make_float4(v0, v0, v1, v1);
        }
    }
    __syncwarp();
    mlp64d(hA2, hB2, Wr1, lane, cst);   // layer 2
    __syncwarp();

    // layer 3: read hB2, write h into A-fragment layout (tf32 bits)
    {
        ull accA[4] = {0ull,0ull,0ull,0ull};
        ull accB[4] = {0ull,0ull,0ull,0ull};
#pragma unroll 4
        for (int j2 = 0; j2 < 32; j2++) {
            ull w0 = dal(__ldg(reinterpret_cast<const double*>(Wr2 + (2*j2)   * 64 + o0)));
            ull w1 = dal(__ldg(reinterpret_cast<const double*>(Wr2 + (2*j2+1) * 64 + o0)));
#pragma unroll
            for (int e = 0; e < 4; e++) {
                ulonglong2 hp = *reinterpret_cast<const ulonglong2*>(hB2 + e * 128 + 4 * j2);
                FFMA2(accA[e], w0, hp.x);
                FFMA2(accB[e], w1, hp.y);
            }
        }
#pragma unroll
        for (int e = 0; e < 4; e++) {
            float2 va = upk(accA[e]);
            float2 vb = upk(accB[e]);
            float v0 = silu_f((va.x + vb.x) * 0.125f) * cst;
            float v1 = silu_f((va.y + vb.y) * 0.125f) * cst;
            const int m = (wid & 3) * 4 + e;           // row within 16-edge tile
#pragma unroll
            for (int cc = 0; cc < 2; cc++) {
                int k  = 2 * lane + cc;
                float v = cc ? v1 : v0;
                int kt  = k >> 3;
                int kin = k & 7;
                int reg = ((m >= 8) ? 1 : 0) + ((kin >= 4) ? 2 : 0);
                int lp  = (m & 7) * 4 + (kin & 3);
                hfr[((etile * 8 + kt) * 4 + reg) * 33 + lp] = tf32_rna(v);
            }
        }
    }
    __syncthreads();   // hfr complete across etile; hA2/hB2 reads all done

    // ================= MMA pass: all 44 n-tiles =============================
    // (hfr is NOT aliased by wsm, so no extra barrier needed after afr load;
    //  wsm C-stores only alias the dead hA2/hB2 regions.)
    {
        unsigned afr[8][4];
#pragma unroll
        for (int kt = 0; kt < 8; kt++)
#pragma unroll
            for (int r = 0; r < 4; r++)
                afr[kt][r] = hfr[((etile * 8 + kt) * 4 + r) * 33 + lane];

        const int nch = wid & 3;
        const int gid = lane >> 2;
        const int tig = lane & 3;
        const uint2* Bf = reinterpret_cast<const uint2*>(g_w3f);
#pragma unroll 1
        for (int tt = 0; tt < 11; tt++) {
            const int nt = nch * 11 + tt;
            float c0 = 0.f, c1 = 0.f, c2 = 0.f, c3 = 0.f;
#pragma unroll
            for (int kt = 0; kt < 8; kt++) {
                uint2 b = __ldg(Bf + (kt * 44 + nt) * 32 + lane);
                mma_tf32(c0, c1, c2, c3, afr[kt][0], afr[kt][1], afr[kt][2], afr[kt][3], b.x, b.y);
            }
            const int col = nt * 8 + tig * 2;
            float* r0 = wsm + (etile * 16 + gid) * WS_STRIDE + col;
            *reinterpret_cast<float2*>(r0) = make_float2(c0, c1);
            *reinterpret_cast<float2*>(r0 + 8 * WS_STRIDE) = make_float2(c2, c3);
        }
    }
    __syncthreads();

    // ================= TP + coalesced vector atomics ========================
    const float A_  = 0.31622776601683794f;  // 1/sqrt(10)
    const float B_  = 0.18257418583505536f;  // 1/sqrt(30)
    const float AL  = 0.11952286093343936f;  // 1/sqrt(70)
    const float BE  = 0.20701966780270626f;  // sqrt(3/70)
    const float SQ3 = 1.7320508075688772f;
    const float SQ5 = 2.23606797749979f;

#pragma unroll 1
    for (int e = 0; e < 4; e++) {
        if (base + e >= E) break;
        const float ux = geo[e * 5 + 0];
        const float uy = geo[e * 5 + 1];
        const float uz = geo[e * 5 + 2];
        const int src = __float_as_int(geo[e * 5 + 3]);
        const int dst = __float_as_int(geo[e * 5 + 4]);

        const float s1x = SQ3 * ux, s1y = SQ3 * uy, s1z = SQ3 * uz;
        const float s20 = 3.872983346207417f * ux * uz;
        const float s21 = 3.872983346207417f * ux * uy;
        const float s22 = SQ5 * (uy*uy - 0.5f*(ux*ux + uz*uz));
        const float s23 = 3.872983346207417f * uy * uz;
        const float s24 = 1.9364916731037085f * (uz*uz - ux*ux);

        const float* wrow = wsm + (wid * 4 + e) * WS_STRIDE + lane;
        float w[11];
#pragma unroll
        for (int k = 0; k < 11; k++) w[k] = wrow[k * 32];

        const float* xp = g_xs + src * 288 + lane;
        const float x0  = __ldg(xp);
        const float x10 = __ldg(xp + 32),  x11 = __ldg(xp + 64),  x12 = __ldg(xp + 96);
        const float x20 = __ldg(xp + 128), x21 = __ldg(xp + 160), x22 = __ldg(xp + 192);
        const float x23 = __ldg(xp + 224), x24 = __ldg(xp + 256);

        // l0
        const float p0 = x0 * w[0];
        const float p1 = 0.5773502691896258f * (x10*s1x + x11*s1y + x12*s1z) * w[1];
        const float p2 = 0.4472135954999579f * (x20*s20 + x21*s21 + x22*s22 + x23*s23 + x24*s24) * w[2];

        // l1
        const float c3 = x0 * w[3];
        float p5x, p5y, p5z;
        {
            float wv = SQ3 * w[5];
            float B00 = -B_*s22 - A_*s24;
            float B01 =  A_*s21;
            float B02 =  A_*s20;
            float B11 =  2.f*B_*s22;
            float B12 =  A_*s23;
            float B22 = -B_*s22 + A_*s24;
            p5x = wv * (x10*B00 + x11*B01 + x12*B02);
            p5y = wv * (x10*B01 + x11*B11 + x12*B12);
            p5z = wv * (x10*B02 + x11*B12 + x12*B22);
        }
        float p6x, p6y, p6z;
        {
            float wv = SQ3 * w[6];
            p6x = wv * (A_*(x20*s1z + x21*s1y) - B_*x22*s1x - A_*x24*s1x);
            p6y = wv * (A_*(x21*s1x + x23*s1z) + 2.f*B_*x22*s1y);
            p6z = wv * (A_*(x20*s1x + x23*s1y + x24*s1z) - B_*x22*s1z);
        }

        // l2
        const float c7 = x0 * w[7];
        const float p70 = c7*s20, p71 = c7*s21, p72 = c7*s22, p73 = c7*s23, p74 = c7*s24;
        float p80, p81, p82, p83, p84;
        {
            float wv = SQ5 * w[8];
            p80 = wv * (A_*(x10*s1z + x12*s1x));
            p81 = wv * (A_*(x10*s1y + x11*s1x));
            p82 = wv * (B_*(-x10*s1x + 2.f*x11*s1y - x12*s1z));
            p83 = wv * (A_*(x11*s1z + x12*s1y));
            p84 = wv * (A_*(-x10*s1x + x12*s1z));
        }
        const float p90 = x20*w[9], p91 = x21*w[9], p92 = x22*w[9], p93 = x23*w[9], p94 = x24*w[9];
        float pa0, pa1, pa2, pa3, pa4;
        {
            float wv = SQ5 * w[10];
            pa0 = wv * (x20*(2.f*AL*s22) + x21*(-BE*s23) + x22*(2.f*AL*s20) + x23*(-BE*s21));
            pa1 = wv * (x20*(-BE*s23) + x21*(-AL*s22 + BE*s24) + x22*(-AL*s21) + x23*(-BE*s20) + x24*(BE*s21));
            pa2 = wv * (x20*(2.f*AL*s20) + x21*(-AL*s21) + x22*(-2.f*AL*s22) + x23*(-AL*s23) + x24*(2.f*AL*s24));
            pa3 = wv * (x20*(-BE*s21) + x21*(-BE*s20) + x22*(-AL*s23) + x23*(-AL*s22 - BE*s24) + x24*(-BE*s23));
            pa4 = wv * (x21*(BE*s21) + x22*(2.f*AL*s24) + x23*(-BE*s23) + x24*(2.f*AL*s22));
        }

        float4* mb = reinterpret_cast<float4*>(reinterpret_cast<float*>(g_mid4) + dst * 1280) + lane;
        atomicAdd(mb,       make_float4(p0, p1, p2, 0.f));          // A
        atomicAdd(mb + 32,  make_float4(c3*s1x, c3*s1y, c3*s1z, 0.f));
        atomicAdd(mb + 64,  make_float4(x10*w[4], x11*w[4], x12*w[4], 0.f));
        atomicAdd(mb + 96,  make_float4(p5x, p5y, p5z, 0.f));
        atomicAdd(mb + 128, make_float4(p6x, p6y, p6z, 0.f));
        atomicAdd(mb + 160, make_float4(p70, p71, p72, p73));
        atomicAdd(mb + 192, make_float4(p80, p81, p82, p83));
        atomicAdd(mb + 224, make_float4(p90, p91, p92, p93));
        atomicAdd(mb + 256, make_float4(pa0, pa1, pa2, pa3));
        atomicAdd(mb + 288, make_float4(p74, p84, p94, pa4));
    }
}

// ---------------- per-node output projection (4 nodes/block, slot-major) ----
__global__ void out_kernel(const float* __restrict__ Wo0,
                           const float* __restrict__ Wo1,
                           const float* __restrict__ Wo2,
                           float* __restrict__ out, int N) {
    const int n0 = blockIdx.x * 4;
    const int t = threadIdx.x;  // 288
    __shared__ float ms[4][1280];
    const int nmax = (N - n0 < 4) ? (N - n0) : 4;
#pragma unroll 1
    for (int j = t; j < nmax * 320; j += 288) {
        const int node = j / 320, jj = j % 320;
        reinterpret_cast<float4*>(ms[node])[jj] = g_mid4[(n0 + node) * 320 + jj];
    }
    __syncthreads();

    const int slot = t >> 5;
    const int w = t & 31;
    float acc[4] = {0.f, 0.f, 0.f, 0.f};
    int off, d, i;
    float scale;

    if (slot == 0) {
        off = 0; d = 1; i = 0;
        scale = 0.006378879538497859f;   // 1/(sqrt(96)*16)
#pragma unroll
        for (int s = 0; s < 3; s++)
#pragma unroll 8
            for (int u = 0; u < 32; u++) {
                float wt = __ldg(Wo0 + (s * 32 + u) * 32 + w);
                const int mi = u * 4 + s;
#pragma unroll
                for (int e = 0; e < 4; e++)
                    acc[e] = fmaf(ms[e][mi], wt, acc[e]);
            }
    } else if (slot < 4) {
        off = 32; d = 3; i = slot - 1;
        scale = 0.005524271728019903f;   // 1/(sqrt(128)*16)
#pragma unroll
        for (int q = 0; q < 4; q++)
#pragma unroll 8
            for (int u = 0; u < 32; u++) {
                float wt = __ldg(Wo1 + (q * 32 + u) * 32 + w);
                const int mi = 128 + q * 128 + u * 4 + i;
#pragma unroll
                for (int e = 0; e < 4; e++)
                    acc[e] = fmaf(ms[e][mi], wt, acc[e]);
            }
    } else {
        off = 128; d = 5; i = slot - 4;
        scale = 0.005524271728019903f;
        if (i < 4) {
#pragma unroll
            for (int r = 0; r < 4; r++)
#pragma unroll 8
                for (int u = 0; u < 32; u++) {
                    float wt = __ldg(Wo2 + (r * 32 + u) * 32 + w);
                    const int mi = 640 + r * 128 + u * 4 + i;
#pragma unroll
                    for (int e = 0; e < 4; e++)
                        acc[e] = fmaf(ms[e][mi], wt, acc[e]);
                }
        } else {
#pragma unroll
            for (int r = 0; r < 4; r++)
#pragma unroll 8
                for (int u = 0; u < 32; u++) {
                    float wt = __ldg(Wo2 + (r * 32 + u) * 32 + w);
                    const int mi = 1152 + u * 4 + r;
#pragma unroll
                    for (int e = 0; e < 4; e++)
                        acc[e] = fmaf(ms[e][mi], wt, acc[e]);
                }
        }
    }

#pragma unroll
    for (int e = 0; e < nmax; e++)
        out[(n0 + e) * 288 + off + w * d + i] = acc[e] * scale;
}

// ---------------- launch -----------------------------------------------------
extern "C" void kernel_launch(void* const* d_in, const int* in_sizes, int n_in,
                              void* d_out, int out_size) {
    const float* f_in   = (const float*)d_in[0];
    const float* pos    = (const float*)d_in[1];
    const int*   batch  = (const int*)d_in[2];
    const int*   esrc   = (const int*)d_in[3];
    const int*   edst   = (const int*)d_in[4];
    const float* shifts = (const float*)d_in[5];
    const float* cell   = (const float*)d_in[6];
    const int wb = n_in - 10;
    const float* Wu0 = (const float*)d_in[wb + 0];
    const float* Wu1 = (const float*)d_in[wb + 1];
    const float* Wu2 = (const float*)d_in[wb + 2];
    const float* Wr0 = (const float*)d_in[wb + 3];
    const float* Wr1 = (const float*)d_in[wb + 4];
    const float* Wr2 = (const float*)d_in[wb + 5];
    const float* Wr3 = (const float*)d_in[wb + 6];
    const float* Wo0 = (const float*)d_in[wb + 7];
    const float* Wo1 = (const float*)d_in[wb + 8];
    const float* Wo2 = (const float*)d_in[wb + 9];

    const int N = in_sizes[0] / 288;
    const int E = in_sizes[3];

    static int smem_set = 0;
    const int smem_bytes = SM_TOTAL_F * 4;  // 55424
    if (!smem_set) {
        cudaFuncSetAttribute(edge_kernel, cudaFuncAttributeMaxDynamicSharedMemorySize, smem_bytes);
        smem_set = 1;
    }

    cst_kernel<<<1, 256>>>();
    const int n4 = N * 320;
    zero_kernel<<<(n4 + 255) / 256, 256>>>(n4);
    w3prep_kernel<<<(8 * 44 * 32 + 255) / 256, 256>>>(Wr3);
    up_kernel<<<(N + 3) / 4, 288>>>(f_in, Wu0, Wu1, Wu2, N);
    edge_kernel<<<(E + 31) / 32, 256, smem_bytes>>>(pos, batch, esrc, edst, shifts, cell,
                                                    Wr0, Wr1, Wr2, E);
    out_kernel<<<(N + 3) / 4, 288>>>(Wo0, Wo1, Wo2, (float*)d_out, N);
}

// round 12
// speedup vs baseline: 1.7444x; 1.0250x over previous
#include <cuda_runtime.h>
#include <math.h>

#define MAXN 10000

// ---------------- device scratch --------------------------------------------
__device__ float    g_cst;                     // CST_SILU
__device__ float    g_xs[MAXN * 288];          // up-projected node features, [node][slot 0..8][u 0..31]
__device__ float4   g_mid4[MAXN * 320];        // aggregated messages, 1280 f/node
__device__ unsigned g_w3f[8 * 44 * 32 * 2];    // Wr3/8 in tf32 mma-B fragment layout

// g_xs per-node layout (288 floats): slot*32 + u, slot = {x0, x1_0..2, x2_0..4}
// g_mid per-node layout (1280 floats):
//   A [0,128):      u*4 + s        s = path0,path1,path2,(pad)          (l0)
//   B [128,640):    128 + q*128 + u*4 + i   q=l1 path 0..3, i=x,y,z,(pad)
//   C [640,1152):   640 + r*128 + u*4 + c   r=l2 path 0..3, c=0..3
//   D [1152,1280):  1152 + u*4 + r          comp4 of l2 path r

typedef unsigned long long ull;

__device__ __forceinline__ float silu_f(float v) {
    return __fdividef(v, 1.0f + __expf(-v));
}

// packed fp32x2 fma helpers
#define FFMA2(d, a, b) asm("fma.rn.f32x2 %0, %1, %2, %3;" : "=l"(d) : "l"(a), "l"(b), "l"(d))

__device__ __forceinline__ float2 upk(ull v) {
    float2 r;
    asm("mov.b64 {%0, %1}, %2;" : "=f"(r.x), "=f"(r.y) : "l"(v));
    return r;
}
__device__ __forceinline__ ull dal(double d) { return __double_as_longlong(d); }

__device__ __forceinline__ unsigned tf32_rna(float x) {
    unsigned u;
    asm("cvt.rna.tf32.f32 %0, %1;" : "=r"(u) : "f"(x));
    return u;
}

__device__ __forceinline__ void mma_tf32(float& c0, float& c1, float& c2, float& c3,
                                         unsigned a0, unsigned a1, unsigned a2, unsigned a3,
                                         unsigned b0, unsigned b1) {
    asm volatile(
        "mma.sync.aligned.m16n8k8.row.col.f32.tf32.tf32.f32 "
        "{%0,%1,%2,%3},{%4,%5,%6,%7},{%8,%9},{%0,%1,%2,%3};"
        : "+f"(c0), "+f"(c1), "+f"(c2), "+f"(c3)
        : "r"(a0), "r"(a1), "r"(a2), "r"(a3), "r"(b0), "r"(b1));
}

// ---------------- fused prep: cst (block 0) + w3prep (1..44) + zero (rest) --
__global__ void prep_kernel(const float* __restrict__ Wr3, int n4zero) {
    const int b = blockIdx.x;
    const int t = threadIdx.x;  // 256

    if (b == 0) {
        // CST_SILU via composite Simpson (double)
        __shared__ double red[256];
        const int NI = 4096;
        const double h = 24.0 / NI;
        double s = 0.0;
        for (int i = t; i <= NI; i += 256) {
            double xx = -12.0 + h * i;
            double sig = 1.0 / (1.0 + exp(-xx));
            double f = xx * sig;
            f = f * f * exp(-0.5 * xx * xx);
            double c = (i == 0 || i == NI) ? 1.0 : ((i & 1) ? 4.0 : 2.0);
            s += c * f;
        }
        red[t] = s;
        __syncthreads();
        for (int o = 128; o > 0; o >>= 1) {
            if (t < o) red[t] += red[t + o];
            __syncthreads();
        }
        if (t == 0) {
            double I = red[0] * h / 3.0 / 2.5066282746310005024;
            g_cst = (float)(1.0 / sqrt(I));
        }
    } else if (b <= 44) {
        // Wr3 -> tf32 B-fragment repack: f in [0, 8*44*32)
        const int f = (b - 1) * 256 + t;
        if (f < 8 * 44 * 32) {
            const int lane = f & 31;
            const int pair = f >> 5;
            const int nt = pair % 44;
            const int kt = pair / 44;
            const int tig = lane & 3;
            const int gid = lane >> 2;
            const int n = nt * 8 + gid;
            float w0 = Wr3[(kt * 8 + tig) * 352 + n] * 0.125f;
            float w1 = Wr3[(kt * 8 + tig + 4) * 352 + n] * 0.125f;
            g_w3f[f * 2 + 0] = tf32_rna(w0);
            g_w3f[f * 2 + 1] = tf32_rna(w1);
        }
    } else {
        const int i = (b - 45) * 256 + t;
        if (i < n4zero) g_mid4[i] = make_float4(0.f, 0.f, 0.f, 0.f);
    }
}

// ---------------- node up-projection (8 nodes/block, slot-major) ------------
__global__ void up_kernel(const float* __restrict__ f_in,
                          const float* __restrict__ Wu0,
                          const float* __restrict__ Wu1,
                          const float* __restrict__ Wu2, int N) {
    const int n0 = blockIdx.x * 8;
    const int t = threadIdx.x;  // 288
    __shared__ float fs[8][288];
    const int nmax = (N - n0 < 8) ? (N - n0) : 8;
#pragma unroll 1
    for (int j = t; j < nmax * 288; j += 288)
        fs[j / 288][j % 288] = f_in[n0 * 288 + j];
    __syncthreads();

    const int slot = t >> 5;
    const int w = t & 31;
    int i, off, d;
    const float* W;
    if (slot == 0)      { i = 0;        d = 1; off = 0;   W = Wu0; }
    else if (slot < 4)  { i = slot - 1; d = 3; off = 32;  W = Wu1; }
    else                { i = slot - 4; d = 5; off = 128; W = Wu2; }

    float acc[8] = {0.f, 0.f, 0.f, 0.f, 0.f, 0.f, 0.f, 0.f};
#pragma unroll 4
    for (int u = 0; u < 32; u++) {
        float wt = __ldg(W + u * 32 + w);
        const int fi = off + u * d + i;
#pragma unroll
        for (int e = 0; e < 8; e++)
            acc[e] = fmaf(fs[e][fi], wt, acc[e]);
    }
#pragma unroll
    for (int e = 0; e < nmax; e++)
        g_xs[(n0 + e) * 288 + slot * 32 + w] = acc[e] * 0.17677669529663687f;
}

// ---------------- radial MLP 64->64 layer (4 edges, duplicated layout) ------
__device__ __forceinline__ void mlp64d(const float* __restrict__ in2,
                                       float* __restrict__ out2,
                                       const float* __restrict__ W,
                                       int lane, float cst) {
    const int o0 = 2 * lane;
    ull accA[4] = {0ull,0ull,0ull,0ull};
    ull accB[4] = {0ull,0ull,0ull,0ull};
#pragma unroll 4
    for (int j2 = 0; j2 < 32; j2++) {
        ull w0 = dal(__ldg(reinterpret_cast<const double*>(W + (2*j2)   * 64 + o0)));
        ull w1 = dal(__ldg(reinterpret_cast<const double*>(W + (2*j2+1) * 64 + o0)));
#pragma unroll
        for (int e = 0; e < 4; e++) {
            ulonglong2 hp = *reinterpret_cast<const ulonglong2*>(in2 + e * 128 + 4 * j2);
            FFMA2(accA[e], w0, hp.x);
            FFMA2(accB[e], w1, hp.y);
        }
    }
#pragma unroll
    for (int e = 0; e < 4; e++) {
        float2 va = upk(accA[e]);
        float2 vb = upk(accB[e]);
        float v0 = silu_f((va.x + vb.x) * 0.125f) * cst;
        float v1 = silu_f((va.y + vb.y) * 0.125f) * cst;
        *reinterpret_cast<float4*>(out2 + e * 128 + 4 * lane) = make_float4(v0, v0, v1, v1);
    }
}

// smem layout (floats):
//   wsm  [0, 11584)        phase-2 radial weights: [32 edges][stride 362]
//        (phase-1 hA2/hB2 [0,8192) alias under wsm; dead before wsm written)
//   hfr  [11584, 13696)    A-fragments (NOT aliased): [etile 2][kt 8][reg 4][33]
//   geo  [13696, 13856)    per-warp edge state: [8 warps][4 edges][5] = ux,uy,uz,src,dst
#define SM_HA 0
#define SM_HB 4096
#define SM_HF 11584
#define SM_GEO 13696
#define WS_STRIDE 362
#define SM_TOTAL_F 13856

// ---------------- fused per-edge kernel (block = 32 edges) ------------------
__global__ void __launch_bounds__(256, 3) edge_kernel(
    const float* __restrict__ pos, const int* __restrict__ batch,
    const int* __restrict__ esrc, const int* __restrict__ edst,
    const float* __restrict__ shifts, const float* __restrict__ cell,
    const float* __restrict__ Wr0, const float* __restrict__ Wr1,
    const float* __restrict__ Wr2, int E)
{
    extern __shared__ float sm[];
    const int wid  = threadIdx.x >> 5;
    const int lane = threadIdx.x & 31;
    float* hA2 = sm + SM_HA + wid * 512;
    float* hB2 = sm + SM_HB + wid * 512;
    unsigned* hfr = reinterpret_cast<unsigned*>(sm + SM_HF);
    float* geo = sm + SM_GEO + wid * 20;   // [4 edges][5]
    float* wsm = sm;                       // aliases hA2/hB2 after phase 1

    const int base = blockIdx.x * 32 + wid * 4;   // this warp's 4 TP edges
    const int etile = wid >> 2;                   // 16-edge tile of this warp
    const float cst = g_cst;

    // ================= phase 1: geometry + radial MLP layers 1-3 ============
    {
        float Lr[4];
#pragma unroll
        for (int e = 0; e < 4; e++) {
            int ei = (base + e < E) ? base + e : E - 1;
            const int src = __ldg(esrc + ei);
            const int dst = __ldg(edst + ei);
            const float sx = __ldg(shifts + 3*ei), sy = __ldg(shifts + 3*ei+1), sz = __ldg(shifts + 3*ei+2);
            const float* Cc = cell + 9 * __ldg(batch + src);
            float vx = __ldg(pos+3*dst+0) - __ldg(pos+3*src+0) + sx*__ldg(Cc+0) + sy*__ldg(Cc+3) + sz*__ldg(Cc+6);
            float vy = __ldg(pos+3*dst+1) - __ldg(pos+3*src+1) + sx*__ldg(Cc+1) + sy*__ldg(Cc+4) + sz*__ldg(Cc+7);
            float vz = __ldg(pos+3*dst+2) - __ldg(pos+3*src+2) + sx*__ldg(Cc+2) + sy*__ldg(Cc+5) + sz*__ldg(Cc+8);
            float L = sqrtf(vx*vx + vy*vy + vz*vz);
            float inv = 1.0f / fmaxf(L, 1e-12f);
            Lr[e] = L;
            if (lane == 0) {
                geo[e * 5 + 0] = vx * inv;
                geo[e * 5 + 1] = vy * inv;
                geo[e * 5 + 2] = vz * inv;
                geo[e * 5 + 3] = __int_as_float(src);
                geo[e * 5 + 4] = __int_as_float(dst);
            }
        }

        // radial embedding, duplicated into hB2[e][0..15]
        const int k = lane & 7;
        const int e = lane >> 3;
        float Ls = Lr[0];
        if (e == 1) Ls = Lr[1]; else if (e == 2) Ls = Lr[2]; else if (e == 3) Ls = Lr[3];
        float tt = (Ls - (float)(k + 1) * (5.0f / 9.0f)) * 1.8f;
        float v = __expf(-tt * tt) * 2.525381361380527f;  // sqrt(8)/1.12
        *reinterpret_cast<float2*>(hB2 + e * 128 + 2 * k) = make_float2(v, v);
    }
    __syncwarp();

    const int o0 = 2 * lane;
    // layer 1: 8 -> 64 (hB2 -> hA2)
    {
        ull acc[4] = {0ull,0ull,0ull,0ull};
#pragma unroll
        for (int j2 = 0; j2 < 4; j2++) {
            ull w0 = dal(__ldg(reinterpret_cast<const double*>(Wr0 + (2*j2)   * 64 + o0)));
            ull w1 = dal(__ldg(reinterpret_cast<const double*>(Wr0 + (2*j2+1) * 64 + o0)));
#pragma unroll
            for (int e = 0; e < 4; e++) {
                ulonglong2 hp = *reinterpret_cast<const ulonglong2*>(hB2 + e * 128 + 4 * j2);
                FFMA2(acc[e], w0, hp.x);
                FFMA2(acc[e], w1, hp.y);
            }
        }
#pragma unroll
        for (int e = 0; e < 4; e++) {
            float2 v = upk(acc[e]);
            float v0 = silu_f(v.x * 0.35355339059327373f) * cst;
            float v1 = silu_f(v.y * 0.35355339059327373f) * cst;
            *reinterpret_cast<float4*>(hA2 + e * 128 + 4 * lane) = make_float4(v0, v0, v1, v1);
        }
    }
    __syncwarp();
    mlp64d(hA2, hB2, Wr1, lane, cst);   // layer 2
    __syncwarp();

    // layer 3: read hB2, write h into A-fragment layout (tf32 bits)
    {
        ull accA[4] = {0ull,0ull,0ull,0ull};
        ull accB[4] = {0ull,0ull,0ull,0ull};
#pragma unroll 4
        for (int j2 = 0; j2 < 32; j2++) {
            ull w0 = dal(__ldg(reinterpret_cast<const double*>(Wr2 + (2*j2)   * 64 + o0)));
            ull w1 = dal(__ldg(reinterpret_cast<const double*>(Wr2 + (2*j2+1) * 64 + o0)));
#pragma unroll
            for (int e = 0; e < 4; e++) {
                ulonglong2 hp = *reinterpret_cast<const ulonglong2*>(hB2 + e * 128 + 4 * j2);
                FFMA2(accA[e], w0, hp.x);
                FFMA2(accB[e], w1, hp.y);
            }
        }
#pragma unroll
        for (int e = 0; e < 4; e++) {
            float2 va = upk(accA[e]);
            float2 vb = upk(accB[e]);
            float v0 = silu_f((va.x + vb.x) * 0.125f) * cst;
            float v1 = silu_f((va.y + vb.y) * 0.125f) * cst;
            const int m = (wid & 3) * 4 + e;           // row within 16-edge tile
#pragma unroll
            for (int cc = 0; cc < 2; cc++) {
                int k  = 2 * lane + cc;
                float v = cc ? v1 : v0;
                int kt  = k >> 3;
                int kin = k & 7;
                int reg = ((m >= 8) ? 1 : 0) + ((kin >= 4) ? 2 : 0);
                int lp  = (m & 7) * 4 + (kin & 3);
                hfr[((etile * 8 + kt) * 4 + reg) * 33 + lp] = tf32_rna(v);
            }
        }
    }
    __syncthreads();   // hfr complete across etile; hA2/hB2 reads all done

    // ================= MMA pass: all 44 n-tiles =============================
    {
        unsigned afr[8][4];
#pragma unroll
        for (int kt = 0; kt < 8; kt++)
#pragma unroll
            for (int r = 0; r < 4; r++)
                afr[kt][r] = hfr[((etile * 8 + kt) * 4 + r) * 33 + lane];

        const int nch = wid & 3;
        const int gid = lane >> 2;
        const int tig = lane & 3;
        const uint2* Bf = reinterpret_cast<const uint2*>(g_w3f);
#pragma unroll 1
        for (int tt = 0; tt < 11; tt++) {
            const int nt = nch * 11 + tt;
            float c0 = 0.f, c1 = 0.f, c2 = 0.f, c3 = 0.f;
#pragma unroll
            for (int kt = 0; kt < 8; kt++) {
                uint2 b = __ldg(Bf + (kt * 44 + nt) * 32 + lane);
                mma_tf32(c0, c1, c2, c3, afr[kt][0], afr[kt][1], afr[kt][2], afr[kt][3], b.x, b.y);
            }
            const int col = nt * 8 + tig * 2;
            float* r0 = wsm + (etile * 16 + gid) * WS_STRIDE + col;
            *reinterpret_cast<float2*>(r0) = make_float2(c0, c1);
            *reinterpret_cast<float2*>(r0 + 8 * WS_STRIDE) = make_float2(c2, c3);
        }
    }
    __syncthreads();

    // ================= TP + coalesced vector atomics ========================
    const float A_  = 0.31622776601683794f;  // 1/sqrt(10)
    const float B_  = 0.18257418583505536f;  // 1/sqrt(30)
    const float AL  = 0.11952286093343936f;  // 1/sqrt(70)
    const float BE  = 0.20701966780270626f;  // sqrt(3/70)
    const float SQ3 = 1.7320508075688772f;
    const float SQ5 = 2.23606797749979f;

#pragma unroll 1
    for (int e = 0; e < 4; e++) {
        if (base + e >= E) break;
        const float ux = geo[e * 5 + 0];
        const float uy = geo[e * 5 + 1];
        const float uz = geo[e * 5 + 2];
        const int src = __float_as_int(geo[e * 5 + 3]);
        const int dst = __float_as_int(geo[e * 5 + 4]);

        const float s1x = SQ3 * ux, s1y = SQ3 * uy, s1z = SQ3 * uz;
        const float s20 = 3.872983346207417f * ux * uz;
        const float s21 = 3.872983346207417f * ux * uy;
        const float s22 = SQ5 * (uy*uy - 0.5f*(ux*ux + uz*uz));
        const float s23 = 3.872983346207417f * uy * uz;
        const float s24 = 1.9364916731037085f * (uz*uz - ux*ux);

        const float* wrow = wsm + (wid * 4 + e) * WS_STRIDE + lane;
        float w[11];
#pragma unroll
        for (int k = 0; k < 11; k++) w[k] = wrow[k * 32];

        const float* xp = g_xs + src * 288 + lane;
        const float x0  = __ldg(xp);
        const float x10 = __ldg(xp + 32),  x11 = __ldg(xp + 64),  x12 = __ldg(xp + 96);
        const float x20 = __ldg(xp + 128), x21 = __ldg(xp + 160), x22 = __ldg(xp + 192);
        const float x23 = __ldg(xp + 224), x24 = __ldg(xp + 256);

        // l0
        const float p0 = x0 * w[0];
        const float p1 = 0.5773502691896258f * (x10*s1x + x11*s1y + x12*s1z) * w[1];
        const float p2 = 0.4472135954999579f * (x20*s20 + x21*s21 + x22*s22 + x23*s23 + x24*s24) * w[2];

        // l1
        const float c3 = x0 * w[3];
        float p5x, p5y, p5z;
        {
            float wv = SQ3 * w[5];
            float B00 = -B_*s22 - A_*s24;
            float B01 =  A_*s21;
            float B02 =  A_*s20;
            float B11 =  2.f*B_*s22;
            float B12 =  A_*s23;
            float B22 = -B_*s22 + A_*s24;
            p5x = wv * (x10*B00 + x11*B01 + x12*B02);
            p5y = wv * (x10*B01 + x11*B11 + x12*B12);
            p5z = wv * (x10*B02 + x11*B12 + x12*B22);
        }
        float p6x, p6y, p6z;
        {
            float wv = SQ3 * w[6];
            p6x = wv * (A_*(x20*s1z + x21*s1y) - B_*x22*s1x - A_*x24*s1x);
            p6y = wv * (A_*(x21*s1x + x23*s1z) + 2.f*B_*x22*s1y);
            p6z = wv * (A_*(x20*s1x + x23*s1y + x24*s1z) - B_*x22*s1z);
        }

        // l2
        const float c7 = x0 * w[7];
        const float p70 = c7*s20, p71 = c7*s21, p72 = c7*s22, p73 = c7*s23, p74 = c7*s24;
        float p80, p81, p82, p83, p84;
        {
            float wv = SQ5 * w[8];
            p80 = wv * (A_*(x10*s1z + x12*s1x));
            p81 = wv * (A_*(x10*s1y + x11*s1x));
            p82 = wv * (B_*(-x10*s1x + 2.f*x11*s1y - x12*s1z));
            p83 = wv * (A_*(x11*s1z + x12*s1y));
            p84 = wv * (A_*(-x10*s1x + x12*s1z));
        }
        const float p90 = x20*w[9], p91 = x21*w[9], p92 = x22*w[9], p93 = x23*w[9], p94 = x24*w[9];
        float pa0, pa1, pa2, pa3, pa4;
        {
            float wv = SQ5 * w[10];
            pa0 = wv * (x20*(2.f*AL*s22) + x21*(-BE*s23) + x22*(2.f*AL*s20) + x23*(-BE*s21));
            pa1 = wv * (x20*(-BE*s23) + x21*(-AL*s22 + BE*s24) + x22*(-AL*s21) + x23*(-BE*s20) + x24*(BE*s21));
            pa2 = wv * (x20*(2.f*AL*s20) + x21*(-AL*s21) + x22*(-2.f*AL*s22) + x23*(-AL*s23) + x24*(2.f*AL*s24));
            pa3 = wv * (x20*(-BE*s21) + x21*(-BE*s20) + x22*(-AL*s23) + x23*(-AL*s22 - BE*s24) + x24*(-BE*s23));
            pa4 = wv * (x21*(BE*s21) + x22*(2.f*AL*s24) + x23*(-BE*s23) + x24*(2.f*AL*s22));
        }

        float4* mb = reinterpret_cast<float4*>(reinterpret_cast<float*>(g_mid4) + dst * 1280) + lane;
        atomicAdd(mb,       make_float4(p0, p1, p2, 0.f));          // A
        atomicAdd(mb + 32,  make_float4(c3*s1x, c3*s1y, c3*s1z, 0.f));
        atomicAdd(mb + 64,  make_float4(x10*w[4], x11*w[4], x12*w[4], 0.f));
        atomicAdd(mb + 96,  make_float4(p5x, p5y, p5z, 0.f));
        atomicAdd(mb + 128, make_float4(p6x, p6y, p6z, 0.f));
        atomicAdd(mb + 160, make_float4(p70, p71, p72, p73));
        atomicAdd(mb + 192, make_float4(p80, p81, p82, p83));
        atomicAdd(mb + 224, make_float4(p90, p91, p92, p93));
        atomicAdd(mb + 256, make_float4(pa0, pa1, pa2, pa3));
        atomicAdd(mb + 288, make_float4(p74, p84, p94, pa4));
    }
}

// ---------------- per-node output projection (8 nodes/block, slot-major) ----
__global__ void out_kernel(const float* __restrict__ Wo0,
                           const float* __restrict__ Wo1,
                           const float* __restrict__ Wo2,
                           float* __restrict__ out, int N) {
    const int n0 = blockIdx.x * 8;
    const int t = threadIdx.x;  // 288
    __shared__ float ms[8][1280];
    const int nmax = (N - n0 < 8) ? (N - n0) : 8;
#pragma unroll 1
    for (int j = t; j < nmax * 320; j += 288) {
        const int node = j / 320, jj = j % 320;
        reinterpret_cast<float4*>(ms[node])[jj] = g_mid4[(n0 + node) * 320 + jj];
    }
    __syncthreads();

    const int slot = t >> 5;
    const int w = t & 31;
    float acc[8] = {0.f, 0.f, 0.f, 0.f, 0.f, 0.f, 0.f, 0.f};
    int off, d, i;
    float scale;

    if (slot == 0) {
        off = 0; d = 1; i = 0;
        scale = 0.006378879538497859f;   // 1/(sqrt(96)*16)
#pragma unroll
        for (int s = 0; s < 3; s++)
#pragma unroll 4
            for (int u = 0; u < 32; u++) {
                float wt = __ldg(Wo0 + (s * 32 + u) * 32 + w);
                const int mi = u * 4 + s;
#pragma unroll
                for (int e = 0; e < 8; e++)
                    acc[e] = fmaf(ms[e][mi], wt, acc[e]);
            }
    } else if (slot < 4) {
        off = 32; d = 3; i = slot - 1;
        scale = 0.005524271728019903f;   // 1/(sqrt(128)*16)
#pragma unroll
        for (int q = 0; q < 4; q++)
#pragma unroll 4
            for (int u = 0; u < 32; u++) {
                float wt = __ldg(Wo1 + (q * 32 + u) * 32 + w);
                const int mi = 128 + q * 128 + u * 4 + i;
#pragma unroll
                for (int e = 0; e < 8; e++)
                    acc[e] = fmaf(ms[e][mi], wt, acc[e]);
            }
    } else {
        off = 128; d = 5; i = slot - 4;
        scale = 0.005524271728019903f;
        if (i < 4) {
#pragma unroll
            for (int r = 0; r < 4; r++)
#pragma unroll 4
                for (int u = 0; u < 32; u++) {
                    float wt = __ldg(Wo2 + (r * 32 + u) * 32 + w);
                    const int mi = 640 + r * 128 + u * 4 + i;
#pragma unroll
                    for (int e = 0; e < 8; e++)
                        acc[e] = fmaf(ms[e][mi], wt, acc[e]);
                }
        } else {
#pragma unroll
            for (int r = 0; r < 4; r++)
#pragma unroll 4
                for (int u = 0; u < 32; u++) {
                    float wt = __ldg(Wo2 + (r * 32 + u) * 32 + w);
                    const int mi = 1152 + u * 4 + r;
#pragma unroll
                    for (int e = 0; e < 8; e++)
                        acc[e] = fmaf(ms[e][mi], wt, acc[e]);
                }
        }
    }

#pragma unroll
    for (int e = 0; e < nmax; e++)
        out[(n0 + e) * 288 + off + w * d + i] = acc[e] * scale;
}

// ---------------- launch -----------------------------------------------------
extern "C" void kernel_launch(void* const* d_in, const int* in_sizes, int n_in,
                              void* d_out, int out_size) {
    const float* f_in   = (const float*)d_in[0];
    const float* pos    = (const float*)d_in[1];
    const int*   batch  = (const int*)d_in[2];
    const int*   esrc   = (const int*)d_in[3];
    const int*   edst   = (const int*)d_in[4];
    const float* shifts = (const float*)d_in[5];
    const float* cell   = (const float*)d_in[6];
    const int wb = n_in - 10;
    const float* Wu0 = (const float*)d_in[wb + 0];
    const float* Wu1 = (const float*)d_in[wb + 1];
    const float* Wu2 = (const float*)d_in[wb + 2];
    const float* Wr0 = (const float*)d_in[wb + 3];
    const float* Wr1 = (const float*)d_in[wb + 4];
    const float* Wr2 = (const float*)d_in[wb + 5];
    const float* Wr3 = (const float*)d_in[wb + 6];
    const float* Wo0 = (const float*)d_in[wb + 7];
    const float* Wo1 = (const float*)d_in[wb + 8];
    const float* Wo2 = (const float*)d_in[wb + 9];

    const int N = in_sizes[0] / 288;
    const int E = in_sizes[3];

    static int smem_set = 0;
    const int smem_bytes = SM_TOTAL_F * 4;  // 55424
    if (!smem_set) {
        cudaFuncSetAttribute(edge_kernel, cudaFuncAttributeMaxDynamicSharedMemorySize, smem_bytes);
        smem_set = 1;
    }

    const int n4 = N * 320;
    const int prep_blocks = 1 + 44 + (n4 + 255) / 256;
    prep_kernel<<<prep_blocks, 256>>>(Wr3, n4);
    up_kernel<<<(N + 7) / 8, 288>>>(f_in, Wu0, Wu1, Wu2, N);
    edge_kernel<<<(E + 31) / 32, 256, smem_bytes>>>(pos, batch, esrc, edst, shifts, cell,
                                                    Wr0, Wr1, Wr2, E);
    out_kernel<<<(N + 7) / 8, 288>>>(Wo0, Wo1, Wo2, (float*)d_out, N);
}

// round 13
// speedup vs baseline: 1.8170x; 1.0416x over previous
#include <cuda_runtime.h>
#include <math.h>

#define MAXN 10000

// ---------------- device scratch --------------------------------------------
__device__ float    g_cst;                     // CST_SILU
__device__ float    g_xs[MAXN * 288];          // up-projected node features, [node][slot 0..8][u 0..31]
__device__ float4   g_mid4[MAXN * 288];        // aggregated messages, 1152 f/node
__device__ unsigned g_w3f[8 * 44 * 32 * 2];    // Wr3/8 in tf32 mma-B fragment layout

// g_xs per-node layout (288 floats): slot*32 + u, slot = {x0, x1_0..2, x2_0..4}
// g_mid per-node layout (1152 floats), u-major float4 groups, NO pad waste:
//   blk0 A [0,128):    u*4 + {p0, p1, p2, p74}
//   blk1..4 B [128,640): 128 + q*128 + u*4 + {x, y, z, extra_q}
//        q = l1 path 0..3;  extra = {p84, p94, pa4, 0}
//   blk5..8 C [640,1152): 640 + r*128 + u*4 + c   r = l2 path 0..3, c = comps 0..3
//   (l2 comp4 of path r lives at blk (r), lane c=3: slot index 4r+3 in transposed view)

typedef unsigned long long ull;

__device__ __forceinline__ float silu_f(float v) {
    return __fdividef(v, 1.0f + __expf(-v));
}

// packed fp32x2 fma helpers
#define FFMA2(d, a, b) asm("fma.rn.f32x2 %0, %1, %2, %3;" : "=l"(d) : "l"(a), "l"(b), "l"(d))

__device__ __forceinline__ float2 upk(ull v) {
    float2 r;
    asm("mov.b64 {%0, %1}, %2;" : "=f"(r.x), "=f"(r.y) : "l"(v));
    return r;
}
__device__ __forceinline__ ull dal(double d) { return __double_as_longlong(d); }

__device__ __forceinline__ unsigned tf32_rna(float x) {
    unsigned u;
    asm("cvt.rna.tf32.f32 %0, %1;" : "=r"(u) : "f"(x));
    return u;
}

__device__ __forceinline__ void mma_tf32(float& c0, float& c1, float& c2, float& c3,
                                         unsigned a0, unsigned a1, unsigned a2, unsigned a3,
                                         unsigned b0, unsigned b1) {
    asm volatile(
        "mma.sync.aligned.m16n8k8.row.col.f32.tf32.tf32.f32 "
        "{%0,%1,%2,%3},{%4,%5,%6,%7},{%8,%9},{%0,%1,%2,%3};"
        : "+f"(c0), "+f"(c1), "+f"(c2), "+f"(c3)
        : "r"(a0), "r"(a1), "r"(a2), "r"(a3), "r"(b0), "r"(b1));
}

// ---------------- fused prep: cst (block 0) + w3prep (1..44) + zero (rest) --
__global__ void prep_kernel(const float* __restrict__ Wr3, int n4zero) {
    const int b = blockIdx.x;
    const int t = threadIdx.x;  // 256

    if (b == 0) {
        __shared__ double red[256];
        const int NI = 4096;
        const double h = 24.0 / NI;
        double s = 0.0;
        for (int i = t; i <= NI; i += 256) {
            double xx = -12.0 + h * i;
            double sig = 1.0 / (1.0 + exp(-xx));
            double f = xx * sig;
            f = f * f * exp(-0.5 * xx * xx);
            double c = (i == 0 || i == NI) ? 1.0 : ((i & 1) ? 4.0 : 2.0);
            s += c * f;
        }
        red[t] = s;
        __syncthreads();
        for (int o = 128; o > 0; o >>= 1) {
            if (t < o) red[t] += red[t + o];
            __syncthreads();
        }
        if (t == 0) {
            double I = red[0] * h / 3.0 / 2.5066282746310005024;
            g_cst = (float)(1.0 / sqrt(I));
        }
    } else if (b <= 44) {
        const int f = (b - 1) * 256 + t;
        if (f < 8 * 44 * 32) {
            const int lane = f & 31;
            const int pair = f >> 5;
            const int nt = pair % 44;
            const int kt = pair / 44;
            const int tig = lane & 3;
            const int gid = lane >> 2;
            const int n = nt * 8 + gid;
            float w0 = Wr3[(kt * 8 + tig) * 352 + n] * 0.125f;
            float w1 = Wr3[(kt * 8 + tig + 4) * 352 + n] * 0.125f;
            g_w3f[f * 2 + 0] = tf32_rna(w0);
            g_w3f[f * 2 + 1] = tf32_rna(w1);
        }
    } else {
        const int i = (b - 45) * 256 + t;
        if (i < n4zero) g_mid4[i] = make_float4(0.f, 0.f, 0.f, 0.f);
    }
}

// ---------------- node up-projection (8 nodes/block, slot-major) ------------
__global__ void up_kernel(const float* __restrict__ f_in,
                          const float* __restrict__ Wu0,
                          const float* __restrict__ Wu1,
                          const float* __restrict__ Wu2, int N) {
    const int n0 = blockIdx.x * 8;
    const int t = threadIdx.x;  // 288
    __shared__ float fs[8][288];
    const int nmax = (N - n0 < 8) ? (N - n0) : 8;
#pragma unroll 1
    for (int j = t; j < nmax * 288; j += 288)
        fs[j / 288][j % 288] = f_in[n0 * 288 + j];
    __syncthreads();

    const int slot = t >> 5;
    const int w = t & 31;
    int i, off, d;
    const float* W;
    if (slot == 0)      { i = 0;        d = 1; off = 0;   W = Wu0; }
    else if (slot < 4)  { i = slot - 1; d = 3; off = 32;  W = Wu1; }
    else                { i = slot - 4; d = 5; off = 128; W = Wu2; }

    float acc[8] = {0.f, 0.f, 0.f, 0.f, 0.f, 0.f, 0.f, 0.f};
#pragma unroll 4
    for (int u = 0; u < 32; u++) {
        float wt = __ldg(W + u * 32 + w);
        const int fi = off + u * d + i;
#pragma unroll
        for (int e = 0; e < 8; e++)
            acc[e] = fmaf(fs[e][fi], wt, acc[e]);
    }
#pragma unroll
    for (int e = 0; e < nmax; e++)
        g_xs[(n0 + e) * 288 + slot * 32 + w] = acc[e] * 0.17677669529663687f;
}

// ---------------- radial MLP 64->64 layer (4 edges, duplicated layout) ------
__device__ __forceinline__ void mlp64d(const float* __restrict__ in2,
                                       float* __restrict__ out2,
                                       const float* __restrict__ W,
                                       int lane, float cst) {
    const int o0 = 2 * lane;
    ull accA[4] = {0ull,0ull,0ull,0ull};
    ull accB[4] = {0ull,0ull,0ull,0ull};
#pragma unroll 4
    for (int j2 = 0; j2 < 32; j2++) {
        ull w0 = dal(__ldg(reinterpret_cast<const double*>(W + (2*j2)   * 64 + o0)));
        ull w1 = dal(__ldg(reinterpret_cast<const double*>(W + (2*j2+1) * 64 + o0)));
#pragma unroll
        for (int e = 0; e < 4; e++) {
            ulonglong2 hp = *reinterpret_cast<const ulonglong2*>(in2 + e * 128 + 4 * j2);
            FFMA2(accA[e], w0, hp.x);
            FFMA2(accB[e], w1, hp.y);
        }
    }
#pragma unroll
    for (int e = 0; e < 4; e++) {
        float2 va = upk(accA[e]);
        float2 vb = upk(accB[e]);
        float v0 = silu_f((va.x + vb.x) * 0.125f) * cst;
        float v1 = silu_f((va.y + vb.y) * 0.125f) * cst;
        *reinterpret_cast<float4*>(out2 + e * 128 + 4 * lane) = make_float4(v0, v0, v1, v1);
    }
}

// smem layout (floats):
//   wsm  [0, 11584)        phase-2 radial weights: [32 edges][stride 362]
//        (phase-1 hA2/hB2 [0,8192) alias under wsm; dead before wsm written)
//   hfr  [11584, 13696)    A-fragments (NOT aliased): [etile 2][kt 8][reg 4][33]
//   geo  [13696, 13856)    per-warp edge state: [8 warps][4 edges][5] = ux,uy,uz,src,dst
#define SM_HA 0
#define SM_HB 4096
#define SM_HF 11584
#define SM_GEO 13696
#define WS_STRIDE 362
#define SM_TOTAL_F 13856

// ---------------- fused per-edge kernel (block = 32 edges) ------------------
__global__ void __launch_bounds__(256, 3) edge_kernel(
    const float* __restrict__ pos, const int* __restrict__ batch,
    const int* __restrict__ esrc, const int* __restrict__ edst,
    const float* __restrict__ shifts, const float* __restrict__ cell,
    const float* __restrict__ Wr0, const float* __restrict__ Wr1,
    const float* __restrict__ Wr2, int E)
{
    extern __shared__ float sm[];
    const int wid  = threadIdx.x >> 5;
    const int lane = threadIdx.x & 31;
    float* hA2 = sm + SM_HA + wid * 512;
    float* hB2 = sm + SM_HB + wid * 512;
    unsigned* hfr = reinterpret_cast<unsigned*>(sm + SM_HF);
    float* geo = sm + SM_GEO + wid * 20;   // [4 edges][5]
    float* wsm = sm;                       // aliases hA2/hB2 after phase 1

    const int base = blockIdx.x * 32 + wid * 4;   // this warp's 4 TP edges
    const int etile = wid >> 2;                   // 16-edge tile of this warp
    const float cst = g_cst;

    // ================= phase 1: geometry + radial MLP layers 1-3 ============
    {
        float Lr[4];
#pragma unroll
        for (int e = 0; e < 4; e++) {
            int ei = (base + e < E) ? base + e : E - 1;
            const int src = __ldg(esrc + ei);
            const int dst = __ldg(edst + ei);
            const float sx = __ldg(shifts + 3*ei), sy = __ldg(shifts + 3*ei+1), sz = __ldg(shifts + 3*ei+2);
            const float* Cc = cell + 9 * __ldg(batch + src);
            float vx = __ldg(pos+3*dst+0) - __ldg(pos+3*src+0) + sx*__ldg(Cc+0) + sy*__ldg(Cc+3) + sz*__ldg(Cc+6);
            float vy = __ldg(pos+3*dst+1) - __ldg(pos+3*src+1) + sx*__ldg(Cc+1) + sy*__ldg(Cc+4) + sz*__ldg(Cc+7);
            float vz = __ldg(pos+3*dst+2) - __ldg(pos+3*src+2) + sx*__ldg(Cc+2) + sy*__ldg(Cc+5) + sz*__ldg(Cc+8);
            float L = sqrtf(vx*vx + vy*vy + vz*vz);
            float inv = 1.0f / fmaxf(L, 1e-12f);
            Lr[e] = L;
            if (lane == 0) {
                geo[e * 5 + 0] = vx * inv;
                geo[e * 5 + 1] = vy * inv;
                geo[e * 5 + 2] = vz * inv;
                geo[e * 5 + 3] = __int_as_float(src);
                geo[e * 5 + 4] = __int_as_float(dst);
            }
        }

        // radial embedding, duplicated into hB2[e][0..15]
        const int k = lane & 7;
        const int e = lane >> 3;
        float Ls = Lr[0];
        if (e == 1) Ls = Lr[1]; else if (e == 2) Ls = Lr[2]; else if (e == 3) Ls = Lr[3];
        float tt = (Ls - (float)(k + 1) * (5.0f / 9.0f)) * 1.8f;
        float v = __expf(-tt * tt) * 2.525381361380527f;  // sqrt(8)/1.12
        *reinterpret_cast<float2*>(hB2 + e * 128 + 2 * k) = make_float2(v, v);
    }
    __syncwarp();

    const int o0 = 2 * lane;
    // layer 1: 8 -> 64 (hB2 -> hA2)
    {
        ull acc[4] = {0ull,0ull,0ull,0ull};
#pragma unroll
        for (int j2 = 0; j2 < 4; j2++) {
            ull w0 = dal(__ldg(reinterpret_cast<const double*>(Wr0 + (2*j2)   * 64 + o0)));
            ull w1 = dal(__ldg(reinterpret_cast<const double*>(Wr0 + (2*j2+1) * 64 + o0)));
#pragma unroll
            for (int e = 0; e < 4; e++) {
                ulonglong2 hp = *reinterpret_cast<const ulonglong2*>(hB2 + e * 128 + 4 * j2);
                FFMA2(acc[e], w0, hp.x);
                FFMA2(acc[e], w1, hp.y);
            }
        }
#pragma unroll
        for (int e = 0; e < 4; e++) {
            float2 v = upk(acc[e]);
            float v0 = silu_f(v.x * 0.35355339059327373f) * cst;
            float v1 = silu_f(v.y * 0.35355339059327373f) * cst;
            *reinterpret_cast<float4*>(hA2 + e * 128 + 4 * lane) = make_float4(v0, v0, v1, v1);
        }
    }
    __syncwarp();
    mlp64d(hA2, hB2, Wr1, lane, cst);   // layer 2
    __syncwarp();

    // layer 3: read hB2, write h into A-fragment layout (tf32 bits)
    {
        ull accA[4] = {0ull,0ull,0ull,0ull};
        ull accB[4] = {0ull,0ull,0ull,0ull};
#pragma unroll 4
        for (int j2 = 0; j2 < 32; j2++) {
            ull w0 = dal(__ldg(reinterpret_cast<const double*>(Wr2 + (2*j2)   * 64 + o0)));
            ull w1 = dal(__ldg(reinterpret_cast<const double*>(Wr2 + (2*j2+1) * 64 + o0)));
#pragma unroll
            for (int e = 0; e < 4; e++) {
                ulonglong2 hp = *reinterpret_cast<const ulonglong2*>(hB2 + e * 128 + 4 * j2);
                FFMA2(accA[e], w0, hp.x);
                FFMA2(accB[e], w1, hp.y);
            }
        }
#pragma unroll
        for (int e = 0; e < 4; e++) {
            float2 va = upk(accA[e]);
            float2 vb = upk(accB[e]);
            float v0 = silu_f((va.x + vb.x) * 0.125f) * cst;
            float v1 = silu_f((va.y + vb.y) * 0.125f) * cst;
            const int m = (wid & 3) * 4 + e;           // row within 16-edge tile
#pragma unroll
            for (int cc = 0; cc < 2; cc++) {
                int k  = 2 * lane + cc;
                float v = cc ? v1 : v0;
                int kt  = k >> 3;
                int kin = k & 7;
                int reg = ((m >= 8) ? 1 : 0) + ((kin >= 4) ? 2 : 0);
                int lp  = (m & 7) * 4 + (kin & 3);
                hfr[((etile * 8 + kt) * 4 + reg) * 33 + lp] = tf32_rna(v);
            }
        }
    }
    __syncthreads();   // hfr complete across etile; hA2/hB2 reads all done

    // ================= MMA pass: all 44 n-tiles =============================
    {
        unsigned afr[8][4];
#pragma unroll
        for (int kt = 0; kt < 8; kt++)
#pragma unroll
            for (int r = 0; r < 4; r++)
                afr[kt][r] = hfr[((etile * 8 + kt) * 4 + r) * 33 + lane];

        const int nch = wid & 3;
        const int gid = lane >> 2;
        const int tig = lane & 3;
        const uint2* Bf = reinterpret_cast<const uint2*>(g_w3f);
#pragma unroll 1
        for (int tt = 0; tt < 11; tt++) {
            const int nt = nch * 11 + tt;
            float c0 = 0.f, c1 = 0.f, c2 = 0.f, c3 = 0.f;
#pragma unroll
            for (int kt = 0; kt < 8; kt++) {
                uint2 b = __ldg(Bf + (kt * 44 + nt) * 32 + lane);
                mma_tf32(c0, c1, c2, c3, afr[kt][0], afr[kt][1], afr[kt][2], afr[kt][3], b.x, b.y);
            }
            const int col = nt * 8 + tig * 2;
            float* r0 = wsm + (etile * 16 + gid) * WS_STRIDE + col;
            *reinterpret_cast<float2*>(r0) = make_float2(c0, c1);
            *reinterpret_cast<float2*>(r0 + 8 * WS_STRIDE) = make_float2(c2, c3);
        }
    }
    __syncthreads();

    // ================= TP + 9 coalesced vector atomics ======================
    const float A_  = 0.31622776601683794f;  // 1/sqrt(10)
    const float B_  = 0.18257418583505536f;  // 1/sqrt(30)
    const float AL  = 0.11952286093343936f;  // 1/sqrt(70)
    const float BE  = 0.20701966780270626f;  // sqrt(3/70)
    const float SQ3 = 1.7320508075688772f;
    const float SQ5 = 2.23606797749979f;

#pragma unroll 1
    for (int e = 0; e < 4; e++) {
        if (base + e >= E) break;
        const float ux = geo[e * 5 + 0];
        const float uy = geo[e * 5 + 1];
        const float uz = geo[e * 5 + 2];
        const int src = __float_as_int(geo[e * 5 + 3]);
        const int dst = __float_as_int(geo[e * 5 + 4]);

        const float s1x = SQ3 * ux, s1y = SQ3 * uy, s1z = SQ3 * uz;
        const float s20 = 3.872983346207417f * ux * uz;
        const float s21 = 3.872983346207417f * ux * uy;
        const float s22 = SQ5 * (uy*uy - 0.5f*(ux*ux + uz*uz));
        const float s23 = 3.872983346207417f * uy * uz;
        const float s24 = 1.9364916731037085f * (uz*uz - ux*ux);

        const float* wrow = wsm + (wid * 4 + e) * WS_STRIDE + lane;
        float w[11];
#pragma unroll
        for (int k = 0; k < 11; k++) w[k] = wrow[k * 32];

        const float* xp = g_xs + src * 288 + lane;
        const float x0  = __ldg(xp);
        const float x10 = __ldg(xp + 32),  x11 = __ldg(xp + 64),  x12 = __ldg(xp + 96);
        const float x20 = __ldg(xp + 128), x21 = __ldg(xp + 160), x22 = __ldg(xp + 192);
        const float x23 = __ldg(xp + 224), x24 = __ldg(xp + 256);

        // l0
        const float p0 = x0 * w[0];
        const float p1 = 0.5773502691896258f * (x10*s1x + x11*s1y + x12*s1z) * w[1];
        const float p2 = 0.4472135954999579f * (x20*s20 + x21*s21 + x22*s22 + x23*s23 + x24*s24) * w[2];

        // l1
        const float c3 = x0 * w[3];
        float p5x, p5y, p5z;
        {
            float wv = SQ3 * w[5];
            float B00 = -B_*s22 - A_*s24;
            float B01 =  A_*s21;
            float B02 =  A_*s20;
            float B11 =  2.f*B_*s22;
            float B12 =  A_*s23;
            float B22 = -B_*s22 + A_*s24;
            p5x = wv * (x10*B00 + x11*B01 + x12*B02);
            p5y = wv * (x10*B01 + x11*B11 + x12*B12);
            p5z = wv * (x10*B02 + x11*B12 + x12*B22);
        }
        float p6x, p6y, p6z;
        {
            float wv = SQ3 * w[6];
            p6x = wv * (A_*(x20*s1z + x21*s1y) - B_*x22*s1x - A_*x24*s1x);
            p6y = wv * (A_*(x21*s1x + x23*s1z) + 2.f*B_*x22*s1y);
            p6z = wv * (A_*(x20*s1x + x23*s1y + x24*s1z) - B_*x22*s1z);
        }

        // l2
        const float c7 = x0 * w[7];
        const float p70 = c7*s20, p71 = c7*s21, p72 = c7*s22, p73 = c7*s23, p74 = c7*s24;
        float p80, p81, p82, p83, p84;
        {
            float wv = SQ5 * w[8];
            p80 = wv * (A_*(x10*s1z + x12*s1x));
            p81 = wv * (A_*(x10*s1y + x11*s1x));
            p82 = wv * (B_*(-x10*s1x + 2.f*x11*s1y - x12*s1z));
            p83 = wv * (A_*(x11*s1z + x12*s1y));
            p84 = wv * (A_*(-x10*s1x + x12*s1z));
        }
        const float p90 = x20*w[9], p91 = x21*w[9], p92 = x22*w[9], p93 = x23*w[9], p94 = x24*w[9];
        float pa0, pa1, pa2, pa3, pa4;
        {
            float wv = SQ5 * w[10];
            pa0 = wv * (x20*(2.f*AL*s22) + x21*(-BE*s23) + x22*(2.f*AL*s20) + x23*(-BE*s21));
            pa1 = wv * (x20*(-BE*s23) + x21*(-AL*s22 + BE*s24) + x22*(-AL*s21) + x23*(-BE*s20) + x24*(BE*s21));
            pa2 = wv * (x20*(2.f*AL*s20) + x21*(-AL*s21) + x22*(-2.f*AL*s22) + x23*(-AL*s23) + x24*(2.f*AL*s24));
            pa3 = wv * (x20*(-BE*s21) + x21*(-BE*s20) + x22*(-AL*s23) + x23*(-AL*s22 - BE*s24) + x24*(-BE*s23));
            pa4 = wv * (x21*(BE*s21) + x22*(2.f*AL*s24) + x23*(-BE*s23) + x24*(2.f*AL*s22));
        }

        float4* mb = reinterpret_cast<float4*>(reinterpret_cast<float*>(g_mid4) + dst * 1152) + lane;
        atomicAdd(mb,       make_float4(p0, p1, p2, p74));            // A (+r0 comp4)
        atomicAdd(mb + 32,  make_float4(c3*s1x, c3*s1y, c3*s1z, p84));// B q0 (+r1 comp4)
        atomicAdd(mb + 64,  make_float4(x10*w[4], x11*w[4], x12*w[4], p94)); // B q1 (+r2 comp4)
        atomicAdd(mb + 96,  make_float4(p5x, p5y, p5z, pa4));         // B q2 (+r3 comp4)
        atomicAdd(mb + 128, make_float4(p6x, p6y, p6z, 0.f));         // B q3
        atomicAdd(mb + 160, make_float4(p70, p71, p72, p73));         // C r0
        atomicAdd(mb + 192, make_float4(p80, p81, p82, p83));         // C r1
        atomicAdd(mb + 224, make_float4(p90, p91, p92, p93));         // C r2
        atomicAdd(mb + 256, make_float4(pa0, pa1, pa2, pa3));         // C r3
    }
}

// ---------------- per-node output projection (8 nodes/block, transposed) ----
// smem ms: [8 nodes][36 slots][32 u]; slot = blk*4 + c  (blk = jj>>5 of float4 idx)
//   l0 s:          slot = s              (s = 0..2)
//   l1 (q,i):      slot = 4 + q*4 + i
//   l2 (r, c<4):   slot = 20 + r*4 + c
//   l2 (r, c==4):  slot = 4*r + 3
__global__ void out_kernel(const float* __restrict__ Wo0,
                           const float* __restrict__ Wo1,
                           const float* __restrict__ Wo2,
                           float* __restrict__ out, int N) {
    const int n0 = blockIdx.x * 8;
    const int t = threadIdx.x;  // 288
    __shared__ float ms[8][1152];
    const int nmax = (N - n0 < 8) ? (N - n0) : 8;
#pragma unroll 1
    for (int j = t; j < nmax * 288; j += 288) {
        const int node = j / 288, jj = j % 288;
        float4 v = g_mid4[(n0 + node) * 288 + jj];
        const int blk = jj >> 5, u = jj & 31;
        float* b = ms[node] + (blk * 4) * 32 + u;
        b[0]  = v.x;
        b[32] = v.y;
        b[64] = v.z;
        b[96] = v.w;
    }
    __syncthreads();

    const int slot = t >> 5;
    const int w = t & 31;
    float acc[8] = {0.f, 0.f, 0.f, 0.f, 0.f, 0.f, 0.f, 0.f};
    int off, d, i;
    float scale;

    // grp-loop helper: accumulate 32 u's of (weight row block grp, ms slot sidx)
    #define OUT_ACC(Wp, grp, sidx)                                             \
        do {                                                                   \
            const float4* mrow[8];                                             \
            _Pragma("unroll")                                                  \
            for (int e = 0; e < 8; e++)                                        \
                mrow[e] = reinterpret_cast<const float4*>(ms[e] + (sidx) * 32);\
            _Pragma("unroll")                                                  \
            for (int u4 = 0; u4 < 8; u4++) {                                   \
                float4 mv[8];                                                  \
                _Pragma("unroll")                                              \
                for (int e = 0; e < 8; e++) mv[e] = mrow[e][u4];               \
                _Pragma("unroll")                                              \
                for (int c = 0; c < 4; c++) {                                  \
                    float wt = __ldg(Wp + ((grp) * 32 + u4 * 4 + c) * 32 + w); \
                    _Pragma("unroll")                                          \
                    for (int e = 0; e < 8; e++) {                              \
                        float mval = (c == 0) ? mv[e].x : (c == 1) ? mv[e].y   \
                                   : (c == 2) ? mv[e].z : mv[e].w;             \
                        acc[e] = fmaf(mval, wt, acc[e]);                       \
                    }                                                          \
                }                                                              \
            }                                                                  \
        } while (0)

    if (slot == 0) {
        off = 0; d = 1; i = 0;
        scale = 0.006378879538497859f;   // 1/(sqrt(96)*16)
#pragma unroll
        for (int s = 0; s < 3; s++)
            OUT_ACC(Wo0, s, s);
    } else if (slot < 4) {
        off = 32; d = 3; i = slot - 1;
        scale = 0.005524271728019903f;   // 1/(sqrt(128)*16)
#pragma unroll
        for (int q = 0; q < 4; q++)
            OUT_ACC(Wo1, q, 4 + q * 4 + i);
    } else {
        off = 128; d = 5; i = slot - 4;
        scale = 0.005524271728019903f;
        if (i < 4) {
#pragma unroll
            for (int r = 0; r < 4; r++)
                OUT_ACC(Wo2, r, 20 + r * 4 + i);
        } else {
#pragma unroll
            for (int r = 0; r < 4; r++)
                OUT_ACC(Wo2, r, 4 * r + 3);
        }
    }
    #undef OUT_ACC

#pragma unroll
    for (int e = 0; e < nmax; e++)
        out[(n0 + e) * 288 + off + w * d + i] = acc[e] * scale;
}

// ---------------- launch -----------------------------------------------------
extern "C" void kernel_launch(void* const* d_in, const int* in_sizes, int n_in,
                              void* d_out, int out_size) {
    const float* f_in   = (const float*)d_in[0];
    const float* pos    = (const float*)d_in[1];
    const int*   batch  = (const int*)d_in[2];
    const int*   esrc   = (const int*)d_in[3];
    const int*   edst   = (const int*)d_in[4];
    const float* shifts = (const float*)d_in[5];
    const float* cell   = (const float*)d_in[6];
    const int wb = n_in - 10;
    const float* Wu0 = (const float*)d_in[wb + 0];
    const float* Wu1 = (const float*)d_in[wb + 1];
    const float* Wu2 = (const float*)d_in[wb + 2];
    const float* Wr0 = (const float*)d_in[wb + 3];
    const float* Wr1 = (const float*)d_in[wb + 4];
    const float* Wr2 = (const float*)d_in[wb + 5];
    const float* Wr3 = (const float*)d_in[wb + 6];
    const float* Wo0 = (const float*)d_in[wb + 7];
    const float* Wo1 = (const float*)d_in[wb + 8];
    const float* Wo2 = (const float*)d_in[wb + 9];

    const int N = in_sizes[0] / 288;
    const int E = in_sizes[3];

    static int smem_set = 0;
    const int smem_bytes = SM_TOTAL_F * 4;  // 55424
    if (!smem_set) {
        cudaFuncSetAttribute(edge_kernel, cudaFuncAttributeMaxDynamicSharedMemorySize, smem_bytes);
        smem_set = 1;
    }

    const int n4 = N * 288;
    const int prep_blocks = 1 + 44 + (n4 + 255) / 256;
    prep_kernel<<<prep_blocks, 256>>>(Wr3, n4);
    up_kernel<<<(N + 7) / 8, 288>>>(f_in, Wu0, Wu1, Wu2, N);
    edge_kernel<<<(E + 31) / 32, 256, smem_bytes>>>(pos, batch, esrc, edst, shifts, cell,
                                                    Wr0, Wr1, Wr2, E);
    out_kernel<<<(N + 7) / 8, 288>>>(Wo0, Wo1, Wo2, (float*)d_out, N);
}